// round 1
// baseline (speedup 1.0000x reference)
#include <cuda_runtime.h>
#include <cstdint>
#include <cstddef>

// Problem constants
#define BB   4
#define CC   256      // D_MODEL = D_INNER
#define SS   64
#define DD   16
#define HH   64
#define WW   64
#define NN   65536    // D*H*W
#define O3S  192      // 3*S
#define KSPLIT 32     // split-K factor for h-GEMM

static const size_t YSIZE = (size_t)BB * CC * NN;   // 67108864

// ---- static scratch (no runtime allocation allowed) ----
__device__ float g_bcdt[(size_t)BB * O3S * NN];   // GEMM1 output (pre-conv)
__device__ float g_conv[(size_t)BB * O3S * NN];   // conv output; dt channels later overwritten by AB
__device__ float g_hpart[(size_t)KSPLIT * BB * CC * SS]; // split-K partials
__device__ float g_h [BB * CC * SS];
__device__ float g_h3[BB * CC * SS];
__device__ float g_h4[BB * CC * SS];

// ============================================================================
// Kernel 1: BCdt = W_bcdt(192x256) @ x(b,256,N) + b_bcdt
// Tiling: BM=64, BN=128, BK=16; 256 threads, 4x8 microtile.
// ============================================================================
__global__ void __launch_bounds__(256) gemm1_kernel(
    const float* __restrict__ x, const float* __restrict__ W,
    const float* __restrict__ bias)
{
    __shared__ __align__(16) float As[64 * 17];   // [m][k], pad 17
    __shared__ __align__(16) float Bs[16 * 128];  // [k][n]

    const int n0 = blockIdx.x * 128;
    const int m0 = blockIdx.y * 64;
    const int b  = blockIdx.z;
    const int tid = threadIdx.x;
    const int tx = tid & 15;     // n direction
    const int ty = tid >> 4;     // m direction

    const float* xb = x + (size_t)b * CC * NN;

    float acc[4][8];
#pragma unroll
    for (int i = 0; i < 4; i++)
#pragma unroll
        for (int j = 0; j < 8; j++) acc[i][j] = 0.f;

    for (int k0 = 0; k0 < 256; k0 += 16) {
        // load W tile 64x16 (1024 elems, 4/thread)
#pragma unroll
        for (int r = 0; r < 4; r++) {
            int idx = tid + r * 256;
            int i = idx >> 4, k = idx & 15;
            As[i * 17 + k] = W[(size_t)(m0 + i) * 256 + k0 + k];
        }
        // load x tile 16x128 (512 float4, 2/thread)
#pragma unroll
        for (int r = 0; r < 2; r++) {
            int f = tid + r * 256;
            int k = f >> 5, j4 = f & 31;
            float4 v = *(const float4*)(xb + (size_t)(k0 + k) * NN + n0 + j4 * 4);
            *(float4*)(&Bs[k * 128 + j4 * 4]) = v;
        }
        __syncthreads();
#pragma unroll
        for (int k = 0; k < 16; k++) {
            float a0 = As[(ty * 4 + 0) * 17 + k];
            float a1 = As[(ty * 4 + 1) * 17 + k];
            float a2 = As[(ty * 4 + 2) * 17 + k];
            float a3 = As[(ty * 4 + 3) * 17 + k];
            float4 b0 = *(float4*)(&Bs[k * 128 + tx * 8]);
            float4 b1 = *(float4*)(&Bs[k * 128 + tx * 8 + 4]);
            float bv[8] = {b0.x, b0.y, b0.z, b0.w, b1.x, b1.y, b1.z, b1.w};
            float av[4] = {a0, a1, a2, a3};
#pragma unroll
            for (int i = 0; i < 4; i++)
#pragma unroll
                for (int j = 0; j < 8; j++) acc[i][j] += av[i] * bv[j];
        }
        __syncthreads();
    }
    // epilogue: + bias, store
#pragma unroll
    for (int i = 0; i < 4; i++) {
        int m = m0 + ty * 4 + i;
        float bb = bias[m];
        float* dst = &g_bcdt[((size_t)(b * O3S + m)) * NN + n0 + tx * 8];
        float4 o0 = make_float4(acc[i][0] + bb, acc[i][1] + bb, acc[i][2] + bb, acc[i][3] + bb);
        float4 o1 = make_float4(acc[i][4] + bb, acc[i][5] + bb, acc[i][6] + bb, acc[i][7] + bb);
        *(float4*)(dst)     = o0;
        *(float4*)(dst + 4) = o1;
    }
}

// ============================================================================
// Kernel 2: depthwise 3x3x3 conv (cross-correlation), pad 1, + b_dw
// block: one (b, ch, d, h-half). shared halo 3x34x66.
// ============================================================================
__global__ void __launch_bounds__(256) conv_kernel(
    const float* __restrict__ wdw, const float* __restrict__ bdw)
{
    __shared__ float s[3][34][66];
    __shared__ float wt[27];

    const int dz = blockIdx.x >> 1;
    const int hhalf = blockIdx.x & 1;
    const int ch = blockIdx.y;
    const int b  = blockIdx.z;
    const int h0 = hhalf * 32;
    const int tid = threadIdx.x;

    const float* base = g_bcdt + ((size_t)(b * O3S + ch)) * NN;

    for (int idx = tid; idx < 3 * 34 * 66; idx += 256) {
        int kd = idx / (34 * 66);
        int rem = idx % (34 * 66);
        int ih = rem / 66, iw = rem % 66;
        int d = dz - 1 + kd, h = h0 - 1 + ih, w = iw - 1;
        float v = 0.f;
        if ((unsigned)d < DD && (unsigned)h < HH && (unsigned)w < WW)
            v = base[((size_t)d * HH + h) * WW + w];
        s[kd][ih][iw] = v;
    }
    if (tid < 27) wt[tid] = wdw[ch * 27 + tid];
    __syncthreads();

    const float bb = bdw[ch];
    const int w = tid & 63;
    const int hl0 = tid >> 6;   // 0..3
    float* outb = g_conv + ((size_t)(b * O3S + ch)) * NN;

#pragma unroll
    for (int r = 0; r < 8; r++) {
        int hl = hl0 + r * 4;   // 0..31
        float acc = bb;
#pragma unroll
        for (int kd = 0; kd < 3; kd++)
#pragma unroll
            for (int kh = 0; kh < 3; kh++)
#pragma unroll
                for (int kw = 0; kw < 3; kw++)
                    acc += s[kd][hl + kh][w + kw] * wt[kd * 9 + kh * 3 + kw];
        outb[((size_t)dz * HH + h0 + hl) * WW + w] = acc;
    }
}

// ============================================================================
// Kernel 3: softmax over n of dt row (A cancels!), fused AB = softmax * B_
// One block per (b, s). AB overwrites dt channel in-place.
// ============================================================================
__global__ void __launch_bounds__(256) softmax_ab_kernel()
{
    const int s_ = blockIdx.x;
    const int b  = blockIdx.y;
    float* dt = g_conv + ((size_t)(b * O3S + 128 + s_)) * NN;
    const float* Bp = g_conv + ((size_t)(b * O3S + s_)) * NN;
    const int tid = threadIdx.x;

    float m = -1e30f, sum = 0.f;
    for (int i = tid * 4; i < NN; i += 1024) {
        float4 v = *(float4*)(dt + i);
        float vals[4] = {v.x, v.y, v.z, v.w};
#pragma unroll
        for (int q = 0; q < 4; q++) {
            float val = vals[q];
            if (val > m) { sum *= __expf(m - val); m = val; }
            sum += __expf(val - m);
        }
    }
    __shared__ float sm[256], ssum[256];
    sm[tid] = m; ssum[tid] = sum;
    __syncthreads();
    for (int off = 128; off > 0; off >>= 1) {
        if (tid < off) {
            float m2 = sm[tid + off], s2 = ssum[tid + off];
            float M = fmaxf(sm[tid], m2);
            ssum[tid] = ssum[tid] * __expf(sm[tid] - M) + s2 * __expf(m2 - M);
            sm[tid] = M;
        }
        __syncthreads();
    }
    const float M = sm[0];
    const float inv = 1.f / ssum[0];

    for (int i = tid * 4; i < NN; i += 1024) {
        float4 v  = *(float4*)(dt + i);
        float4 bv = *(const float4*)(Bp + i);
        float4 o;
        o.x = __expf(v.x - M) * inv * bv.x;
        o.y = __expf(v.y - M) * inv * bv.y;
        o.z = __expf(v.z - M) * inv * bv.z;
        o.w = __expf(v.w - M) * inv * bv.w;
        *(float4*)(dt + i) = o;
    }
}

// ============================================================================
// Kernel 4: h[b,c,s] = sum_n x[b,c,n] * AB[b,s,n]   (split-K partials)
// block: (ksplit, ctile, b); BM=64 (c), BN=64 (s), inner BK=64, chunk=2048.
// ============================================================================
__global__ void __launch_bounds__(256) hgemm_kernel(const float* __restrict__ x)
{
    __shared__ float As[64 * 65];  // x tile: [c][kk]
    __shared__ float Bs[64 * 65];  // AB tile transposed: [kk][s]

    const int ks = blockIdx.x;          // 0..31
    const int c0 = blockIdx.y * 64;
    const int b  = blockIdx.z;
    const int nbase = ks * (NN / KSPLIT);  // 2048 chunk
    const int tid = threadIdx.x;
    const int tx = tid & 15;   // s
    const int ty = tid >> 4;   // c

    const float* xb = x + ((size_t)(b * CC + c0)) * NN;
    const float* ab = g_conv + ((size_t)(b * O3S + 128)) * NN;

    float acc[4][4];
#pragma unroll
    for (int i = 0; i < 4; i++)
#pragma unroll
        for (int j = 0; j < 4; j++) acc[i][j] = 0.f;

    for (int kc = 0; kc < NN / KSPLIT; kc += 64) {
        const int nb = nbase + kc;
#pragma unroll
        for (int r = 0; r < 16; r++) {
            int idx = tid + r * 256;
            int i = idx >> 6, kk = idx & 63;
            As[i * 65 + kk] = xb[(size_t)i * NN + nb + kk];
        }
#pragma unroll
        for (int r = 0; r < 16; r++) {
            int idx = tid + r * 256;
            int sr = idx >> 6, kk = idx & 63;
            Bs[kk * 65 + sr] = ab[(size_t)sr * NN + nb + kk];  // conflict-free scatter
        }
        __syncthreads();
#pragma unroll 8
        for (int kk = 0; kk < 64; kk++) {
            float a0 = As[(ty * 4 + 0) * 65 + kk];
            float a1 = As[(ty * 4 + 1) * 65 + kk];
            float a2 = As[(ty * 4 + 2) * 65 + kk];
            float a3 = As[(ty * 4 + 3) * 65 + kk];
            float b0 = Bs[kk * 65 + tx * 4 + 0];
            float b1 = Bs[kk * 65 + tx * 4 + 1];
            float b2 = Bs[kk * 65 + tx * 4 + 2];
            float b3 = Bs[kk * 65 + tx * 4 + 3];
            float av[4] = {a0, a1, a2, a3};
            float bv[4] = {b0, b1, b2, b3};
#pragma unroll
            for (int i = 0; i < 4; i++)
#pragma unroll
                for (int j = 0; j < 4; j++) acc[i][j] += av[i] * bv[j];
        }
        __syncthreads();
    }
    float* dst = g_hpart + (size_t)ks * (BB * CC * SS);
#pragma unroll
    for (int i = 0; i < 4; i++)
#pragma unroll
        for (int j = 0; j < 4; j++)
            dst[((size_t)(b * CC + c0 + ty * 4 + i)) * SS + tx * 4 + j] = acc[i][j];
}

// deterministic reduction of split-K partials
__global__ void __launch_bounds__(256) hreduce_kernel()
{
    int i = blockIdx.x * 256 + threadIdx.x;   // < 65536
    float sum = 0.f;
#pragma unroll
    for (int ks = 0; ks < KSPLIT; ks++)
        sum += g_hpart[(size_t)ks * (BB * CC * SS) + i];
    g_h[i] = sum;
}

// ============================================================================
// Kernel 5: hz = W_hz @ h + b_hz ; h3 = h2*silu(z) + h2*Dp
// thread per (b, o, s)
// ============================================================================
__global__ void __launch_bounds__(256) e1_kernel(
    const float* __restrict__ Whz, const float* __restrict__ bhz,
    const float* __restrict__ Dp)
{
    const int b = blockIdx.y;
    const int o = blockIdx.x * 4 + (threadIdx.x >> 6);
    const int s_ = threadIdx.x & 63;
    const float* hb = g_h + (size_t)b * CC * SS;
    const float* w1 = Whz + (size_t)o * 256;
    const float* w2 = Whz + (size_t)(o + 256) * 256;
    float a1 = bhz[o], a2 = bhz[o + 256];
    for (int c = 0; c < 256; c++) {
        float hv = hb[c * 64 + s_];
        a1 += w1[c] * hv;
        a2 += w2[c] * hv;
    }
    float sig = 1.f / (1.f + __expf(-a2));
    g_h3[((size_t)b * CC + o) * SS + s_] = a1 * (a2 * sig) + a1 * Dp[0];
}

// Kernel 6: h4 = W_out @ h3 + b_out ; write to scratch + output tail
__global__ void __launch_bounds__(256) e2_kernel(
    const float* __restrict__ Wout, const float* __restrict__ bout,
    float* __restrict__ out)
{
    const int b = blockIdx.y;
    const int o = blockIdx.x * 4 + (threadIdx.x >> 6);
    const int s_ = threadIdx.x & 63;
    const float* hb = g_h3 + (size_t)b * CC * SS;
    const float* w1 = Wout + (size_t)o * 256;
    float acc = bout[o];
    for (int c = 0; c < 256; c++)
        acc += w1[c] * hb[c * 64 + s_];
    size_t idx = ((size_t)b * CC + o) * SS + s_;
    g_h4[idx] = acc;
    out[YSIZE + idx] = acc;
}

// ============================================================================
// Kernel 7: y[b,c,n] = sum_s h4[b,c,s] * C_[b,s,n]
// block: (ntile 128, ctile 64, b); K=64 single chunk; 4x8 microtile.
// ============================================================================
__global__ void __launch_bounds__(256) ygemm_kernel(float* __restrict__ y)
{
    __shared__ __align__(16) float As[64 * 64];   // h4 [c][s]
    __shared__ __align__(16) float Bs[64 * 128];  // C_ [s][n]

    const int n0 = blockIdx.x * 128;
    const int c0 = blockIdx.y * 64;
    const int b  = blockIdx.z;
    const int tid = threadIdx.x;
    const int tx = tid & 15;
    const int ty = tid >> 4;

#pragma unroll
    for (int r = 0; r < 16; r++) {
        int idx = tid + r * 256;
        int i = idx >> 6, sr = idx & 63;
        As[i * 64 + sr] = g_h4[((size_t)(b * CC + c0 + i)) * SS + sr];
    }
    const float* cp = g_conv + ((size_t)(b * O3S + 64)) * NN;  // C_ channels
#pragma unroll
    for (int r = 0; r < 8; r++) {
        int f = tid + r * 256;
        int sr = f >> 5, j4 = f & 31;
        float4 v = *(const float4*)(cp + (size_t)sr * NN + n0 + j4 * 4);
        *(float4*)(&Bs[sr * 128 + j4 * 4]) = v;
    }
    __syncthreads();

    float acc[4][8];
#pragma unroll
    for (int i = 0; i < 4; i++)
#pragma unroll
        for (int j = 0; j < 8; j++) acc[i][j] = 0.f;

#pragma unroll 8
    for (int k = 0; k < 64; k++) {
        float a0 = As[(ty * 4 + 0) * 64 + k];
        float a1 = As[(ty * 4 + 1) * 64 + k];
        float a2 = As[(ty * 4 + 2) * 64 + k];
        float a3 = As[(ty * 4 + 3) * 64 + k];
        float4 b0 = *(float4*)(&Bs[k * 128 + tx * 8]);
        float4 b1 = *(float4*)(&Bs[k * 128 + tx * 8 + 4]);
        float av[4] = {a0, a1, a2, a3};
        float bv[8] = {b0.x, b0.y, b0.z, b0.w, b1.x, b1.y, b1.z, b1.w};
#pragma unroll
        for (int i = 0; i < 4; i++)
#pragma unroll
            for (int j = 0; j < 8; j++) acc[i][j] += av[i] * bv[j];
    }
#pragma unroll
    for (int i = 0; i < 4; i++) {
        float* dst = y + ((size_t)(b * CC + c0 + ty * 4 + i)) * NN + n0 + tx * 8;
        float4 o0 = make_float4(acc[i][0], acc[i][1], acc[i][2], acc[i][3]);
        float4 o1 = make_float4(acc[i][4], acc[i][5], acc[i][6], acc[i][7]);
        *(float4*)(dst)     = o0;
        *(float4*)(dst + 4) = o1;
    }
}

// ============================================================================
extern "C" void kernel_launch(void* const* d_in, const int* in_sizes, int n_in,
                              void* d_out, int out_size)
{
    const float* x      = (const float*)d_in[0];
    const float* W_bcdt = (const float*)d_in[1];
    const float* b_bcdt = (const float*)d_in[2];
    const float* W_dw   = (const float*)d_in[3];
    const float* b_dw   = (const float*)d_in[4];
    const float* W_hz   = (const float*)d_in[5];
    const float* b_hz   = (const float*)d_in[6];
    const float* W_out  = (const float*)d_in[7];
    const float* b_out  = (const float*)d_in[8];
    // d_in[9] = A : unused (softmax shift invariance along the reduced axis)
    const float* Dp     = (const float*)d_in[10];
    float* out = (float*)d_out;

    gemm1_kernel<<<dim3(NN / 128, 3, BB), 256>>>(x, W_bcdt, b_bcdt);
    conv_kernel<<<dim3(32, O3S, BB), 256>>>(W_dw, b_dw);
    softmax_ab_kernel<<<dim3(SS, BB), 256>>>();
    hgemm_kernel<<<dim3(KSPLIT, 4, BB), 256>>>(x);
    hreduce_kernel<<<256, 256>>>();
    e1_kernel<<<dim3(64, BB), 256>>>(W_hz, b_hz, Dp);
    e2_kernel<<<dim3(64, BB), 256>>>(W_out, b_out, out);
    ygemm_kernel<<<dim3(NN / 128, 4, BB), 256>>>(out);
}

// round 3
// speedup vs baseline: 1.4796x; 1.4796x over previous
#include <cuda_runtime.h>
#include <cuda_bf16.h>
#include <cstdint>
#include <cstddef>

// Problem constants
#define BB   4
#define CC   256      // D_MODEL = D_INNER
#define SS   64
#define DD   16
#define HH   64
#define WW   64
#define NN   65536    // D*H*W
#define O3S  192      // 3*S
#define KSPLIT 32     // split-K factor for h-GEMM

static const size_t YSIZE = (size_t)BB * CC * NN;   // 67108864

// ---- static scratch (no runtime allocation allowed) ----
__device__ float g_bcdt[(size_t)BB * O3S * NN];   // GEMM1 output (pre-conv)
__device__ float g_conv[(size_t)BB * O3S * NN];   // conv output; dt channels later overwritten by AB
__device__ float g_hpart[(size_t)KSPLIT * BB * CC * SS]; // split-K partials
__device__ float g_h [BB * CC * SS];
__device__ float g_h3[BB * CC * SS];
__device__ float g_h4[BB * CC * SS];

// ============================================================================
// mma.sync helpers (legacy HMMA path — tcgen05 PTX is rejected at compute_103)
// ============================================================================
__device__ __forceinline__ uint32_t smem_u32(const void* p) {
    uint32_t a;
    asm("{ .reg .u64 t; cvta.to.shared.u64 t, %1; cvt.u32.u64 %0, t; }" : "=r"(a) : "l"(p));
    return a;
}
__device__ __forceinline__ void ldsm_x4(uint32_t* r, uint32_t addr) {
    asm volatile("ldmatrix.sync.aligned.m8n8.x4.shared.b16 {%0,%1,%2,%3}, [%4];"
        : "=r"(r[0]), "=r"(r[1]), "=r"(r[2]), "=r"(r[3]) : "r"(addr));
}
__device__ __forceinline__ void ldsm_x2_t(uint32_t* r, uint32_t addr) {
    asm volatile("ldmatrix.sync.aligned.m8n8.x2.trans.shared.b16 {%0,%1}, [%2];"
        : "=r"(r[0]), "=r"(r[1]) : "r"(addr));
}
__device__ __forceinline__ void mma_bf16(float* c, const uint32_t* a, const uint32_t* b) {
    asm volatile(
        "mma.sync.aligned.m16n8k16.row.col.f32.bf16.bf16.f32 "
        "{%0,%1,%2,%3}, {%4,%5,%6,%7}, {%8,%9}, {%0,%1,%2,%3};"
        : "+f"(c[0]), "+f"(c[1]), "+f"(c[2]), "+f"(c[3])
        : "r"(a[0]), "r"(a[1]), "r"(a[2]), "r"(a[3]), "r"(b[0]), "r"(b[1]));
}
// fp32 -> bf16 hi/lo split, packed pairs
__device__ __forceinline__ void split2(float v0, float v1, uint32_t& hi, uint32_t& lo) {
    __nv_bfloat16 h0 = __float2bfloat16(v0), h1 = __float2bfloat16(v1);
    float r0 = v0 - __bfloat162float(h0), r1 = v1 - __bfloat162float(h1);
    __nv_bfloat162 hh = __halves2bfloat162(h0, h1);
    __nv_bfloat162 ll = __floats2bfloat162_rn(r0, r1);
    hi = *(uint32_t*)&hh; lo = *(uint32_t*)&ll;
}

// ============================================================================
// Kernel 1 (HMMA): BCdt = W_bcdt(192x256) @ x(b,256,N) + b_bcdt
// bf16 hi/lo split (3 passes). BM=64, BN=128, BK=32. 8 warps: 2(m) x 4(n).
// ============================================================================
#define A_STRIDE 40    // halves per A row (32 + 8 pad) -> conflict-free ldmatrix
#define B_STRIDE 136   // halves per B row (128 + 8 pad)

__global__ void __launch_bounds__(256) gemm1_mma_kernel(
    const float* __restrict__ x, const float* __restrict__ W,
    const float* __restrict__ bias)
{
    __shared__ __align__(16) uint16_t As_hi[64 * A_STRIDE];
    __shared__ __align__(16) uint16_t As_lo[64 * A_STRIDE];
    __shared__ __align__(16) uint16_t Bs_hi[32 * B_STRIDE];
    __shared__ __align__(16) uint16_t Bs_lo[32 * B_STRIDE];

    const int n0 = blockIdx.x * 128;
    const int m0 = blockIdx.y * 64;    // 0,64,128 : all rows valid (192 = 3*64)
    const int b  = blockIdx.z;
    const int tid  = threadIdx.x;
    const int wid  = tid >> 5;
    const int lane = tid & 31;
    const int wm = wid >> 2;           // 0..1  (m)
    const int wn = wid & 3;            // 0..3  (n)

    const float* xb = x + (size_t)b * CC * NN;

    const uint32_t as_hi = smem_u32(As_hi), as_lo = smem_u32(As_lo);
    const uint32_t bs_hi = smem_u32(Bs_hi), bs_lo = smem_u32(Bs_lo);

    float acc[2][4][4];
#pragma unroll
    for (int i = 0; i < 2; i++)
#pragma unroll
        for (int j = 0; j < 4; j++)
#pragma unroll
            for (int q = 0; q < 4; q++) acc[i][j][q] = 0.f;

    for (int k0 = 0; k0 < 256; k0 += 32) {
        // ---- load W tile 64m x 32k (512 float4, 2/thread) ----
#pragma unroll
        for (int r = 0; r < 2; r++) {
            int f = tid + r * 256;
            int m = f >> 3, k = (f & 7) << 2;
            float4 v = *(const float4*)(W + (size_t)(m0 + m) * 256 + k0 + k);
            uint32_t h01, l01, h23, l23;
            split2(v.x, v.y, h01, l01);
            split2(v.z, v.w, h23, l23);
            int off = m * A_STRIDE + k;
            *(uint2*)(As_hi + off) = make_uint2(h01, h23);
            *(uint2*)(As_lo + off) = make_uint2(l01, l23);
        }
        // ---- load x tile 32k x 128n (1024 float4, 4/thread) ----
#pragma unroll
        for (int r = 0; r < 4; r++) {
            int f = tid + r * 256;
            int krow = f >> 5, n = (f & 31) << 2;
            float4 v = *(const float4*)(xb + (size_t)(k0 + krow) * NN + n0 + n);
            uint32_t h01, l01, h23, l23;
            split2(v.x, v.y, h01, l01);
            split2(v.z, v.w, h23, l23);
            int off = krow * B_STRIDE + n;
            *(uint2*)(Bs_hi + off) = make_uint2(h01, h23);
            *(uint2*)(Bs_lo + off) = make_uint2(l01, l23);
        }
        __syncthreads();

#pragma unroll
        for (int ks = 0; ks < 2; ks++) {
            // A fragments: 2 m-tiles x (hi,lo)
            uint32_t a_hi[2][4], a_lo[2][4];
            const int arow = lane & 15;
            const int acol = (lane >> 4) << 3;   // 0 or 8 halves
#pragma unroll
            for (int mi = 0; mi < 2; mi++) {
                uint32_t off = (uint32_t)((wm * 32 + mi * 16 + arow) * A_STRIDE
                                          + ks * 16 + acol) * 2;
                ldsm_x4(a_hi[mi], as_hi + off);
                ldsm_x4(a_lo[mi], as_lo + off);
            }
            // B fragments: 4 n-tiles x (hi,lo)
            uint32_t b_hi[4][2], b_lo[4][2];
            const int brow = lane & 15;          // k within 16
#pragma unroll
            for (int ni = 0; ni < 4; ni++) {
                uint32_t off = (uint32_t)((ks * 16 + brow) * B_STRIDE
                                          + wn * 32 + ni * 8) * 2;
                ldsm_x2_t(b_hi[ni], bs_hi + off);
                ldsm_x2_t(b_lo[ni], bs_lo + off);
            }
#pragma unroll
            for (int mi = 0; mi < 2; mi++)
#pragma unroll
                for (int ni = 0; ni < 4; ni++) {
                    mma_bf16(acc[mi][ni], a_hi[mi], b_hi[ni]);
                    mma_bf16(acc[mi][ni], a_hi[mi], b_lo[ni]);
                    mma_bf16(acc[mi][ni], a_lo[mi], b_hi[ni]);
                }
        }
        __syncthreads();
    }

    // ---- epilogue: + bias, store fp32 ----
    const int qrow = lane >> 2;
    const int qcol = (lane & 3) << 1;
#pragma unroll
    for (int mi = 0; mi < 2; mi++) {
        int mA = m0 + wm * 32 + mi * 16 + qrow;
        float bA = bias[mA], bB = bias[mA + 8];
        float* rowA = g_bcdt + ((size_t)(b * O3S + mA)) * NN + n0;
        float* rowB = rowA + (size_t)8 * NN;
#pragma unroll
        for (int ni = 0; ni < 4; ni++) {
            int n = wn * 32 + ni * 8 + qcol;
            *(float2*)(rowA + n) = make_float2(acc[mi][ni][0] + bA, acc[mi][ni][1] + bA);
            *(float2*)(rowB + n) = make_float2(acc[mi][ni][2] + bB, acc[mi][ni][3] + bB);
        }
    }
}

// ============================================================================
// Kernel 2: depthwise 3x3x3 conv (cross-correlation), pad 1, + b_dw
// ============================================================================
__global__ void __launch_bounds__(256) conv_kernel(
    const float* __restrict__ wdw, const float* __restrict__ bdw)
{
    __shared__ float s[3][34][66];
    __shared__ float wt[27];

    const int dz = blockIdx.x >> 1;
    const int hhalf = blockIdx.x & 1;
    const int ch = blockIdx.y;
    const int b  = blockIdx.z;
    const int h0 = hhalf * 32;
    const int tid = threadIdx.x;

    const float* base = g_bcdt + ((size_t)(b * O3S + ch)) * NN;

    for (int idx = tid; idx < 3 * 34 * 66; idx += 256) {
        int kd = idx / (34 * 66);
        int rem = idx % (34 * 66);
        int ih = rem / 66, iw = rem % 66;
        int d = dz - 1 + kd, h = h0 - 1 + ih, w = iw - 1;
        float v = 0.f;
        if ((unsigned)d < DD && (unsigned)h < HH && (unsigned)w < WW)
            v = base[((size_t)d * HH + h) * WW + w];
        s[kd][ih][iw] = v;
    }
    if (tid < 27) wt[tid] = wdw[ch * 27 + tid];
    __syncthreads();

    const float bb = bdw[ch];
    const int w = tid & 63;
    const int hl0 = tid >> 6;   // 0..3
    float* outb = g_conv + ((size_t)(b * O3S + ch)) * NN;

#pragma unroll
    for (int r = 0; r < 8; r++) {
        int hl = hl0 + r * 4;   // 0..31
        float acc = bb;
#pragma unroll
        for (int kd = 0; kd < 3; kd++)
#pragma unroll
            for (int kh = 0; kh < 3; kh++)
#pragma unroll
                for (int kw = 0; kw < 3; kw++)
                    acc += s[kd][hl + kh][w + kw] * wt[kd * 9 + kh * 3 + kw];
        outb[((size_t)dz * HH + h0 + hl) * WW + w] = acc;
    }
}

// ============================================================================
// Kernel 3: softmax over n of dt row (A cancels), fused AB = softmax * B_
// ============================================================================
__global__ void __launch_bounds__(256) softmax_ab_kernel()
{
    const int s_ = blockIdx.x;
    const int b  = blockIdx.y;
    float* dt = g_conv + ((size_t)(b * O3S + 128 + s_)) * NN;
    const float* Bp = g_conv + ((size_t)(b * O3S + s_)) * NN;
    const int tid = threadIdx.x;

    float m = -1e30f, sum = 0.f;
    for (int i = tid * 4; i < NN; i += 1024) {
        float4 v = *(float4*)(dt + i);
        float vals[4] = {v.x, v.y, v.z, v.w};
#pragma unroll
        for (int q = 0; q < 4; q++) {
            float val = vals[q];
            if (val > m) { sum *= __expf(m - val); m = val; }
            sum += __expf(val - m);
        }
    }
    __shared__ float sm[256], ssum[256];
    sm[tid] = m; ssum[tid] = sum;
    __syncthreads();
    for (int off = 128; off > 0; off >>= 1) {
        if (tid < off) {
            float m2 = sm[tid + off], s2 = ssum[tid + off];
            float M = fmaxf(sm[tid], m2);
            ssum[tid] = ssum[tid] * __expf(sm[tid] - M) + s2 * __expf(m2 - M);
            sm[tid] = M;
        }
        __syncthreads();
    }
    const float M = sm[0];
    const float inv = 1.f / ssum[0];

    for (int i = tid * 4; i < NN; i += 1024) {
        float4 v  = *(float4*)(dt + i);
        float4 bv = *(const float4*)(Bp + i);
        float4 o;
        o.x = __expf(v.x - M) * inv * bv.x;
        o.y = __expf(v.y - M) * inv * bv.y;
        o.z = __expf(v.z - M) * inv * bv.z;
        o.w = __expf(v.w - M) * inv * bv.w;
        *(float4*)(dt + i) = o;
    }
}

// ============================================================================
// Kernel 4: h[b,c,s] = sum_n x[b,c,n] * AB[b,s,n]   (split-K partials)
// ============================================================================
__global__ void __launch_bounds__(256) hgemm_kernel(const float* __restrict__ x)
{
    __shared__ float As[64 * 65];  // x tile: [c][kk]
    __shared__ float Bs[64 * 65];  // AB tile transposed: [kk][s]

    const int ks = blockIdx.x;          // 0..31
    const int c0 = blockIdx.y * 64;
    const int b  = blockIdx.z;
    const int nbase = ks * (NN / KSPLIT);  // 2048 chunk
    const int tid = threadIdx.x;
    const int tx = tid & 15;   // s
    const int ty = tid >> 4;   // c

    const float* xb = x + ((size_t)(b * CC + c0)) * NN;
    const float* ab = g_conv + ((size_t)(b * O3S + 128)) * NN;

    float acc[4][4];
#pragma unroll
    for (int i = 0; i < 4; i++)
#pragma unroll
        for (int j = 0; j < 4; j++) acc[i][j] = 0.f;

    for (int kc = 0; kc < NN / KSPLIT; kc += 64) {
        const int nb = nbase + kc;
#pragma unroll
        for (int r = 0; r < 16; r++) {
            int idx = tid + r * 256;
            int i = idx >> 6, kk = idx & 63;
            As[i * 65 + kk] = xb[(size_t)i * NN + nb + kk];
        }
#pragma unroll
        for (int r = 0; r < 16; r++) {
            int idx = tid + r * 256;
            int sr = idx >> 6, kk = idx & 63;
            Bs[kk * 65 + sr] = ab[(size_t)sr * NN + nb + kk];
        }
        __syncthreads();
#pragma unroll 8
        for (int kk = 0; kk < 64; kk++) {
            float a0 = As[(ty * 4 + 0) * 65 + kk];
            float a1 = As[(ty * 4 + 1) * 65 + kk];
            float a2 = As[(ty * 4 + 2) * 65 + kk];
            float a3 = As[(ty * 4 + 3) * 65 + kk];
            float b0 = Bs[kk * 65 + tx * 4 + 0];
            float b1 = Bs[kk * 65 + tx * 4 + 1];
            float b2 = Bs[kk * 65 + tx * 4 + 2];
            float b3 = Bs[kk * 65 + tx * 4 + 3];
            float av[4] = {a0, a1, a2, a3};
            float bv[4] = {b0, b1, b2, b3};
#pragma unroll
            for (int i = 0; i < 4; i++)
#pragma unroll
                for (int j = 0; j < 4; j++) acc[i][j] += av[i] * bv[j];
        }
        __syncthreads();
    }
    float* dst = g_hpart + (size_t)ks * (BB * CC * SS);
#pragma unroll
    for (int i = 0; i < 4; i++)
#pragma unroll
        for (int j = 0; j < 4; j++)
            dst[((size_t)(b * CC + c0 + ty * 4 + i)) * SS + tx * 4 + j] = acc[i][j];
}

// deterministic reduction of split-K partials
__global__ void __launch_bounds__(256) hreduce_kernel()
{
    int i = blockIdx.x * 256 + threadIdx.x;   // < 65536
    float sum = 0.f;
#pragma unroll
    for (int ks = 0; ks < KSPLIT; ks++)
        sum += g_hpart[(size_t)ks * (BB * CC * SS) + i];
    g_h[i] = sum;
}

// ============================================================================
// Kernel 5: hz = W_hz @ h + b_hz ; h3 = h2*silu(z) + h2*Dp
// ============================================================================
__global__ void __launch_bounds__(256) e1_kernel(
    const float* __restrict__ Whz, const float* __restrict__ bhz,
    const float* __restrict__ Dp)
{
    const int b = blockIdx.y;
    const int o = blockIdx.x * 4 + (threadIdx.x >> 6);
    const int s_ = threadIdx.x & 63;
    const float* hb = g_h + (size_t)b * CC * SS;
    const float* w1 = Whz + (size_t)o * 256;
    const float* w2 = Whz + (size_t)(o + 256) * 256;
    float a1 = bhz[o], a2 = bhz[o + 256];
    for (int c = 0; c < 256; c++) {
        float hv = hb[c * 64 + s_];
        a1 += w1[c] * hv;
        a2 += w2[c] * hv;
    }
    float sig = 1.f / (1.f + __expf(-a2));
    g_h3[((size_t)b * CC + o) * SS + s_] = a1 * (a2 * sig) + a1 * Dp[0];
}

// Kernel 6: h4 = W_out @ h3 + b_out ; write to scratch + output tail
__global__ void __launch_bounds__(256) e2_kernel(
    const float* __restrict__ Wout, const float* __restrict__ bout,
    float* __restrict__ out)
{
    const int b = blockIdx.y;
    const int o = blockIdx.x * 4 + (threadIdx.x >> 6);
    const int s_ = threadIdx.x & 63;
    const float* hb = g_h3 + (size_t)b * CC * SS;
    const float* w1 = Wout + (size_t)o * 256;
    float acc = bout[o];
    for (int c = 0; c < 256; c++)
        acc += w1[c] * hb[c * 64 + s_];
    size_t idx = ((size_t)b * CC + o) * SS + s_;
    g_h4[idx] = acc;
    out[YSIZE + idx] = acc;
}

// ============================================================================
// Kernel 7: y[b,c,n] = sum_s h4[b,c,s] * C_[b,s,n]
// ============================================================================
__global__ void __launch_bounds__(256) ygemm_kernel(float* __restrict__ y)
{
    __shared__ __align__(16) float As[64 * 64];   // h4 [c][s]
    __shared__ __align__(16) float Bs[64 * 128];  // C_ [s][n]

    const int n0 = blockIdx.x * 128;
    const int c0 = blockIdx.y * 64;
    const int b  = blockIdx.z;
    const int tid = threadIdx.x;
    const int tx = tid & 15;
    const int ty = tid >> 4;

#pragma unroll
    for (int r = 0; r < 16; r++) {
        int idx = tid + r * 256;
        int i = idx >> 6, sr = idx & 63;
        As[i * 64 + sr] = g_h4[((size_t)(b * CC + c0 + i)) * SS + sr];
    }
    const float* cp = g_conv + ((size_t)(b * O3S + 64)) * NN;  // C_ channels
#pragma unroll
    for (int r = 0; r < 8; r++) {
        int f = tid + r * 256;
        int sr = f >> 5, j4 = f & 31;
        float4 v = *(const float4*)(cp + (size_t)sr * NN + n0 + j4 * 4);
        *(float4*)(&Bs[sr * 128 + j4 * 4]) = v;
    }
    __syncthreads();

    float acc[4][8];
#pragma unroll
    for (int i = 0; i < 4; i++)
#pragma unroll
        for (int j = 0; j < 8; j++) acc[i][j] = 0.f;

#pragma unroll 8
    for (int k = 0; k < 64; k++) {
        float a0 = As[(ty * 4 + 0) * 64 + k];
        float a1 = As[(ty * 4 + 1) * 64 + k];
        float a2 = As[(ty * 4 + 2) * 64 + k];
        float a3 = As[(ty * 4 + 3) * 64 + k];
        float4 b0 = *(float4*)(&Bs[k * 128 + tx * 8]);
        float4 b1 = *(float4*)(&Bs[k * 128 + tx * 8 + 4]);
        float av[4] = {a0, a1, a2, a3};
        float bv[8] = {b0.x, b0.y, b0.z, b0.w, b1.x, b1.y, b1.z, b1.w};
#pragma unroll
        for (int i = 0; i < 4; i++)
#pragma unroll
            for (int j = 0; j < 8; j++) acc[i][j] += av[i] * bv[j];
    }
#pragma unroll
    for (int i = 0; i < 4; i++) {
        float* dst = y + ((size_t)(b * CC + c0 + ty * 4 + i)) * NN + n0 + tx * 8;
        float4 o0 = make_float4(acc[i][0], acc[i][1], acc[i][2], acc[i][3]);
        float4 o1 = make_float4(acc[i][4], acc[i][5], acc[i][6], acc[i][7]);
        *(float4*)(dst)     = o0;
        *(float4*)(dst + 4) = o1;
    }
}

// ============================================================================
extern "C" void kernel_launch(void* const* d_in, const int* in_sizes, int n_in,
                              void* d_out, int out_size)
{
    const float* x      = (const float*)d_in[0];
    const float* W_bcdt = (const float*)d_in[1];
    const float* b_bcdt = (const float*)d_in[2];
    const float* W_dw   = (const float*)d_in[3];
    const float* b_dw   = (const float*)d_in[4];
    const float* W_hz   = (const float*)d_in[5];
    const float* b_hz   = (const float*)d_in[6];
    const float* W_out  = (const float*)d_in[7];
    const float* b_out  = (const float*)d_in[8];
    // d_in[9] = A : unused (softmax shift invariance along the reduced axis)
    const float* Dp     = (const float*)d_in[10];
    float* out = (float*)d_out;

    gemm1_mma_kernel<<<dim3(NN / 128, 3, BB), 256>>>(x, W_bcdt, b_bcdt);
    conv_kernel<<<dim3(32, O3S, BB), 256>>>(W_dw, b_dw);
    softmax_ab_kernel<<<dim3(SS, BB), 256>>>();
    hgemm_kernel<<<dim3(KSPLIT, 4, BB), 256>>>(x);
    hreduce_kernel<<<256, 256>>>();
    e1_kernel<<<dim3(64, BB), 256>>>(W_hz, b_hz, Dp);
    e2_kernel<<<dim3(64, BB), 256>>>(W_out, b_out, out);
    ygemm_kernel<<<dim3(NN / 128, 4, BB), 256>>>(out);
}

// round 4
// speedup vs baseline: 2.0364x; 1.3763x over previous
#include <cuda_runtime.h>
#include <cuda_bf16.h>
#include <cstdint>
#include <cstddef>

// Problem constants
#define BB   4
#define CC   256      // D_MODEL = D_INNER
#define SS   64
#define DD   16
#define HH   64
#define WW   64
#define NN   65536    // D*H*W
#define O3S  192      // 3*S
#define KSPLIT_H 64   // split-K factor for h-GEMM

static const size_t YSIZE = (size_t)BB * CC * NN;   // 67108864

// ---- static scratch (no runtime allocation allowed) ----
__device__ float g_bcdt[(size_t)BB * O3S * NN];
__device__ float g_conv[(size_t)BB * O3S * NN];
__device__ float g_hpart[(size_t)KSPLIT_H * BB * CC * SS];
__device__ float g_h [BB * CC * SS];
__device__ float g_h3[BB * CC * SS];
__device__ float g_h4[BB * CC * SS];

// ============================================================================
// mma.sync helpers (legacy HMMA path — tcgen05 PTX is rejected at compute_103)
// ============================================================================
__device__ __forceinline__ uint32_t smem_u32(const void* p) {
    uint32_t a;
    asm("{ .reg .u64 t; cvta.to.shared.u64 t, %1; cvt.u32.u64 %0, t; }" : "=r"(a) : "l"(p));
    return a;
}
__device__ __forceinline__ void ldsm_x4(uint32_t* r, uint32_t addr) {
    asm volatile("ldmatrix.sync.aligned.m8n8.x4.shared.b16 {%0,%1,%2,%3}, [%4];"
        : "=r"(r[0]), "=r"(r[1]), "=r"(r[2]), "=r"(r[3]) : "r"(addr));
}
__device__ __forceinline__ void ldsm_x2(uint32_t* r, uint32_t addr) {
    asm volatile("ldmatrix.sync.aligned.m8n8.x2.shared.b16 {%0,%1}, [%2];"
        : "=r"(r[0]), "=r"(r[1]) : "r"(addr));
}
__device__ __forceinline__ void ldsm_x2_t(uint32_t* r, uint32_t addr) {
    asm volatile("ldmatrix.sync.aligned.m8n8.x2.trans.shared.b16 {%0,%1}, [%2];"
        : "=r"(r[0]), "=r"(r[1]) : "r"(addr));
}
__device__ __forceinline__ void mma_bf16(float* c, const uint32_t* a, const uint32_t* b) {
    asm volatile(
        "mma.sync.aligned.m16n8k16.row.col.f32.bf16.bf16.f32 "
        "{%0,%1,%2,%3}, {%4,%5,%6,%7}, {%8,%9}, {%0,%1,%2,%3};"
        : "+f"(c[0]), "+f"(c[1]), "+f"(c[2]), "+f"(c[3])
        : "r"(a[0]), "r"(a[1]), "r"(a[2]), "r"(a[3]), "r"(b[0]), "r"(b[1]));
}
// fp32 -> bf16 hi/lo split, packed pairs
__device__ __forceinline__ void split2(float v0, float v1, uint32_t& hi, uint32_t& lo) {
    __nv_bfloat16 h0 = __float2bfloat16(v0), h1 = __float2bfloat16(v1);
    float r0 = v0 - __bfloat162float(h0), r1 = v1 - __bfloat162float(h1);
    __nv_bfloat162 hh = __halves2bfloat162(h0, h1);
    __nv_bfloat162 ll = __floats2bfloat162_rn(r0, r1);
    hi = *(uint32_t*)&hh; lo = *(uint32_t*)&ll;
}

#define A_STRIDE 40    // halves per 32-k row (32 + 8 pad)
#define B_STRIDE 136   // halves per 128-n row (128 + 8 pad)

// ============================================================================
// Kernel 1 (HMMA): BCdt = W_bcdt(192x256) @ x(b,256,N) + b_bcdt
// bf16 hi/lo split (3 passes). BM=64, BN=128, BK=32. 8 warps: 2(m) x 4(n).
// ============================================================================
__global__ void __launch_bounds__(256) gemm1_mma_kernel(
    const float* __restrict__ x, const float* __restrict__ W,
    const float* __restrict__ bias)
{
    __shared__ __align__(16) uint16_t As_hi[64 * A_STRIDE];
    __shared__ __align__(16) uint16_t As_lo[64 * A_STRIDE];
    __shared__ __align__(16) uint16_t Bs_hi[32 * B_STRIDE];
    __shared__ __align__(16) uint16_t Bs_lo[32 * B_STRIDE];

    const int n0 = blockIdx.x * 128;
    const int m0 = blockIdx.y * 64;
    const int b  = blockIdx.z;
    const int tid  = threadIdx.x;
    const int wid  = tid >> 5;
    const int lane = tid & 31;
    const int wm = wid >> 2;
    const int wn = wid & 3;

    const float* xb = x + (size_t)b * CC * NN;
    const uint32_t as_hi = smem_u32(As_hi), as_lo = smem_u32(As_lo);
    const uint32_t bs_hi = smem_u32(Bs_hi), bs_lo = smem_u32(Bs_lo);

    float acc[2][4][4];
#pragma unroll
    for (int i = 0; i < 2; i++)
#pragma unroll
        for (int j = 0; j < 4; j++)
#pragma unroll
            for (int q = 0; q < 4; q++) acc[i][j][q] = 0.f;

    for (int k0 = 0; k0 < 256; k0 += 32) {
#pragma unroll
        for (int r = 0; r < 2; r++) {
            int f = tid + r * 256;
            int m = f >> 3, k = (f & 7) << 2;
            float4 v = *(const float4*)(W + (size_t)(m0 + m) * 256 + k0 + k);
            uint32_t h01, l01, h23, l23;
            split2(v.x, v.y, h01, l01);
            split2(v.z, v.w, h23, l23);
            int off = m * A_STRIDE + k;
            *(uint2*)(As_hi + off) = make_uint2(h01, h23);
            *(uint2*)(As_lo + off) = make_uint2(l01, l23);
        }
#pragma unroll
        for (int r = 0; r < 4; r++) {
            int f = tid + r * 256;
            int krow = f >> 5, n = (f & 31) << 2;
            float4 v = *(const float4*)(xb + (size_t)(k0 + krow) * NN + n0 + n);
            uint32_t h01, l01, h23, l23;
            split2(v.x, v.y, h01, l01);
            split2(v.z, v.w, h23, l23);
            int off = krow * B_STRIDE + n;
            *(uint2*)(Bs_hi + off) = make_uint2(h01, h23);
            *(uint2*)(Bs_lo + off) = make_uint2(l01, l23);
        }
        __syncthreads();

#pragma unroll
        for (int ks = 0; ks < 2; ks++) {
            uint32_t a_hi[2][4], a_lo[2][4];
            const int arow = lane & 15;
            const int acol = (lane >> 4) << 3;
#pragma unroll
            for (int mi = 0; mi < 2; mi++) {
                uint32_t off = (uint32_t)((wm * 32 + mi * 16 + arow) * A_STRIDE
                                          + ks * 16 + acol) * 2;
                ldsm_x4(a_hi[mi], as_hi + off);
                ldsm_x4(a_lo[mi], as_lo + off);
            }
            uint32_t b_hi[4][2], b_lo[4][2];
            const int brow = lane & 15;
#pragma unroll
            for (int ni = 0; ni < 4; ni++) {
                uint32_t off = (uint32_t)((ks * 16 + brow) * B_STRIDE
                                          + wn * 32 + ni * 8) * 2;
                ldsm_x2_t(b_hi[ni], bs_hi + off);
                ldsm_x2_t(b_lo[ni], bs_lo + off);
            }
#pragma unroll
            for (int mi = 0; mi < 2; mi++)
#pragma unroll
                for (int ni = 0; ni < 4; ni++) {
                    mma_bf16(acc[mi][ni], a_hi[mi], b_hi[ni]);
                    mma_bf16(acc[mi][ni], a_hi[mi], b_lo[ni]);
                    mma_bf16(acc[mi][ni], a_lo[mi], b_hi[ni]);
                }
        }
        __syncthreads();
    }

    const int qrow = lane >> 2;
    const int qcol = (lane & 3) << 1;
#pragma unroll
    for (int mi = 0; mi < 2; mi++) {
        int mA = m0 + wm * 32 + mi * 16 + qrow;
        float bA = bias[mA], bB = bias[mA + 8];
        float* rowA = g_bcdt + ((size_t)(b * O3S + mA)) * NN + n0;
        float* rowB = rowA + (size_t)8 * NN;
#pragma unroll
        for (int ni = 0; ni < 4; ni++) {
            int n = wn * 32 + ni * 8 + qcol;
            *(float2*)(rowA + n) = make_float2(acc[mi][ni][0] + bA, acc[mi][ni][1] + bA);
            *(float2*)(rowB + n) = make_float2(acc[mi][ni][2] + bB, acc[mi][ni][3] + bB);
        }
    }
}

// ============================================================================
// Kernel 2: depthwise 3x3x3 conv, pad 1, + b_dw
// ============================================================================
__global__ void __launch_bounds__(256) conv_kernel(
    const float* __restrict__ wdw, const float* __restrict__ bdw)
{
    __shared__ float s[3][34][66];
    __shared__ float wt[27];

    const int dz = blockIdx.x >> 1;
    const int hhalf = blockIdx.x & 1;
    const int ch = blockIdx.y;
    const int b  = blockIdx.z;
    const int h0 = hhalf * 32;
    const int tid = threadIdx.x;

    const float* base = g_bcdt + ((size_t)(b * O3S + ch)) * NN;

    for (int idx = tid; idx < 3 * 34 * 66; idx += 256) {
        int kd = idx / (34 * 66);
        int rem = idx % (34 * 66);
        int ih = rem / 66, iw = rem % 66;
        int d = dz - 1 + kd, h = h0 - 1 + ih, w = iw - 1;
        float v = 0.f;
        if ((unsigned)d < DD && (unsigned)h < HH && (unsigned)w < WW)
            v = base[((size_t)d * HH + h) * WW + w];
        s[kd][ih][iw] = v;
    }
    if (tid < 27) wt[tid] = wdw[ch * 27 + tid];
    __syncthreads();

    const float bb = bdw[ch];
    const int w = tid & 63;
    const int hl0 = tid >> 6;
    float* outb = g_conv + ((size_t)(b * O3S + ch)) * NN;

#pragma unroll
    for (int r = 0; r < 8; r++) {
        int hl = hl0 + r * 4;
        float acc = bb;
#pragma unroll
        for (int kd = 0; kd < 3; kd++)
#pragma unroll
            for (int kh = 0; kh < 3; kh++)
#pragma unroll
                for (int kw = 0; kw < 3; kw++)
                    acc += s[kd][hl + kh][w + kw] * wt[kd * 9 + kh * 3 + kw];
        outb[((size_t)dz * HH + h0 + hl) * WW + w] = acc;
    }
}

// ============================================================================
// Kernel 3: softmax over n of dt (A cancels), fused AB = softmax * B_
// ============================================================================
__global__ void __launch_bounds__(256) softmax_ab_kernel()
{
    const int s_ = blockIdx.x;
    const int b  = blockIdx.y;
    float* dt = g_conv + ((size_t)(b * O3S + 128 + s_)) * NN;
    const float* Bp = g_conv + ((size_t)(b * O3S + s_)) * NN;
    const int tid = threadIdx.x;

    float m = -1e30f, sum = 0.f;
    for (int i = tid * 4; i < NN; i += 1024) {
        float4 v = *(float4*)(dt + i);
        float vals[4] = {v.x, v.y, v.z, v.w};
#pragma unroll
        for (int q = 0; q < 4; q++) {
            float val = vals[q];
            if (val > m) { sum *= __expf(m - val); m = val; }
            sum += __expf(val - m);
        }
    }
    __shared__ float sm[256], ssum[256];
    sm[tid] = m; ssum[tid] = sum;
    __syncthreads();
    for (int off = 128; off > 0; off >>= 1) {
        if (tid < off) {
            float m2 = sm[tid + off], s2 = ssum[tid + off];
            float M = fmaxf(sm[tid], m2);
            ssum[tid] = ssum[tid] * __expf(sm[tid] - M) + s2 * __expf(m2 - M);
            sm[tid] = M;
        }
        __syncthreads();
    }
    const float M = sm[0];
    const float inv = 1.f / ssum[0];

    for (int i = tid * 4; i < NN; i += 1024) {
        float4 v  = *(float4*)(dt + i);
        float4 bv = *(const float4*)(Bp + i);
        float4 o;
        o.x = __expf(v.x - M) * inv * bv.x;
        o.y = __expf(v.y - M) * inv * bv.y;
        o.z = __expf(v.z - M) * inv * bv.z;
        o.w = __expf(v.w - M) * inv * bv.w;
        *(float4*)(dt + i) = o;
    }
}

// ============================================================================
// Kernel 4 (HMMA): h[b,c,s] = sum_n x[b,c,n] * AB[b,s,n]   split-K partials
// A = x (row-major K-major), B = AB (col-major: [s][n], n=k contiguous).
// BM=128(c), BN=64(s), BK=32. 8 warps: 2(m) x 4(n). hi/lo 3 passes.
// ============================================================================
#define HB_STRIDE 40   // halves per 32-k row of B (s rows)

__global__ void __launch_bounds__(256) hgemm_mma_kernel(const float* __restrict__ x)
{
    __shared__ __align__(16) uint16_t As_hi[128 * A_STRIDE];
    __shared__ __align__(16) uint16_t As_lo[128 * A_STRIDE];
    __shared__ __align__(16) uint16_t Bs_hi[64 * HB_STRIDE];
    __shared__ __align__(16) uint16_t Bs_lo[64 * HB_STRIDE];

    const int ks = blockIdx.x;               // 0..63
    const int c0 = blockIdx.y * 128;         // 0,128
    const int b  = blockIdx.z;
    const int nbase = ks * (NN / KSPLIT_H);  // 1024 chunk
    const int tid  = threadIdx.x;
    const int wid  = tid >> 5;
    const int lane = tid & 31;
    const int wm = wid >> 2;                 // 0..1 (c)
    const int wn = wid & 3;                  // 0..3 (s)

    const float* xb = x + ((size_t)(b * CC + c0)) * NN;
    const float* ab = g_conv + ((size_t)(b * O3S + 128)) * NN;
    const uint32_t as_hi = smem_u32(As_hi), as_lo = smem_u32(As_lo);
    const uint32_t bs_hi = smem_u32(Bs_hi), bs_lo = smem_u32(Bs_lo);

    float acc[4][2][4];
#pragma unroll
    for (int i = 0; i < 4; i++)
#pragma unroll
        for (int j = 0; j < 2; j++)
#pragma unroll
            for (int q = 0; q < 4; q++) acc[i][j][q] = 0.f;

    for (int kc = 0; kc < NN / KSPLIT_H; kc += 32) {
        const int nb = nbase + kc;
        // x tile 128c x 32k: 1024 float4, 4/thread
#pragma unroll
        for (int r = 0; r < 4; r++) {
            int f = tid + r * 256;
            int c = f >> 3, k = (f & 7) << 2;
            float4 v = *(const float4*)(xb + (size_t)c * NN + nb + k);
            uint32_t h01, l01, h23, l23;
            split2(v.x, v.y, h01, l01);
            split2(v.z, v.w, h23, l23);
            int off = c * A_STRIDE + k;
            *(uint2*)(As_hi + off) = make_uint2(h01, h23);
            *(uint2*)(As_lo + off) = make_uint2(l01, l23);
        }
        // AB tile 64s x 32k: 512 float4, 2/thread
#pragma unroll
        for (int r = 0; r < 2; r++) {
            int f = tid + r * 256;
            int sr = f >> 3, k = (f & 7) << 2;
            float4 v = *(const float4*)(ab + (size_t)sr * NN + nb + k);
            uint32_t h01, l01, h23, l23;
            split2(v.x, v.y, h01, l01);
            split2(v.z, v.w, h23, l23);
            int off = sr * HB_STRIDE + k;
            *(uint2*)(Bs_hi + off) = make_uint2(h01, h23);
            *(uint2*)(Bs_lo + off) = make_uint2(l01, l23);
        }
        __syncthreads();

#pragma unroll
        for (int kq = 0; kq < 2; kq++) {
            uint32_t a_hi[4][4], a_lo[4][4];
            const int arow = lane & 15;
            const int acol = (lane >> 4) << 3;
#pragma unroll
            for (int mi = 0; mi < 4; mi++) {
                uint32_t off = (uint32_t)((wm * 64 + mi * 16 + arow) * A_STRIDE
                                          + kq * 16 + acol) * 2;
                ldsm_x4(a_hi[mi], as_hi + off);
                ldsm_x4(a_lo[mi], as_lo + off);
            }
            // B: [s][k] k-contiguous -> non-trans x2.
            // lanes 0-7: rows s(ni*8+l) at k0 ; lanes 8-15: same rows at k0+8
            uint32_t b_hi[2][2], b_lo[2][2];
            const int l = lane & 15;
            const int srow = l & 7;
            const int koff = (l >> 3) << 3;
#pragma unroll
            for (int ni = 0; ni < 2; ni++) {
                uint32_t off = (uint32_t)((wn * 16 + ni * 8 + srow) * HB_STRIDE
                                          + kq * 16 + koff) * 2;
                ldsm_x2(b_hi[ni], bs_hi + off);
                ldsm_x2(b_lo[ni], bs_lo + off);
            }
#pragma unroll
            for (int mi = 0; mi < 4; mi++)
#pragma unroll
                for (int ni = 0; ni < 2; ni++) {
                    mma_bf16(acc[mi][ni], a_hi[mi], b_hi[ni]);
                    mma_bf16(acc[mi][ni], a_hi[mi], b_lo[ni]);
                    mma_bf16(acc[mi][ni], a_lo[mi], b_hi[ni]);
                }
        }
        __syncthreads();
    }

    // store partials: (c, s) per split slot
    float* dst = g_hpart + (size_t)ks * (BB * CC * SS);
    const int qrow = lane >> 2;
    const int qcol = (lane & 3) << 1;
#pragma unroll
    for (int mi = 0; mi < 4; mi++) {
        int cA = c0 + wm * 64 + mi * 16 + qrow;
#pragma unroll
        for (int ni = 0; ni < 2; ni++) {
            int sA = wn * 16 + ni * 8 + qcol;
            float* pA = dst + ((size_t)(b * CC + cA)) * SS + sA;
            float* pB = dst + ((size_t)(b * CC + cA + 8)) * SS + sA;
            *(float2*)pA = make_float2(acc[mi][ni][0], acc[mi][ni][1]);
            *(float2*)pB = make_float2(acc[mi][ni][2], acc[mi][ni][3]);
        }
    }
}

// deterministic reduction of split-K partials
__global__ void __launch_bounds__(256) hreduce_kernel()
{
    int i = blockIdx.x * 256 + threadIdx.x;   // < 65536
    float sum = 0.f;
#pragma unroll
    for (int ks = 0; ks < KSPLIT_H; ks++)
        sum += g_hpart[(size_t)ks * (BB * CC * SS) + i];
    g_h[i] = sum;
}

// ============================================================================
// Kernel 5: hz = W_hz @ h + b_hz ; h3 = h2*silu(z) + h2*Dp
// ============================================================================
__global__ void __launch_bounds__(256) e1_kernel(
    const float* __restrict__ Whz, const float* __restrict__ bhz,
    const float* __restrict__ Dp)
{
    const int b = blockIdx.y;
    const int o = blockIdx.x * 4 + (threadIdx.x >> 6);
    const int s_ = threadIdx.x & 63;
    const float* hb = g_h + (size_t)b * CC * SS;
    const float* w1 = Whz + (size_t)o * 256;
    const float* w2 = Whz + (size_t)(o + 256) * 256;
    float a1 = bhz[o], a2 = bhz[o + 256];
    for (int c = 0; c < 256; c++) {
        float hv = hb[c * 64 + s_];
        a1 += w1[c] * hv;
        a2 += w2[c] * hv;
    }
    float sig = 1.f / (1.f + __expf(-a2));
    g_h3[((size_t)b * CC + o) * SS + s_] = a1 * (a2 * sig) + a1 * Dp[0];
}

// Kernel 6: h4 = W_out @ h3 + b_out ; write to scratch + output tail
__global__ void __launch_bounds__(256) e2_kernel(
    const float* __restrict__ Wout, const float* __restrict__ bout,
    float* __restrict__ out)
{
    const int b = blockIdx.y;
    const int o = blockIdx.x * 4 + (threadIdx.x >> 6);
    const int s_ = threadIdx.x & 63;
    const float* hb = g_h3 + (size_t)b * CC * SS;
    const float* w1 = Wout + (size_t)o * 256;
    float acc = bout[o];
    for (int c = 0; c < 256; c++)
        acc += w1[c] * hb[c * 64 + s_];
    size_t idx = ((size_t)b * CC + o) * SS + s_;
    g_h4[idx] = acc;
    out[YSIZE + idx] = acc;
}

// ============================================================================
// Kernel 7 (HMMA): y[b,c,n] = sum_s h4[b,c,s] * C_[b,s,n]
// Clone of gemm1: BM=64, BN=128, K=64 (2 x BK=32). hi/lo 3 passes.
// ============================================================================
__global__ void __launch_bounds__(256) ygemm_mma_kernel(float* __restrict__ y)
{
    __shared__ __align__(16) uint16_t As_hi[64 * A_STRIDE];
    __shared__ __align__(16) uint16_t As_lo[64 * A_STRIDE];
    __shared__ __align__(16) uint16_t Bs_hi[32 * B_STRIDE];
    __shared__ __align__(16) uint16_t Bs_lo[32 * B_STRIDE];

    const int n0 = blockIdx.x * 128;
    const int m0 = blockIdx.y * 64;     // 0..192 (c)
    const int b  = blockIdx.z;
    const int tid  = threadIdx.x;
    const int wid  = tid >> 5;
    const int lane = tid & 31;
    const int wm = wid >> 2;
    const int wn = wid & 3;

    const float* h4b = g_h4 + (size_t)b * CC * SS;
    const float* cp  = g_conv + ((size_t)(b * O3S + 64)) * NN;  // C_ channels
    const uint32_t as_hi = smem_u32(As_hi), as_lo = smem_u32(As_lo);
    const uint32_t bs_hi = smem_u32(Bs_hi), bs_lo = smem_u32(Bs_lo);

    float acc[2][4][4];
#pragma unroll
    for (int i = 0; i < 2; i++)
#pragma unroll
        for (int j = 0; j < 4; j++)
#pragma unroll
            for (int q = 0; q < 4; q++) acc[i][j][q] = 0.f;

    for (int k0 = 0; k0 < 64; k0 += 32) {
        // h4 tile 64c x 32s: 512 float4, 2/thread
#pragma unroll
        for (int r = 0; r < 2; r++) {
            int f = tid + r * 256;
            int m = f >> 3, k = (f & 7) << 2;
            float4 v = *(const float4*)(h4b + (size_t)(m0 + m) * SS + k0 + k);
            uint32_t h01, l01, h23, l23;
            split2(v.x, v.y, h01, l01);
            split2(v.z, v.w, h23, l23);
            int off = m * A_STRIDE + k;
            *(uint2*)(As_hi + off) = make_uint2(h01, h23);
            *(uint2*)(As_lo + off) = make_uint2(l01, l23);
        }
        // C_ tile 32s x 128n: 1024 float4, 4/thread
#pragma unroll
        for (int r = 0; r < 4; r++) {
            int f = tid + r * 256;
            int krow = f >> 5, n = (f & 31) << 2;
            float4 v = *(const float4*)(cp + (size_t)(k0 + krow) * NN + n0 + n);
            uint32_t h01, l01, h23, l23;
            split2(v.x, v.y, h01, l01);
            split2(v.z, v.w, h23, l23);
            int off = krow * B_STRIDE + n;
            *(uint2*)(Bs_hi + off) = make_uint2(h01, h23);
            *(uint2*)(Bs_lo + off) = make_uint2(l01, l23);
        }
        __syncthreads();

#pragma unroll
        for (int ks = 0; ks < 2; ks++) {
            uint32_t a_hi[2][4], a_lo[2][4];
            const int arow = lane & 15;
            const int acol = (lane >> 4) << 3;
#pragma unroll
            for (int mi = 0; mi < 2; mi++) {
                uint32_t off = (uint32_t)((wm * 32 + mi * 16 + arow) * A_STRIDE
                                          + ks * 16 + acol) * 2;
                ldsm_x4(a_hi[mi], as_hi + off);
                ldsm_x4(a_lo[mi], as_lo + off);
            }
            uint32_t b_hi[4][2], b_lo[4][2];
            const int brow = lane & 15;
#pragma unroll
            for (int ni = 0; ni < 4; ni++) {
                uint32_t off = (uint32_t)((ks * 16 + brow) * B_STRIDE
                                          + wn * 32 + ni * 8) * 2;
                ldsm_x2_t(b_hi[ni], bs_hi + off);
                ldsm_x2_t(b_lo[ni], bs_lo + off);
            }
#pragma unroll
            for (int mi = 0; mi < 2; mi++)
#pragma unroll
                for (int ni = 0; ni < 4; ni++) {
                    mma_bf16(acc[mi][ni], a_hi[mi], b_hi[ni]);
                    mma_bf16(acc[mi][ni], a_hi[mi], b_lo[ni]);
                    mma_bf16(acc[mi][ni], a_lo[mi], b_hi[ni]);
                }
        }
        __syncthreads();
    }

    const int qrow = lane >> 2;
    const int qcol = (lane & 3) << 1;
#pragma unroll
    for (int mi = 0; mi < 2; mi++) {
        int mA = m0 + wm * 32 + mi * 16 + qrow;
        float* rowA = y + ((size_t)(b * CC + mA)) * NN + n0;
        float* rowB = rowA + (size_t)8 * NN;
#pragma unroll
        for (int ni = 0; ni < 4; ni++) {
            int n = wn * 32 + ni * 8 + qcol;
            *(float2*)(rowA + n) = make_float2(acc[mi][ni][0], acc[mi][ni][1]);
            *(float2*)(rowB + n) = make_float2(acc[mi][ni][2], acc[mi][ni][3]);
        }
    }
}

// ============================================================================
extern "C" void kernel_launch(void* const* d_in, const int* in_sizes, int n_in,
                              void* d_out, int out_size)
{
    const float* x      = (const float*)d_in[0];
    const float* W_bcdt = (const float*)d_in[1];
    const float* b_bcdt = (const float*)d_in[2];
    const float* W_dw   = (const float*)d_in[3];
    const float* b_dw   = (const float*)d_in[4];
    const float* W_hz   = (const float*)d_in[5];
    const float* b_hz   = (const float*)d_in[6];
    const float* W_out  = (const float*)d_in[7];
    const float* b_out  = (const float*)d_in[8];
    // d_in[9] = A : unused (softmax shift invariance along the reduced axis)
    const float* Dp     = (const float*)d_in[10];
    float* out = (float*)d_out;

    gemm1_mma_kernel<<<dim3(NN / 128, 3, BB), 256>>>(x, W_bcdt, b_bcdt);
    conv_kernel<<<dim3(32, O3S, BB), 256>>>(W_dw, b_dw);
    softmax_ab_kernel<<<dim3(SS, BB), 256>>>();
    hgemm_mma_kernel<<<dim3(KSPLIT_H, 2, BB), 256>>>(x);
    hreduce_kernel<<<256, 256>>>();
    e1_kernel<<<dim3(64, BB), 256>>>(W_hz, b_hz, Dp);
    e2_kernel<<<dim3(64, BB), 256>>>(W_out, b_out, out);
    ygemm_mma_kernel<<<dim3(NN / 128, 4, BB), 256>>>(out);
}

// round 5
// speedup vs baseline: 2.1501x; 1.0559x over previous
#include <cuda_runtime.h>
#include <cuda_bf16.h>
#include <cstdint>
#include <cstddef>

// Problem constants
#define BB   4
#define CC   256      // D_MODEL = D_INNER
#define SS   64
#define DD   16
#define HH   64
#define WW   64
#define NN   65536    // D*H*W
#define O3S  192      // 3*S
#define KSPLIT_H 64   // split-K factor for h-GEMM

static const size_t YSIZE = (size_t)BB * CC * NN;   // 67108864

// ---- static scratch (no runtime allocation allowed) ----
__device__ float g_bcdt[(size_t)BB * O3S * NN];
__device__ float g_conv[(size_t)BB * O3S * NN];
__device__ float g_hpart[(size_t)KSPLIT_H * BB * CC * SS];
__device__ float g_h [BB * CC * SS];
__device__ float g_h3[BB * CC * SS];
__device__ float g_h4[BB * CC * SS];

// ============================================================================
// mma.sync helpers (legacy HMMA path — tcgen05 PTX is rejected at compute_103)
// ============================================================================
__device__ __forceinline__ uint32_t smem_u32(const void* p) {
    uint32_t a;
    asm("{ .reg .u64 t; cvta.to.shared.u64 t, %1; cvt.u32.u64 %0, t; }" : "=r"(a) : "l"(p));
    return a;
}
__device__ __forceinline__ void ldsm_x4(uint32_t* r, uint32_t addr) {
    asm volatile("ldmatrix.sync.aligned.m8n8.x4.shared.b16 {%0,%1,%2,%3}, [%4];"
        : "=r"(r[0]), "=r"(r[1]), "=r"(r[2]), "=r"(r[3]) : "r"(addr));
}
__device__ __forceinline__ void ldsm_x2(uint32_t* r, uint32_t addr) {
    asm volatile("ldmatrix.sync.aligned.m8n8.x2.shared.b16 {%0,%1}, [%2];"
        : "=r"(r[0]), "=r"(r[1]) : "r"(addr));
}
__device__ __forceinline__ void ldsm_x2_t(uint32_t* r, uint32_t addr) {
    asm volatile("ldmatrix.sync.aligned.m8n8.x2.trans.shared.b16 {%0,%1}, [%2];"
        : "=r"(r[0]), "=r"(r[1]) : "r"(addr));
}
__device__ __forceinline__ void mma_bf16(float* c, const uint32_t* a, const uint32_t* b) {
    asm volatile(
        "mma.sync.aligned.m16n8k16.row.col.f32.bf16.bf16.f32 "
        "{%0,%1,%2,%3}, {%4,%5,%6,%7}, {%8,%9}, {%0,%1,%2,%3};"
        : "+f"(c[0]), "+f"(c[1]), "+f"(c[2]), "+f"(c[3])
        : "r"(a[0]), "r"(a[1]), "r"(a[2]), "r"(a[3]), "r"(b[0]), "r"(b[1]));
}
// fp32 -> bf16 hi/lo split, packed pairs
__device__ __forceinline__ void split2(float v0, float v1, uint32_t& hi, uint32_t& lo) {
    __nv_bfloat16 h0 = __float2bfloat16(v0), h1 = __float2bfloat16(v1);
    float r0 = v0 - __bfloat162float(h0), r1 = v1 - __bfloat162float(h1);
    __nv_bfloat162 hh = __halves2bfloat162(h0, h1);
    __nv_bfloat162 ll = __floats2bfloat162_rn(r0, r1);
    hi = *(uint32_t*)&hh; lo = *(uint32_t*)&ll;
}

#define A_STRIDE 40    // halves per 32-k row (32 + 8 pad)
#define B_STRIDE 136   // halves per 128-n row (128 + 8 pad)

// ============================================================================
// Kernel 1 (HMMA): BCdt = W_bcdt(192x256) @ x(b,256,N) + b_bcdt
// BM=64, BN=128, BK=32. 8 warps: 2(m) x 4(n). hi/lo 3 passes.
// Grid: (m-tile FASTEST for L2 reuse of the x tile, n-tile, b)
// ============================================================================
__global__ void __launch_bounds__(256) gemm1_mma_kernel(
    const float* __restrict__ x, const float* __restrict__ W,
    const float* __restrict__ bias)
{
    __shared__ __align__(16) uint16_t As_hi[64 * A_STRIDE];
    __shared__ __align__(16) uint16_t As_lo[64 * A_STRIDE];
    __shared__ __align__(16) uint16_t Bs_hi[32 * B_STRIDE];
    __shared__ __align__(16) uint16_t Bs_lo[32 * B_STRIDE];

    const int m0 = blockIdx.x * 64;     // 0,64,128  (fastest -> concurrent sharers)
    const int n0 = blockIdx.y * 128;
    const int b  = blockIdx.z;
    const int tid  = threadIdx.x;
    const int wid  = tid >> 5;
    const int lane = tid & 31;
    const int wm = wid >> 2;
    const int wn = wid & 3;

    const float* xb = x + (size_t)b * CC * NN;
    const uint32_t as_hi = smem_u32(As_hi), as_lo = smem_u32(As_lo);
    const uint32_t bs_hi = smem_u32(Bs_hi), bs_lo = smem_u32(Bs_lo);

    float acc[2][4][4];
#pragma unroll
    for (int i = 0; i < 2; i++)
#pragma unroll
        for (int j = 0; j < 4; j++)
#pragma unroll
            for (int q = 0; q < 4; q++) acc[i][j][q] = 0.f;

    for (int k0 = 0; k0 < 256; k0 += 32) {
#pragma unroll
        for (int r = 0; r < 2; r++) {
            int f = tid + r * 256;
            int m = f >> 3, k = (f & 7) << 2;
            float4 v = *(const float4*)(W + (size_t)(m0 + m) * 256 + k0 + k);
            uint32_t h01, l01, h23, l23;
            split2(v.x, v.y, h01, l01);
            split2(v.z, v.w, h23, l23);
            int off = m * A_STRIDE + k;
            *(uint2*)(As_hi + off) = make_uint2(h01, h23);
            *(uint2*)(As_lo + off) = make_uint2(l01, l23);
        }
#pragma unroll
        for (int r = 0; r < 4; r++) {
            int f = tid + r * 256;
            int krow = f >> 5, n = (f & 31) << 2;
            float4 v = *(const float4*)(xb + (size_t)(k0 + krow) * NN + n0 + n);
            uint32_t h01, l01, h23, l23;
            split2(v.x, v.y, h01, l01);
            split2(v.z, v.w, h23, l23);
            int off = krow * B_STRIDE + n;
            *(uint2*)(Bs_hi + off) = make_uint2(h01, h23);
            *(uint2*)(Bs_lo + off) = make_uint2(l01, l23);
        }
        __syncthreads();

#pragma unroll
        for (int ks = 0; ks < 2; ks++) {
            uint32_t a_hi[2][4], a_lo[2][4];
            const int arow = lane & 15;
            const int acol = (lane >> 4) << 3;
#pragma unroll
            for (int mi = 0; mi < 2; mi++) {
                uint32_t off = (uint32_t)((wm * 32 + mi * 16 + arow) * A_STRIDE
                                          + ks * 16 + acol) * 2;
                ldsm_x4(a_hi[mi], as_hi + off);
                ldsm_x4(a_lo[mi], as_lo + off);
            }
            uint32_t b_hi[4][2], b_lo[4][2];
            const int brow = lane & 15;
#pragma unroll
            for (int ni = 0; ni < 4; ni++) {
                uint32_t off = (uint32_t)((ks * 16 + brow) * B_STRIDE
                                          + wn * 32 + ni * 8) * 2;
                ldsm_x2_t(b_hi[ni], bs_hi + off);
                ldsm_x2_t(b_lo[ni], bs_lo + off);
            }
#pragma unroll
            for (int mi = 0; mi < 2; mi++)
#pragma unroll
                for (int ni = 0; ni < 4; ni++) {
                    mma_bf16(acc[mi][ni], a_hi[mi], b_hi[ni]);
                    mma_bf16(acc[mi][ni], a_hi[mi], b_lo[ni]);
                    mma_bf16(acc[mi][ni], a_lo[mi], b_hi[ni]);
                }
        }
        __syncthreads();
    }

    const int qrow = lane >> 2;
    const int qcol = (lane & 3) << 1;
#pragma unroll
    for (int mi = 0; mi < 2; mi++) {
        int mA = m0 + wm * 32 + mi * 16 + qrow;
        float bA = bias[mA], bB = bias[mA + 8];
        float* rowA = g_bcdt + ((size_t)(b * O3S + mA)) * NN + n0;
        float* rowB = rowA + (size_t)8 * NN;
#pragma unroll
        for (int ni = 0; ni < 4; ni++) {
            int n = wn * 32 + ni * 8 + qcol;
            *(float2*)(rowA + n) = make_float2(acc[mi][ni][0] + bA, acc[mi][ni][1] + bA);
            *(float2*)(rowB + n) = make_float2(acc[mi][ni][2] + bB, acc[mi][ni][3] + bB);
        }
    }
}

// ============================================================================
// Kernel 2: depthwise 3x3x3 conv, pad 1, + b_dw
// ============================================================================
__global__ void __launch_bounds__(256) conv_kernel(
    const float* __restrict__ wdw, const float* __restrict__ bdw)
{
    __shared__ float s[3][34][66];
    __shared__ float wt[27];

    const int dz = blockIdx.x >> 1;
    const int hhalf = blockIdx.x & 1;
    const int ch = blockIdx.y;
    const int b  = blockIdx.z;
    const int h0 = hhalf * 32;
    const int tid = threadIdx.x;

    const float* base = g_bcdt + ((size_t)(b * O3S + ch)) * NN;

    for (int idx = tid; idx < 3 * 34 * 66; idx += 256) {
        int kd = idx / (34 * 66);
        int rem = idx % (34 * 66);
        int ih = rem / 66, iw = rem % 66;
        int d = dz - 1 + kd, h = h0 - 1 + ih, w = iw - 1;
        float v = 0.f;
        if ((unsigned)d < DD && (unsigned)h < HH && (unsigned)w < WW)
            v = base[((size_t)d * HH + h) * WW + w];
        s[kd][ih][iw] = v;
    }
    if (tid < 27) wt[tid] = wdw[ch * 27 + tid];
    __syncthreads();

    const float bb = bdw[ch];
    const int w = tid & 63;
    const int hl0 = tid >> 6;
    float* outb = g_conv + ((size_t)(b * O3S + ch)) * NN;

#pragma unroll
    for (int r = 0; r < 8; r++) {
        int hl = hl0 + r * 4;
        float acc = bb;
#pragma unroll
        for (int kd = 0; kd < 3; kd++)
#pragma unroll
            for (int kh = 0; kh < 3; kh++)
#pragma unroll
                for (int kw = 0; kw < 3; kw++)
                    acc += s[kd][hl + kh][w + kw] * wt[kd * 9 + kh * 3 + kw];
        outb[((size_t)dz * HH + h0 + hl) * WW + w] = acc;
    }
}

// ============================================================================
// Kernel 3: softmax over n of dt (A cancels), fused AB = softmax * B_
// 1024 threads/block for latency hiding.
// ============================================================================
__global__ void __launch_bounds__(1024) softmax_ab_kernel()
{
    const int s_ = blockIdx.x;
    const int b  = blockIdx.y;
    float* dt = g_conv + ((size_t)(b * O3S + 128 + s_)) * NN;
    const float* Bp = g_conv + ((size_t)(b * O3S + s_)) * NN;
    const int tid = threadIdx.x;

    float m = -1e30f, sum = 0.f;
    for (int i = tid * 4; i < NN; i += 4096) {
        float4 v = *(float4*)(dt + i);
        float vals[4] = {v.x, v.y, v.z, v.w};
#pragma unroll
        for (int q = 0; q < 4; q++) {
            float val = vals[q];
            if (val > m) { sum *= __expf(m - val); m = val; }
            sum += __expf(val - m);
        }
    }
    __shared__ float sm[1024], ssum[1024];
    sm[tid] = m; ssum[tid] = sum;
    __syncthreads();
    for (int off = 512; off > 0; off >>= 1) {
        if (tid < off) {
            float m2 = sm[tid + off], s2 = ssum[tid + off];
            float M = fmaxf(sm[tid], m2);
            ssum[tid] = ssum[tid] * __expf(sm[tid] - M) + s2 * __expf(m2 - M);
            sm[tid] = M;
        }
        __syncthreads();
    }
    const float M = sm[0];
    const float inv = 1.f / ssum[0];

    for (int i = tid * 4; i < NN; i += 4096) {
        float4 v  = *(float4*)(dt + i);
        float4 bv = *(const float4*)(Bp + i);
        float4 o;
        o.x = __expf(v.x - M) * inv * bv.x;
        o.y = __expf(v.y - M) * inv * bv.y;
        o.z = __expf(v.z - M) * inv * bv.z;
        o.w = __expf(v.w - M) * inv * bv.w;
        *(float4*)(dt + i) = o;
    }
}

// ============================================================================
// Kernel 4 (HMMA): h[b,c,s] = sum_n x[b,c,n] * AB[b,s,n]   split-K partials
// BM=64(c), BN=64(s), BK=32. 8 warps: 2(m) x 4(n). hi/lo 3 passes.
// Grid: (c-tile FASTEST for L2 reuse of AB tile, ks, b)
// ============================================================================
#define HB_STRIDE 40   // halves per 32-k row of B (s rows)

__global__ void __launch_bounds__(256) hgemm_mma_kernel(const float* __restrict__ x)
{
    __shared__ __align__(16) uint16_t As_hi[64 * A_STRIDE];
    __shared__ __align__(16) uint16_t As_lo[64 * A_STRIDE];
    __shared__ __align__(16) uint16_t Bs_hi[64 * HB_STRIDE];
    __shared__ __align__(16) uint16_t Bs_lo[64 * HB_STRIDE];

    const int c0 = blockIdx.x * 64;          // 0..192 (fastest)
    const int ks = blockIdx.y;               // 0..63
    const int b  = blockIdx.z;
    const int nbase = ks * (NN / KSPLIT_H);  // 1024 chunk
    const int tid  = threadIdx.x;
    const int wid  = tid >> 5;
    const int lane = tid & 31;
    const int wm = wid >> 2;                 // 0..1 (c)
    const int wn = wid & 3;                  // 0..3 (s)

    const float* xb = x + ((size_t)(b * CC + c0)) * NN;
    const float* ab = g_conv + ((size_t)(b * O3S + 128)) * NN;
    const uint32_t as_hi = smem_u32(As_hi), as_lo = smem_u32(As_lo);
    const uint32_t bs_hi = smem_u32(Bs_hi), bs_lo = smem_u32(Bs_lo);

    float acc[2][2][4];
#pragma unroll
    for (int i = 0; i < 2; i++)
#pragma unroll
        for (int j = 0; j < 2; j++)
#pragma unroll
            for (int q = 0; q < 4; q++) acc[i][j][q] = 0.f;

    for (int kc = 0; kc < NN / KSPLIT_H; kc += 32) {
        const int nb = nbase + kc;
        // x tile 64c x 32k: 512 float4, 2/thread
#pragma unroll
        for (int r = 0; r < 2; r++) {
            int f = tid + r * 256;
            int c = f >> 3, k = (f & 7) << 2;
            float4 v = *(const float4*)(xb + (size_t)c * NN + nb + k);
            uint32_t h01, l01, h23, l23;
            split2(v.x, v.y, h01, l01);
            split2(v.z, v.w, h23, l23);
            int off = c * A_STRIDE + k;
            *(uint2*)(As_hi + off) = make_uint2(h01, h23);
            *(uint2*)(As_lo + off) = make_uint2(l01, l23);
        }
        // AB tile 64s x 32k: 512 float4, 2/thread
#pragma unroll
        for (int r = 0; r < 2; r++) {
            int f = tid + r * 256;
            int sr = f >> 3, k = (f & 7) << 2;
            float4 v = *(const float4*)(ab + (size_t)sr * NN + nb + k);
            uint32_t h01, l01, h23, l23;
            split2(v.x, v.y, h01, l01);
            split2(v.z, v.w, h23, l23);
            int off = sr * HB_STRIDE + k;
            *(uint2*)(Bs_hi + off) = make_uint2(h01, h23);
            *(uint2*)(Bs_lo + off) = make_uint2(l01, l23);
        }
        __syncthreads();

#pragma unroll
        for (int kq = 0; kq < 2; kq++) {
            uint32_t a_hi[2][4], a_lo[2][4];
            const int arow = lane & 15;
            const int acol = (lane >> 4) << 3;
#pragma unroll
            for (int mi = 0; mi < 2; mi++) {
                uint32_t off = (uint32_t)((wm * 32 + mi * 16 + arow) * A_STRIDE
                                          + kq * 16 + acol) * 2;
                ldsm_x4(a_hi[mi], as_hi + off);
                ldsm_x4(a_lo[mi], as_lo + off);
            }
            // B: [s][k] k-contiguous -> non-trans x2
            uint32_t b_hi[2][2], b_lo[2][2];
            const int l = lane & 15;
            const int srow = l & 7;
            const int koff = (l >> 3) << 3;
#pragma unroll
            for (int ni = 0; ni < 2; ni++) {
                uint32_t off = (uint32_t)((wn * 16 + ni * 8 + srow) * HB_STRIDE
                                          + kq * 16 + koff) * 2;
                ldsm_x2(b_hi[ni], bs_hi + off);
                ldsm_x2(b_lo[ni], bs_lo + off);
            }
#pragma unroll
            for (int mi = 0; mi < 2; mi++)
#pragma unroll
                for (int ni = 0; ni < 2; ni++) {
                    mma_bf16(acc[mi][ni], a_hi[mi], b_hi[ni]);
                    mma_bf16(acc[mi][ni], a_hi[mi], b_lo[ni]);
                    mma_bf16(acc[mi][ni], a_lo[mi], b_hi[ni]);
                }
        }
        __syncthreads();
    }

    float* dst = g_hpart + (size_t)ks * (BB * CC * SS);
    const int qrow = lane >> 2;
    const int qcol = (lane & 3) << 1;
#pragma unroll
    for (int mi = 0; mi < 2; mi++) {
        int cA = c0 + wm * 32 + mi * 16 + qrow;
#pragma unroll
        for (int ni = 0; ni < 2; ni++) {
            int sA = wn * 16 + ni * 8 + qcol;
            float* pA = dst + ((size_t)(b * CC + cA)) * SS + sA;
            float* pB = dst + ((size_t)(b * CC + cA + 8)) * SS + sA;
            *(float2*)pA = make_float2(acc[mi][ni][0], acc[mi][ni][1]);
            *(float2*)pB = make_float2(acc[mi][ni][2], acc[mi][ni][3]);
        }
    }
}

// deterministic reduction of split-K partials
__global__ void __launch_bounds__(256) hreduce_kernel()
{
    int i = blockIdx.x * 256 + threadIdx.x;   // < 65536
    float sum = 0.f;
#pragma unroll
    for (int ks = 0; ks < KSPLIT_H; ks++)
        sum += g_hpart[(size_t)ks * (BB * CC * SS) + i];
    g_h[i] = sum;
}

// ============================================================================
// Kernel 5: hz = W_hz @ h + b_hz ; h3 = h2*silu(z) + h2*Dp
// ============================================================================
__global__ void __launch_bounds__(256) e1_kernel(
    const float* __restrict__ Whz, const float* __restrict__ bhz,
    const float* __restrict__ Dp)
{
    const int b = blockIdx.y;
    const int o = blockIdx.x * 4 + (threadIdx.x >> 6);
    const int s_ = threadIdx.x & 63;
    const float* hb = g_h + (size_t)b * CC * SS;
    const float* w1 = Whz + (size_t)o * 256;
    const float* w2 = Whz + (size_t)(o + 256) * 256;
    float a1 = bhz[o], a2 = bhz[o + 256];
    for (int c = 0; c < 256; c++) {
        float hv = hb[c * 64 + s_];
        a1 += w1[c] * hv;
        a2 += w2[c] * hv;
    }
    float sig = 1.f / (1.f + __expf(-a2));
    g_h3[((size_t)b * CC + o) * SS + s_] = a1 * (a2 * sig) + a1 * Dp[0];
}

// Kernel 6: h4 = W_out @ h3 + b_out ; write to scratch + output tail
__global__ void __launch_bounds__(256) e2_kernel(
    const float* __restrict__ Wout, const float* __restrict__ bout,
    float* __restrict__ out)
{
    const int b = blockIdx.y;
    const int o = blockIdx.x * 4 + (threadIdx.x >> 6);
    const int s_ = threadIdx.x & 63;
    const float* hb = g_h3 + (size_t)b * CC * SS;
    const float* w1 = Wout + (size_t)o * 256;
    float acc = bout[o];
    for (int c = 0; c < 256; c++)
        acc += w1[c] * hb[c * 64 + s_];
    size_t idx = ((size_t)b * CC + o) * SS + s_;
    g_h4[idx] = acc;
    out[YSIZE + idx] = acc;
}

// ============================================================================
// Kernel 7 (HMMA): y[b,c,n] = sum_s h4[b,c,s] * C_[b,s,n]
// BM=64, BN=128, K=64 (2 x BK=32). hi/lo 3 passes.
// Grid: (m-tile FASTEST for L2 reuse of C_ tile, n-tile, b)
// ============================================================================
__global__ void __launch_bounds__(256) ygemm_mma_kernel(float* __restrict__ y)
{
    __shared__ __align__(16) uint16_t As_hi[64 * A_STRIDE];
    __shared__ __align__(16) uint16_t As_lo[64 * A_STRIDE];
    __shared__ __align__(16) uint16_t Bs_hi[32 * B_STRIDE];
    __shared__ __align__(16) uint16_t Bs_lo[32 * B_STRIDE];

    const int m0 = blockIdx.x * 64;     // 0..192 (c)  (fastest)
    const int n0 = blockIdx.y * 128;
    const int b  = blockIdx.z;
    const int tid  = threadIdx.x;
    const int wid  = tid >> 5;
    const int lane = tid & 31;
    const int wm = wid >> 2;
    const int wn = wid & 3;

    const float* h4b = g_h4 + (size_t)b * CC * SS;
    const float* cp  = g_conv + ((size_t)(b * O3S + 64)) * NN;  // C_ channels
    const uint32_t as_hi = smem_u32(As_hi), as_lo = smem_u32(As_lo);
    const uint32_t bs_hi = smem_u32(Bs_hi), bs_lo = smem_u32(Bs_lo);

    float acc[2][4][4];
#pragma unroll
    for (int i = 0; i < 2; i++)
#pragma unroll
        for (int j = 0; j < 4; j++)
#pragma unroll
            for (int q = 0; q < 4; q++) acc[i][j][q] = 0.f;

    for (int k0 = 0; k0 < 64; k0 += 32) {
        // h4 tile 64c x 32s: 512 float4, 2/thread
#pragma unroll
        for (int r = 0; r < 2; r++) {
            int f = tid + r * 256;
            int m = f >> 3, k = (f & 7) << 2;
            float4 v = *(const float4*)(h4b + (size_t)(m0 + m) * SS + k0 + k);
            uint32_t h01, l01, h23, l23;
            split2(v.x, v.y, h01, l01);
            split2(v.z, v.w, h23, l23);
            int off = m * A_STRIDE + k;
            *(uint2*)(As_hi + off) = make_uint2(h01, h23);
            *(uint2*)(As_lo + off) = make_uint2(l01, l23);
        }
        // C_ tile 32s x 128n: 1024 float4, 4/thread
#pragma unroll
        for (int r = 0; r < 4; r++) {
            int f = tid + r * 256;
            int krow = f >> 5, n = (f & 31) << 2;
            float4 v = *(const float4*)(cp + (size_t)(k0 + krow) * NN + n0 + n);
            uint32_t h01, l01, h23, l23;
            split2(v.x, v.y, h01, l01);
            split2(v.z, v.w, h23, l23);
            int off = krow * B_STRIDE + n;
            *(uint2*)(Bs_hi + off) = make_uint2(h01, h23);
            *(uint2*)(Bs_lo + off) = make_uint2(l01, l23);
        }
        __syncthreads();

#pragma unroll
        for (int ks = 0; ks < 2; ks++) {
            uint32_t a_hi[2][4], a_lo[2][4];
            const int arow = lane & 15;
            const int acol = (lane >> 4) << 3;
#pragma unroll
            for (int mi = 0; mi < 2; mi++) {
                uint32_t off = (uint32_t)((wm * 32 + mi * 16 + arow) * A_STRIDE
                                          + ks * 16 + acol) * 2;
                ldsm_x4(a_hi[mi], as_hi + off);
                ldsm_x4(a_lo[mi], as_lo + off);
            }
            uint32_t b_hi[4][2], b_lo[4][2];
            const int brow = lane & 15;
#pragma unroll
            for (int ni = 0; ni < 4; ni++) {
                uint32_t off = (uint32_t)((ks * 16 + brow) * B_STRIDE
                                          + wn * 32 + ni * 8) * 2;
                ldsm_x2_t(b_hi[ni], bs_hi + off);
                ldsm_x2_t(b_lo[ni], bs_lo + off);
            }
#pragma unroll
            for (int mi = 0; mi < 2; mi++)
#pragma unroll
                for (int ni = 0; ni < 4; ni++) {
                    mma_bf16(acc[mi][ni], a_hi[mi], b_hi[ni]);
                    mma_bf16(acc[mi][ni], a_hi[mi], b_lo[ni]);
                    mma_bf16(acc[mi][ni], a_lo[mi], b_hi[ni]);
                }
        }
        __syncthreads();
    }

    const int qrow = lane >> 2;
    const int qcol = (lane & 3) << 1;
#pragma unroll
    for (int mi = 0; mi < 2; mi++) {
        int mA = m0 + wm * 32 + mi * 16 + qrow;
        float* rowA = y + ((size_t)(b * CC + mA)) * NN + n0;
        float* rowB = rowA + (size_t)8 * NN;
#pragma unroll
        for (int ni = 0; ni < 4; ni++) {
            int n = wn * 32 + ni * 8 + qcol;
            *(float2*)(rowA + n) = make_float2(acc[mi][ni][0], acc[mi][ni][1]);
            *(float2*)(rowB + n) = make_float2(acc[mi][ni][2], acc[mi][ni][3]);
        }
    }
}

// ============================================================================
extern "C" void kernel_launch(void* const* d_in, const int* in_sizes, int n_in,
                              void* d_out, int out_size)
{
    const float* x      = (const float*)d_in[0];
    const float* W_bcdt = (const float*)d_in[1];
    const float* b_bcdt = (const float*)d_in[2];
    const float* W_dw   = (const float*)d_in[3];
    const float* b_dw   = (const float*)d_in[4];
    const float* W_hz   = (const float*)d_in[5];
    const float* b_hz   = (const float*)d_in[6];
    const float* W_out  = (const float*)d_in[7];
    const float* b_out  = (const float*)d_in[8];
    // d_in[9] = A : unused (softmax shift invariance along the reduced axis)
    const float* Dp     = (const float*)d_in[10];
    float* out = (float*)d_out;

    gemm1_mma_kernel<<<dim3(3, NN / 128, BB), 256>>>(x, W_bcdt, b_bcdt);
    conv_kernel<<<dim3(32, O3S, BB), 256>>>(W_dw, b_dw);
    softmax_ab_kernel<<<dim3(SS, BB), 1024>>>();
    hgemm_mma_kernel<<<dim3(4, KSPLIT_H, BB), 256>>>(x);
    hreduce_kernel<<<256, 256>>>();
    e1_kernel<<<dim3(64, BB), 256>>>(W_hz, b_hz, Dp);
    e2_kernel<<<dim3(64, BB), 256>>>(W_out, b_out, out);
    ygemm_mma_kernel<<<dim3(4, NN / 128, BB), 256>>>(out);
}

// round 6
// speedup vs baseline: 2.1605x; 1.0048x over previous
#include <cuda_runtime.h>
#include <cuda_bf16.h>
#include <cstdint>
#include <cstddef>

// Problem constants
#define BB   4
#define CC   256      // D_MODEL = D_INNER
#define SS   64
#define DD   16
#define HH   64
#define WW   64
#define NN   65536    // D*H*W
#define O3S  192      // 3*S
#define KSPLIT_H 64   // split-K factor for h-GEMM

static const size_t YSIZE = (size_t)BB * CC * NN;   // 67108864

// ---- static scratch (no runtime allocation allowed) ----
__device__ float g_bcdt[(size_t)BB * O3S * NN];
__device__ float g_conv[(size_t)BB * O3S * NN];
__device__ float g_hpart[(size_t)KSPLIT_H * BB * CC * SS];
__device__ float g_h [BB * CC * SS];
__device__ float g_h3[BB * CC * SS];
__device__ float g_h4[BB * CC * SS];

// ============================================================================
// helpers
// ============================================================================
__device__ __forceinline__ uint32_t smem_u32(const void* p) {
    uint32_t a;
    asm("{ .reg .u64 t; cvta.to.shared.u64 t, %1; cvt.u32.u64 %0, t; }" : "=r"(a) : "l"(p));
    return a;
}
__device__ __forceinline__ void ldsm_x4(uint32_t* r, uint32_t addr) {
    asm volatile("ldmatrix.sync.aligned.m8n8.x4.shared.b16 {%0,%1,%2,%3}, [%4];"
        : "=r"(r[0]), "=r"(r[1]), "=r"(r[2]), "=r"(r[3]) : "r"(addr));
}
__device__ __forceinline__ void ldsm_x2(uint32_t* r, uint32_t addr) {
    asm volatile("ldmatrix.sync.aligned.m8n8.x2.shared.b16 {%0,%1}, [%2];"
        : "=r"(r[0]), "=r"(r[1]) : "r"(addr));
}
__device__ __forceinline__ void ldsm_x2_t(uint32_t* r, uint32_t addr) {
    asm volatile("ldmatrix.sync.aligned.m8n8.x2.trans.shared.b16 {%0,%1}, [%2];"
        : "=r"(r[0]), "=r"(r[1]) : "r"(addr));
}
__device__ __forceinline__ void mma_bf16(float* c, const uint32_t* a, const uint32_t* b) {
    asm volatile(
        "mma.sync.aligned.m16n8k16.row.col.f32.bf16.bf16.f32 "
        "{%0,%1,%2,%3}, {%4,%5,%6,%7}, {%8,%9}, {%0,%1,%2,%3};"
        : "+f"(c[0]), "+f"(c[1]), "+f"(c[2]), "+f"(c[3])
        : "r"(a[0]), "r"(a[1]), "r"(a[2]), "r"(a[3]), "r"(b[0]), "r"(b[1]));
}
// fp32 -> bf16 hi/lo split, packed pairs
__device__ __forceinline__ void split2(float v0, float v1, uint32_t& hi, uint32_t& lo) {
    __nv_bfloat16 h0 = __float2bfloat16(v0), h1 = __float2bfloat16(v1);
    float r0 = v0 - __bfloat162float(h0), r1 = v1 - __bfloat162float(h1);
    __nv_bfloat162 hh = __halves2bfloat162(h0, h1);
    __nv_bfloat162 ll = __floats2bfloat162_rn(r0, r1);
    hi = *(uint32_t*)&hh; lo = *(uint32_t*)&ll;
}
// FMA-pipe exp: exp(x) = 2^n * 2^f, poly 2^f on [-0.5,0.5] (~2e-9 rel err).
// Assumes x <= ~0 (max-subtracted); clamps hard underflow.
__device__ __forceinline__ float fexp(float x) {
    float t = fmaxf(x * 1.4426950408889634f, -125.0f);
    float n = rintf(t);
    float f = t - n;
    float p = 1.5403530393381609e-4f;
    p = fmaf(p, f, 1.3333558146428443e-3f);
    p = fmaf(p, f, 9.618129107628477e-3f);
    p = fmaf(p, f, 5.550410866482158e-2f);
    p = fmaf(p, f, 2.402265069591999e-1f);
    p = fmaf(p, f, 6.931471805599453e-1f);
    p = fmaf(p, f, 1.0f);
    return __int_as_float(((int)n + 127) << 23) * p;
}

#define A_STRIDE 40    // halves per 32-k row (32 + 8 pad)
#define B_STRIDE 136   // halves per 128-n row (128 + 8 pad)

// ============================================================================
// Kernel 1 (HMMA): BCdt = W_bcdt(192x256) @ x(b,256,N) + b_bcdt
// BM=64, BN=128, BK=32. 8 warps: 2(m) x 4(n). hi/lo 3 passes.
// x tile prefetched into registers (overlap LDG with MMA).
// ============================================================================
__global__ void __launch_bounds__(256) gemm1_mma_kernel(
    const float* __restrict__ x, const float* __restrict__ W,
    const float* __restrict__ bias)
{
    __shared__ __align__(16) uint16_t As_hi[64 * A_STRIDE];
    __shared__ __align__(16) uint16_t As_lo[64 * A_STRIDE];
    __shared__ __align__(16) uint16_t Bs_hi[32 * B_STRIDE];
    __shared__ __align__(16) uint16_t Bs_lo[32 * B_STRIDE];

    const int m0 = blockIdx.x * 64;     // fastest -> L2 sharing of x tile
    const int n0 = blockIdx.y * 128;
    const int b  = blockIdx.z;
    const int tid  = threadIdx.x;
    const int wid  = tid >> 5;
    const int lane = tid & 31;
    const int wm = wid >> 2;
    const int wn = wid & 3;

    const float* xb = x + (size_t)b * CC * NN;
    const uint32_t as_hi = smem_u32(As_hi), as_lo = smem_u32(As_lo);
    const uint32_t bs_hi = smem_u32(Bs_hi), bs_lo = smem_u32(Bs_lo);

    // x-tile load indices: 4 rows per thread, rows krow0+{0,8,16,24}, col n fixed
    const int krow0 = tid >> 5;           // 0..7
    const int nloc  = (tid & 31) << 2;    // 0..124

    float acc[2][4][4];
#pragma unroll
    for (int i = 0; i < 2; i++)
#pragma unroll
        for (int j = 0; j < 4; j++)
#pragma unroll
            for (int q = 0; q < 4; q++) acc[i][j][q] = 0.f;

    // prefetch x tile for k0=0
    float4 rbx[4];
#pragma unroll
    for (int r = 0; r < 4; r++)
        rbx[r] = *(const float4*)(xb + (size_t)(krow0 + r * 8) * NN + n0 + nloc);

    for (int k0 = 0; k0 < 256; k0 += 32) {
        // W tile (L2-hot): load + convert + store
#pragma unroll
        for (int r = 0; r < 2; r++) {
            int f = tid + r * 256;
            int m = f >> 3, k = (f & 7) << 2;
            float4 v = *(const float4*)(W + (size_t)(m0 + m) * 256 + k0 + k);
            uint32_t h01, l01, h23, l23;
            split2(v.x, v.y, h01, l01);
            split2(v.z, v.w, h23, l23);
            int off = m * A_STRIDE + k;
            *(uint2*)(As_hi + off) = make_uint2(h01, h23);
            *(uint2*)(As_lo + off) = make_uint2(l01, l23);
        }
        // x tile: convert prefetched regs -> smem
#pragma unroll
        for (int r = 0; r < 4; r++) {
            float4 v = rbx[r];
            uint32_t h01, l01, h23, l23;
            split2(v.x, v.y, h01, l01);
            split2(v.z, v.w, h23, l23);
            int off = (krow0 + r * 8) * B_STRIDE + nloc;
            *(uint2*)(Bs_hi + off) = make_uint2(h01, h23);
            *(uint2*)(Bs_lo + off) = make_uint2(l01, l23);
        }
        __syncthreads();

        // prefetch next x tile (overlaps with MMA below)
        if (k0 + 32 < 256) {
#pragma unroll
            for (int r = 0; r < 4; r++)
                rbx[r] = *(const float4*)(xb + (size_t)(k0 + 32 + krow0 + r * 8) * NN + n0 + nloc);
        }

#pragma unroll
        for (int ks = 0; ks < 2; ks++) {
            uint32_t a_hi[2][4], a_lo[2][4];
            const int arow = lane & 15;
            const int acol = (lane >> 4) << 3;
#pragma unroll
            for (int mi = 0; mi < 2; mi++) {
                uint32_t off = (uint32_t)((wm * 32 + mi * 16 + arow) * A_STRIDE
                                          + ks * 16 + acol) * 2;
                ldsm_x4(a_hi[mi], as_hi + off);
                ldsm_x4(a_lo[mi], as_lo + off);
            }
            uint32_t b_hi[4][2], b_lo[4][2];
            const int brow = lane & 15;
#pragma unroll
            for (int ni = 0; ni < 4; ni++) {
                uint32_t off = (uint32_t)((ks * 16 + brow) * B_STRIDE
                                          + wn * 32 + ni * 8) * 2;
                ldsm_x2_t(b_hi[ni], bs_hi + off);
                ldsm_x2_t(b_lo[ni], bs_lo + off);
            }
#pragma unroll
            for (int mi = 0; mi < 2; mi++)
#pragma unroll
                for (int ni = 0; ni < 4; ni++) {
                    mma_bf16(acc[mi][ni], a_hi[mi], b_hi[ni]);
                    mma_bf16(acc[mi][ni], a_hi[mi], b_lo[ni]);
                    mma_bf16(acc[mi][ni], a_lo[mi], b_hi[ni]);
                }
        }
        __syncthreads();
    }

    const int qrow = lane >> 2;
    const int qcol = (lane & 3) << 1;
#pragma unroll
    for (int mi = 0; mi < 2; mi++) {
        int mA = m0 + wm * 32 + mi * 16 + qrow;
        float bA = bias[mA], bB = bias[mA + 8];
        float* rowA = g_bcdt + ((size_t)(b * O3S + mA)) * NN + n0;
        float* rowB = rowA + (size_t)8 * NN;
#pragma unroll
        for (int ni = 0; ni < 4; ni++) {
            int n = wn * 32 + ni * 8 + qcol;
            *(float2*)(rowA + n) = make_float2(acc[mi][ni][0] + bA, acc[mi][ni][1] + bA);
            *(float2*)(rowB + n) = make_float2(acc[mi][ni][2] + bB, acc[mi][ni][3] + bB);
        }
    }
}

// ============================================================================
// Kernel 2: depthwise 3x3x3 conv, pad 1, + b_dw
// ============================================================================
__global__ void __launch_bounds__(256) conv_kernel(
    const float* __restrict__ wdw, const float* __restrict__ bdw)
{
    __shared__ float s[3][34][66];
    __shared__ float wt[27];

    const int dz = blockIdx.x >> 1;
    const int hhalf = blockIdx.x & 1;
    const int ch = blockIdx.y;
    const int b  = blockIdx.z;
    const int h0 = hhalf * 32;
    const int tid = threadIdx.x;

    const float* base = g_bcdt + ((size_t)(b * O3S + ch)) * NN;

    for (int idx = tid; idx < 3 * 34 * 66; idx += 256) {
        int kd = idx / (34 * 66);
        int rem = idx % (34 * 66);
        int ih = rem / 66, iw = rem % 66;
        int d = dz - 1 + kd, h = h0 - 1 + ih, w = iw - 1;
        float v = 0.f;
        if ((unsigned)d < DD && (unsigned)h < HH && (unsigned)w < WW)
            v = base[((size_t)d * HH + h) * WW + w];
        s[kd][ih][iw] = v;
    }
    if (tid < 27) wt[tid] = wdw[ch * 27 + tid];
    __syncthreads();

    const float bb = bdw[ch];
    const int w = tid & 63;
    const int hl0 = tid >> 6;
    float* outb = g_conv + ((size_t)(b * O3S + ch)) * NN;

#pragma unroll
    for (int r = 0; r < 8; r++) {
        int hl = hl0 + r * 4;
        float acc = bb;
#pragma unroll
        for (int kd = 0; kd < 3; kd++)
#pragma unroll
            for (int kh = 0; kh < 3; kh++)
#pragma unroll
                for (int kw = 0; kw < 3; kw++)
                    acc += s[kd][hl + kh][w + kw] * wt[kd * 9 + kh * 3 + kw];
        outb[((size_t)dz * HH + h0 + hl) * WW + w] = acc;
    }
}

// ============================================================================
// Kernel 3: softmax over n of dt (A cancels), fused AB = softmax * B_
// 3 passes, FMA-pipe exp (no MUFU bottleneck). 1024 threads/block.
// ============================================================================
__global__ void __launch_bounds__(1024) softmax_ab_kernel()
{
    const int s_ = blockIdx.x;
    const int b  = blockIdx.y;
    float* dt = g_conv + ((size_t)(b * O3S + 128 + s_)) * NN;
    const float* Bp = g_conv + ((size_t)(b * O3S + s_)) * NN;
    const int tid = threadIdx.x;
    const int lane = tid & 31;
    const int warp = tid >> 5;
    __shared__ float red[32];
    __shared__ float bcast[2];

    // ---- P1: max ----
    float m = -1e30f;
    for (int i = tid * 4; i < NN; i += 4096) {
        float4 v = *(const float4*)(dt + i);
        m = fmaxf(m, fmaxf(fmaxf(v.x, v.y), fmaxf(v.z, v.w)));
    }
#pragma unroll
    for (int o = 16; o > 0; o >>= 1) m = fmaxf(m, __shfl_xor_sync(0xffffffffu, m, o));
    if (lane == 0) red[warp] = m;
    __syncthreads();
    if (warp == 0) {
        float v = red[lane];
#pragma unroll
        for (int o = 16; o > 0; o >>= 1) v = fmaxf(v, __shfl_xor_sync(0xffffffffu, v, o));
        if (lane == 0) bcast[0] = v;
    }
    __syncthreads();
    const float M = bcast[0];

    // ---- P2: sum of exp ----
    float sum = 0.f;
    for (int i = tid * 4; i < NN; i += 4096) {
        float4 v = *(const float4*)(dt + i);
        sum += fexp(v.x - M) + fexp(v.y - M) + fexp(v.z - M) + fexp(v.w - M);
    }
#pragma unroll
    for (int o = 16; o > 0; o >>= 1) sum += __shfl_xor_sync(0xffffffffu, sum, o);
    if (lane == 0) red[warp] = sum;
    __syncthreads();
    if (warp == 0) {
        float v = red[lane];
#pragma unroll
        for (int o = 16; o > 0; o >>= 1) v += __shfl_xor_sync(0xffffffffu, v, o);
        if (lane == 0) bcast[1] = 1.f / v;
    }
    __syncthreads();
    const float inv = bcast[1];

    // ---- P3: AB = exp(dt-M)*inv*B (in place over dt) ----
    for (int i = tid * 4; i < NN; i += 4096) {
        float4 v  = *(const float4*)(dt + i);
        float4 bv = *(const float4*)(Bp + i);
        float4 o;
        o.x = fexp(v.x - M) * inv * bv.x;
        o.y = fexp(v.y - M) * inv * bv.y;
        o.z = fexp(v.z - M) * inv * bv.z;
        o.w = fexp(v.w - M) * inv * bv.w;
        *(float4*)(dt + i) = o;
    }
}

// ============================================================================
// Kernel 4 (HMMA): h[b,c,s] = sum_n x[b,c,n] * AB[b,s,n]   split-K partials
// BM=64(c), BN=64(s), BK=32. Register-prefetch double buffer.
// ============================================================================
#define HB_STRIDE 40   // halves per 32-k row of B (s rows)

__global__ void __launch_bounds__(256) hgemm_mma_kernel(const float* __restrict__ x)
{
    __shared__ __align__(16) uint16_t As_hi[64 * A_STRIDE];
    __shared__ __align__(16) uint16_t As_lo[64 * A_STRIDE];
    __shared__ __align__(16) uint16_t Bs_hi[64 * HB_STRIDE];
    __shared__ __align__(16) uint16_t Bs_lo[64 * HB_STRIDE];

    const int c0 = blockIdx.x * 64;          // fastest -> L2 sharing of AB tile
    const int ks = blockIdx.y;               // 0..63
    const int b  = blockIdx.z;
    const int nbase = ks * (NN / KSPLIT_H);  // 1024 chunk
    const int tid  = threadIdx.x;
    const int wid  = tid >> 5;
    const int lane = tid & 31;
    const int wm = wid >> 2;                 // 0..1 (c)
    const int wn = wid & 3;                  // 0..3 (s)

    const float* xb = x + ((size_t)(b * CC + c0)) * NN;
    const float* ab = g_conv + ((size_t)(b * O3S + 128)) * NN;
    const uint32_t as_hi = smem_u32(As_hi), as_lo = smem_u32(As_lo);
    const uint32_t bs_hi = smem_u32(Bs_hi), bs_lo = smem_u32(Bs_lo);

    // load indices: row pairs (r, r+32), col lk
    const int lr = tid >> 3;            // 0..31
    const int lk = (tid & 7) << 2;      // 0..28

    float acc[2][2][4];
#pragma unroll
    for (int i = 0; i < 2; i++)
#pragma unroll
        for (int j = 0; j < 2; j++)
#pragma unroll
            for (int q = 0; q < 4; q++) acc[i][j][q] = 0.f;

    // prefetch first tile
    float4 rx[2], rab[2];
    rx[0]  = *(const float4*)(xb + (size_t)lr * NN + nbase + lk);
    rx[1]  = *(const float4*)(xb + (size_t)(lr + 32) * NN + nbase + lk);
    rab[0] = *(const float4*)(ab + (size_t)lr * NN + nbase + lk);
    rab[1] = *(const float4*)(ab + (size_t)(lr + 32) * NN + nbase + lk);

    for (int kc = 0; kc < NN / KSPLIT_H; kc += 32) {
        // convert prefetched regs -> smem
#pragma unroll
        for (int r = 0; r < 2; r++) {
            float4 v = rx[r];
            uint32_t h01, l01, h23, l23;
            split2(v.x, v.y, h01, l01);
            split2(v.z, v.w, h23, l23);
            int off = (lr + r * 32) * A_STRIDE + lk;
            *(uint2*)(As_hi + off) = make_uint2(h01, h23);
            *(uint2*)(As_lo + off) = make_uint2(l01, l23);
        }
#pragma unroll
        for (int r = 0; r < 2; r++) {
            float4 v = rab[r];
            uint32_t h01, l01, h23, l23;
            split2(v.x, v.y, h01, l01);
            split2(v.z, v.w, h23, l23);
            int off = (lr + r * 32) * HB_STRIDE + lk;
            *(uint2*)(Bs_hi + off) = make_uint2(h01, h23);
            *(uint2*)(Bs_lo + off) = make_uint2(l01, l23);
        }
        __syncthreads();

        // prefetch next tile (overlaps with MMA)
        if (kc + 32 < NN / KSPLIT_H) {
            const int nb2 = nbase + kc + 32;
            rx[0]  = *(const float4*)(xb + (size_t)lr * NN + nb2 + lk);
            rx[1]  = *(const float4*)(xb + (size_t)(lr + 32) * NN + nb2 + lk);
            rab[0] = *(const float4*)(ab + (size_t)lr * NN + nb2 + lk);
            rab[1] = *(const float4*)(ab + (size_t)(lr + 32) * NN + nb2 + lk);
        }

#pragma unroll
        for (int kq = 0; kq < 2; kq++) {
            uint32_t a_hi[2][4], a_lo[2][4];
            const int arow = lane & 15;
            const int acol = (lane >> 4) << 3;
#pragma unroll
            for (int mi = 0; mi < 2; mi++) {
                uint32_t off = (uint32_t)((wm * 32 + mi * 16 + arow) * A_STRIDE
                                          + kq * 16 + acol) * 2;
                ldsm_x4(a_hi[mi], as_hi + off);
                ldsm_x4(a_lo[mi], as_lo + off);
            }
            uint32_t b_hi[2][2], b_lo[2][2];
            const int l = lane & 15;
            const int srow = l & 7;
            const int koff = (l >> 3) << 3;
#pragma unroll
            for (int ni = 0; ni < 2; ni++) {
                uint32_t off = (uint32_t)((wn * 16 + ni * 8 + srow) * HB_STRIDE
                                          + kq * 16 + koff) * 2;
                ldsm_x2(b_hi[ni], bs_hi + off);
                ldsm_x2(b_lo[ni], bs_lo + off);
            }
#pragma unroll
            for (int mi = 0; mi < 2; mi++)
#pragma unroll
                for (int ni = 0; ni < 2; ni++) {
                    mma_bf16(acc[mi][ni], a_hi[mi], b_hi[ni]);
                    mma_bf16(acc[mi][ni], a_hi[mi], b_lo[ni]);
                    mma_bf16(acc[mi][ni], a_lo[mi], b_hi[ni]);
                }
        }
        __syncthreads();
    }

    float* dst = g_hpart + (size_t)ks * (BB * CC * SS);
    const int qrow = lane >> 2;
    const int qcol = (lane & 3) << 1;
#pragma unroll
    for (int mi = 0; mi < 2; mi++) {
        int cA = c0 + wm * 32 + mi * 16 + qrow;
#pragma unroll
        for (int ni = 0; ni < 2; ni++) {
            int sA = wn * 16 + ni * 8 + qcol;
            float* pA = dst + ((size_t)(b * CC + cA)) * SS + sA;
            float* pB = dst + ((size_t)(b * CC + cA + 8)) * SS + sA;
            *(float2*)pA = make_float2(acc[mi][ni][0], acc[mi][ni][1]);
            *(float2*)pB = make_float2(acc[mi][ni][2], acc[mi][ni][3]);
        }
    }
}

// deterministic reduction of split-K partials
__global__ void __launch_bounds__(256) hreduce_kernel()
{
    int i = blockIdx.x * 256 + threadIdx.x;   // < 65536
    float sum = 0.f;
#pragma unroll
    for (int ks = 0; ks < KSPLIT_H; ks++)
        sum += g_hpart[(size_t)ks * (BB * CC * SS) + i];
    g_h[i] = sum;
}

// ============================================================================
// Kernel 5: hz = W_hz @ h + b_hz ; h3 = h2*silu(z) + h2*Dp
// ============================================================================
__global__ void __launch_bounds__(256) e1_kernel(
    const float* __restrict__ Whz, const float* __restrict__ bhz,
    const float* __restrict__ Dp)
{
    const int b = blockIdx.y;
    const int o = blockIdx.x * 4 + (threadIdx.x >> 6);
    const int s_ = threadIdx.x & 63;
    const float* hb = g_h + (size_t)b * CC * SS;
    const float* w1 = Whz + (size_t)o * 256;
    const float* w2 = Whz + (size_t)(o + 256) * 256;
    float a1 = bhz[o], a2 = bhz[o + 256];
    for (int c = 0; c < 256; c++) {
        float hv = hb[c * 64 + s_];
        a1 += w1[c] * hv;
        a2 += w2[c] * hv;
    }
    float sig = 1.f / (1.f + __expf(-a2));
    g_h3[((size_t)b * CC + o) * SS + s_] = a1 * (a2 * sig) + a1 * Dp[0];
}

// Kernel 6: h4 = W_out @ h3 + b_out ; write to scratch + output tail
__global__ void __launch_bounds__(256) e2_kernel(
    const float* __restrict__ Wout, const float* __restrict__ bout,
    float* __restrict__ out)
{
    const int b = blockIdx.y;
    const int o = blockIdx.x * 4 + (threadIdx.x >> 6);
    const int s_ = threadIdx.x & 63;
    const float* hb = g_h3 + (size_t)b * CC * SS;
    const float* w1 = Wout + (size_t)o * 256;
    float acc = bout[o];
    for (int c = 0; c < 256; c++)
        acc += w1[c] * hb[c * 64 + s_];
    size_t idx = ((size_t)b * CC + o) * SS + s_;
    g_h4[idx] = acc;
    out[YSIZE + idx] = acc;
}

// ============================================================================
// Kernel 7 (HMMA): y[b,c,n] = sum_s h4[b,c,s] * C_[b,s,n]
// BM=64, BN=128, K=64 (2 x BK=32).
// ============================================================================
__global__ void __launch_bounds__(256) ygemm_mma_kernel(float* __restrict__ y)
{
    __shared__ __align__(16) uint16_t As_hi[64 * A_STRIDE];
    __shared__ __align__(16) uint16_t As_lo[64 * A_STRIDE];
    __shared__ __align__(16) uint16_t Bs_hi[32 * B_STRIDE];
    __shared__ __align__(16) uint16_t Bs_lo[32 * B_STRIDE];

    const int m0 = blockIdx.x * 64;     // fastest -> L2 sharing of C_ tile
    const int n0 = blockIdx.y * 128;
    const int b  = blockIdx.z;
    const int tid  = threadIdx.x;
    const int wid  = tid >> 5;
    const int lane = tid & 31;
    const int wm = wid >> 2;
    const int wn = wid & 3;

    const float* h4b = g_h4 + (size_t)b * CC * SS;
    const float* cp  = g_conv + ((size_t)(b * O3S + 64)) * NN;  // C_ channels
    const uint32_t as_hi = smem_u32(As_hi), as_lo = smem_u32(As_lo);
    const uint32_t bs_hi = smem_u32(Bs_hi), bs_lo = smem_u32(Bs_lo);

    float acc[2][4][4];
#pragma unroll
    for (int i = 0; i < 2; i++)
#pragma unroll
        for (int j = 0; j < 4; j++)
#pragma unroll
            for (int q = 0; q < 4; q++) acc[i][j][q] = 0.f;

    for (int k0 = 0; k0 < 64; k0 += 32) {
#pragma unroll
        for (int r = 0; r < 2; r++) {
            int f = tid + r * 256;
            int m = f >> 3, k = (f & 7) << 2;
            float4 v = *(const float4*)(h4b + (size_t)(m0 + m) * SS + k0 + k);
            uint32_t h01, l01, h23, l23;
            split2(v.x, v.y, h01, l01);
            split2(v.z, v.w, h23, l23);
            int off = m * A_STRIDE + k;
            *(uint2*)(As_hi + off) = make_uint2(h01, h23);
            *(uint2*)(As_lo + off) = make_uint2(l01, l23);
        }
#pragma unroll
        for (int r = 0; r < 4; r++) {
            int f = tid + r * 256;
            int krow = f >> 5, n = (f & 31) << 2;
            float4 v = *(const float4*)(cp + (size_t)(k0 + krow) * NN + n0 + n);
            uint32_t h01, l01, h23, l23;
            split2(v.x, v.y, h01, l01);
            split2(v.z, v.w, h23, l23);
            int off = krow * B_STRIDE + n;
            *(uint2*)(Bs_hi + off) = make_uint2(h01, h23);
            *(uint2*)(Bs_lo + off) = make_uint2(l01, l23);
        }
        __syncthreads();

#pragma unroll
        for (int ks = 0; ks < 2; ks++) {
            uint32_t a_hi[2][4], a_lo[2][4];
            const int arow = lane & 15;
            const int acol = (lane >> 4) << 3;
#pragma unroll
            for (int mi = 0; mi < 2; mi++) {
                uint32_t off = (uint32_t)((wm * 32 + mi * 16 + arow) * A_STRIDE
                                          + ks * 16 + acol) * 2;
                ldsm_x4(a_hi[mi], as_hi + off);
                ldsm_x4(a_lo[mi], as_lo + off);
            }
            uint32_t b_hi[4][2], b_lo[4][2];
            const int brow = lane & 15;
#pragma unroll
            for (int ni = 0; ni < 4; ni++) {
                uint32_t off = (uint32_t)((ks * 16 + brow) * B_STRIDE
                                          + wn * 32 + ni * 8) * 2;
                ldsm_x2_t(b_hi[ni], bs_hi + off);
                ldsm_x2_t(b_lo[ni], bs_lo + off);
            }
#pragma unroll
            for (int mi = 0; mi < 2; mi++)
#pragma unroll
                for (int ni = 0; ni < 4; ni++) {
                    mma_bf16(acc[mi][ni], a_hi[mi], b_hi[ni]);
                    mma_bf16(acc[mi][ni], a_hi[mi], b_lo[ni]);
                    mma_bf16(acc[mi][ni], a_lo[mi], b_hi[ni]);
                }
        }
        __syncthreads();
    }

    const int qrow = lane >> 2;
    const int qcol = (lane & 3) << 1;
#pragma unroll
    for (int mi = 0; mi < 2; mi++) {
        int mA = m0 + wm * 32 + mi * 16 + qrow;
        float* rowA = y + ((size_t)(b * CC + mA)) * NN + n0;
        float* rowB = rowA + (size_t)8 * NN;
#pragma unroll
        for (int ni = 0; ni < 4; ni++) {
            int n = wn * 32 + ni * 8 + qcol;
            *(float2*)(rowA + n) = make_float2(acc[mi][ni][0], acc[mi][ni][1]);
            *(float2*)(rowB + n) = make_float2(acc[mi][ni][2], acc[mi][ni][3]);
        }
    }
}

// ============================================================================
extern "C" void kernel_launch(void* const* d_in, const int* in_sizes, int n_in,
                              void* d_out, int out_size)
{
    const float* x      = (const float*)d_in[0];
    const float* W_bcdt = (const float*)d_in[1];
    const float* b_bcdt = (const float*)d_in[2];
    const float* W_dw   = (const float*)d_in[3];
    const float* b_dw   = (const float*)d_in[4];
    const float* W_hz   = (const float*)d_in[5];
    const float* b_hz   = (const float*)d_in[6];
    const float* W_out  = (const float*)d_in[7];
    const float* b_out  = (const float*)d_in[8];
    // d_in[9] = A : unused (softmax shift invariance along the reduced axis)
    const float* Dp     = (const float*)d_in[10];
    float* out = (float*)d_out;

    gemm1_mma_kernel<<<dim3(3, NN / 128, BB), 256>>>(x, W_bcdt, b_bcdt);
    conv_kernel<<<dim3(32, O3S, BB), 256>>>(W_dw, b_dw);
    softmax_ab_kernel<<<dim3(SS, BB), 1024>>>();
    hgemm_mma_kernel<<<dim3(4, KSPLIT_H, BB), 256>>>(x);
    hreduce_kernel<<<256, 256>>>();
    e1_kernel<<<dim3(64, BB), 256>>>(W_hz, b_hz, Dp);
    e2_kernel<<<dim3(64, BB), 256>>>(W_out, b_out, out);
    ygemm_mma_kernel<<<dim3(4, NN / 128, BB), 256>>>(out);
}

// round 7
// speedup vs baseline: 2.2427x; 1.0381x over previous
#include <cuda_runtime.h>
#include <cuda_bf16.h>
#include <cstdint>
#include <cstddef>

// Problem constants
#define BB   4
#define CC   256      // D_MODEL = D_INNER
#define SS   64
#define DD   16
#define HH   64
#define WW   64
#define NN   65536    // D*H*W
#define O3S  192      // 3*S
#define KSPLIT_H 64   // split-K factor for h-GEMM

static const size_t YSIZE = (size_t)BB * CC * NN;   // 67108864

// ---- static scratch (no runtime allocation allowed) ----
__device__ float g_bcdt[(size_t)BB * O3S * NN];
__device__ float g_conv[(size_t)BB * O3S * NN];
__device__ float g_hpart[(size_t)KSPLIT_H * BB * CC * SS];
__device__ float g_psum[BB * SS * 4];   // per-quarter exp-sums (softmax)
__device__ float g_h [BB * CC * SS];
__device__ float g_h3[BB * CC * SS];
__device__ float g_h4[BB * CC * SS];

// ============================================================================
// helpers
// ============================================================================
__device__ __forceinline__ uint32_t smem_u32(const void* p) {
    uint32_t a;
    asm("{ .reg .u64 t; cvta.to.shared.u64 t, %1; cvt.u32.u64 %0, t; }" : "=r"(a) : "l"(p));
    return a;
}
__device__ __forceinline__ void ldsm_x4(uint32_t* r, uint32_t addr) {
    asm volatile("ldmatrix.sync.aligned.m8n8.x4.shared.b16 {%0,%1,%2,%3}, [%4];"
        : "=r"(r[0]), "=r"(r[1]), "=r"(r[2]), "=r"(r[3]) : "r"(addr));
}
__device__ __forceinline__ void ldsm_x2(uint32_t* r, uint32_t addr) {
    asm volatile("ldmatrix.sync.aligned.m8n8.x2.shared.b16 {%0,%1}, [%2];"
        : "=r"(r[0]), "=r"(r[1]) : "r"(addr));
}
__device__ __forceinline__ void ldsm_x2_t(uint32_t* r, uint32_t addr) {
    asm volatile("ldmatrix.sync.aligned.m8n8.x2.trans.shared.b16 {%0,%1}, [%2];"
        : "=r"(r[0]), "=r"(r[1]) : "r"(addr));
}
__device__ __forceinline__ void mma_bf16(float* c, const uint32_t* a, const uint32_t* b) {
    asm volatile(
        "mma.sync.aligned.m16n8k16.row.col.f32.bf16.bf16.f32 "
        "{%0,%1,%2,%3}, {%4,%5,%6,%7}, {%8,%9}, {%0,%1,%2,%3};"
        : "+f"(c[0]), "+f"(c[1]), "+f"(c[2]), "+f"(c[3])
        : "r"(a[0]), "r"(a[1]), "r"(a[2]), "r"(a[3]), "r"(b[0]), "r"(b[1]));
}
__device__ __forceinline__ void split2(float v0, float v1, uint32_t& hi, uint32_t& lo) {
    __nv_bfloat16 h0 = __float2bfloat16(v0), h1 = __float2bfloat16(v1);
    float r0 = v0 - __bfloat162float(h0), r1 = v1 - __bfloat162float(h1);
    __nv_bfloat162 hh = __halves2bfloat162(h0, h1);
    __nv_bfloat162 ll = __floats2bfloat162_rn(r0, r1);
    hi = *(uint32_t*)&hh; lo = *(uint32_t*)&ll;
}
// FMA-pipe exp (poly 2^f on [-0.5,0.5], ~2e-9 rel err), clamped both sides
__device__ __forceinline__ float fexp(float x) {
    float t = fminf(fmaxf(x * 1.4426950408889634f, -125.0f), 125.0f);
    float n = rintf(t);
    float f = t - n;
    float p = 1.5403530393381609e-4f;
    p = fmaf(p, f, 1.3333558146428443e-3f);
    p = fmaf(p, f, 9.618129107628477e-3f);
    p = fmaf(p, f, 5.550410866482158e-2f);
    p = fmaf(p, f, 2.402265069591999e-1f);
    p = fmaf(p, f, 6.931471805599453e-1f);
    p = fmaf(p, f, 1.0f);
    return __int_as_float(((int)n + 127) << 23) * p;
}
__device__ __forceinline__ void cp16(uint32_t s, const void* g) {
    asm volatile("cp.async.cg.shared.global [%0], [%1], 16;" :: "r"(s), "l"(g));
}
#define CP_COMMIT() asm volatile("cp.async.commit_group;")
#define CP_WAIT(n)  asm volatile("cp.async.wait_group %0;" :: "n"(n))

#define A_STRIDE 40    // halves per 32-k row (32 + 8 pad)
#define B_STRIDE 136   // halves per 128-n row (128 + 8 pad)
#define HB_STRIDE 40

// ============================================================================
// Kernel 1 (HMMA): BCdt = W_bcdt(192x256) @ x(b,256,N) + b_bcdt
// BM=64, BN=128, BK=32. x tile register-prefetched.
// ============================================================================
__global__ void __launch_bounds__(256) gemm1_mma_kernel(
    const float* __restrict__ x, const float* __restrict__ W,
    const float* __restrict__ bias)
{
    __shared__ __align__(16) uint16_t As_hi[64 * A_STRIDE];
    __shared__ __align__(16) uint16_t As_lo[64 * A_STRIDE];
    __shared__ __align__(16) uint16_t Bs_hi[32 * B_STRIDE];
    __shared__ __align__(16) uint16_t Bs_lo[32 * B_STRIDE];

    const int m0 = blockIdx.x * 64;     // fastest -> L2 sharing of x tile
    const int n0 = blockIdx.y * 128;
    const int b  = blockIdx.z;
    const int tid  = threadIdx.x;
    const int wid  = tid >> 5;
    const int lane = tid & 31;
    const int wm = wid >> 2;
    const int wn = wid & 3;

    const float* xb = x + (size_t)b * CC * NN;
    const uint32_t as_hi = smem_u32(As_hi), as_lo = smem_u32(As_lo);
    const uint32_t bs_hi = smem_u32(Bs_hi), bs_lo = smem_u32(Bs_lo);

    const int krow0 = tid >> 5;
    const int nloc  = (tid & 31) << 2;

    float acc[2][4][4];
#pragma unroll
    for (int i = 0; i < 2; i++)
#pragma unroll
        for (int j = 0; j < 4; j++)
#pragma unroll
            for (int q = 0; q < 4; q++) acc[i][j][q] = 0.f;

    float4 rbx[4];
#pragma unroll
    for (int r = 0; r < 4; r++)
        rbx[r] = *(const float4*)(xb + (size_t)(krow0 + r * 8) * NN + n0 + nloc);

    for (int k0 = 0; k0 < 256; k0 += 32) {
#pragma unroll
        for (int r = 0; r < 2; r++) {
            int f = tid + r * 256;
            int m = f >> 3, k = (f & 7) << 2;
            float4 v = *(const float4*)(W + (size_t)(m0 + m) * 256 + k0 + k);
            uint32_t h01, l01, h23, l23;
            split2(v.x, v.y, h01, l01);
            split2(v.z, v.w, h23, l23);
            int off = m * A_STRIDE + k;
            *(uint2*)(As_hi + off) = make_uint2(h01, h23);
            *(uint2*)(As_lo + off) = make_uint2(l01, l23);
        }
#pragma unroll
        for (int r = 0; r < 4; r++) {
            float4 v = rbx[r];
            uint32_t h01, l01, h23, l23;
            split2(v.x, v.y, h01, l01);
            split2(v.z, v.w, h23, l23);
            int off = (krow0 + r * 8) * B_STRIDE + nloc;
            *(uint2*)(Bs_hi + off) = make_uint2(h01, h23);
            *(uint2*)(Bs_lo + off) = make_uint2(l01, l23);
        }
        __syncthreads();

        if (k0 + 32 < 256) {
#pragma unroll
            for (int r = 0; r < 4; r++)
                rbx[r] = *(const float4*)(xb + (size_t)(k0 + 32 + krow0 + r * 8) * NN + n0 + nloc);
        }

#pragma unroll
        for (int ks = 0; ks < 2; ks++) {
            uint32_t a_hi[2][4], a_lo[2][4];
            const int arow = lane & 15;
            const int acol = (lane >> 4) << 3;
#pragma unroll
            for (int mi = 0; mi < 2; mi++) {
                uint32_t off = (uint32_t)((wm * 32 + mi * 16 + arow) * A_STRIDE
                                          + ks * 16 + acol) * 2;
                ldsm_x4(a_hi[mi], as_hi + off);
                ldsm_x4(a_lo[mi], as_lo + off);
            }
            uint32_t b_hi[4][2], b_lo[4][2];
            const int brow = lane & 15;
#pragma unroll
            for (int ni = 0; ni < 4; ni++) {
                uint32_t off = (uint32_t)((ks * 16 + brow) * B_STRIDE
                                          + wn * 32 + ni * 8) * 2;
                ldsm_x2_t(b_hi[ni], bs_hi + off);
                ldsm_x2_t(b_lo[ni], bs_lo + off);
            }
#pragma unroll
            for (int mi = 0; mi < 2; mi++)
#pragma unroll
                for (int ni = 0; ni < 4; ni++) {
                    mma_bf16(acc[mi][ni], a_hi[mi], b_hi[ni]);
                    mma_bf16(acc[mi][ni], a_hi[mi], b_lo[ni]);
                    mma_bf16(acc[mi][ni], a_lo[mi], b_hi[ni]);
                }
        }
        __syncthreads();
    }

    const int qrow = lane >> 2;
    const int qcol = (lane & 3) << 1;
#pragma unroll
    for (int mi = 0; mi < 2; mi++) {
        int mA = m0 + wm * 32 + mi * 16 + qrow;
        float bA = bias[mA], bB = bias[mA + 8];
        float* rowA = g_bcdt + ((size_t)(b * O3S + mA)) * NN + n0;
        float* rowB = rowA + (size_t)8 * NN;
#pragma unroll
        for (int ni = 0; ni < 4; ni++) {
            int n = wn * 32 + ni * 8 + qcol;
            *(float2*)(rowA + n) = make_float2(acc[mi][ni][0] + bA, acc[mi][ni][1] + bA);
            *(float2*)(rowB + n) = make_float2(acc[mi][ni][2] + bB, acc[mi][ni][3] + bB);
        }
    }
}

// ============================================================================
// Kernel 2: depthwise 3x3x3 conv, pad 1, + b_dw
// ============================================================================
__global__ void __launch_bounds__(256) conv_kernel(
    const float* __restrict__ wdw, const float* __restrict__ bdw)
{
    __shared__ float s[3][34][66];
    __shared__ float wt[27];

    const int dz = blockIdx.x >> 1;
    const int hhalf = blockIdx.x & 1;
    const int ch = blockIdx.y;
    const int b  = blockIdx.z;
    const int h0 = hhalf * 32;
    const int tid = threadIdx.x;

    const float* base = g_bcdt + ((size_t)(b * O3S + ch)) * NN;

    for (int idx = tid; idx < 3 * 34 * 66; idx += 256) {
        int kd = idx / (34 * 66);
        int rem = idx % (34 * 66);
        int ih = rem / 66, iw = rem % 66;
        int d = dz - 1 + kd, h = h0 - 1 + ih, w = iw - 1;
        float v = 0.f;
        if ((unsigned)d < DD && (unsigned)h < HH && (unsigned)w < WW)
            v = base[((size_t)d * HH + h) * WW + w];
        s[kd][ih][iw] = v;
    }
    if (tid < 27) wt[tid] = wdw[ch * 27 + tid];
    __syncthreads();

    const float bb = bdw[ch];
    const int w = tid & 63;
    const int hl0 = tid >> 6;
    float* outb = g_conv + ((size_t)(b * O3S + ch)) * NN;

#pragma unroll
    for (int r = 0; r < 8; r++) {
        int hl = hl0 + r * 4;
        float acc = bb;
#pragma unroll
        for (int kd = 0; kd < 3; kd++)
#pragma unroll
            for (int kh = 0; kh < 3; kh++)
#pragma unroll
                for (int kw = 0; kw < 3; kw++)
                    acc += s[kd][hl + kh][w + kw] * wt[kd * 9 + kh * 3 + kw];
        outb[((size_t)dz * HH + h0 + hl) * WW + w] = acc;
    }
}

// ============================================================================
// Kernel 3: SINGLE-PASS unnormalized softmax-AB.
// AB_unnorm = exp(dt) * B_ written over dt channels; per-quarter exp-sums
// stored to g_psum. Normalization (1/sum) is folded into hreduce.
// (No max subtraction: dt is conv output of 0.05-scaled weights, |dt| small;
//  fexp is clamped so no inf even in pathological cases.)
// Grid: (SS*4 quarters, BB), 256 threads.
// ============================================================================
__global__ void __launch_bounds__(256) softmax_ab_kernel()
{
    const int s_ = blockIdx.x >> 2;
    const int q  = blockIdx.x & 3;
    const int b  = blockIdx.y;
    float* dt = g_conv + ((size_t)(b * O3S + 128 + s_)) * NN;
    const float* Bp = g_conv + ((size_t)(b * O3S + s_)) * NN;
    const int base = q * (NN / 4);
    const int tid = threadIdx.x;
    const int lane = tid & 31;
    const int warp = tid >> 5;
    __shared__ float red[8];

    float sum = 0.f;
    for (int i = base + tid * 4; i < base + NN / 4; i += 1024) {
        float4 v  = *(const float4*)(dt + i);
        float4 bv = *(const float4*)(Bp + i);
        float ex = fexp(v.x), ey = fexp(v.y), ez = fexp(v.z), ew = fexp(v.w);
        sum += (ex + ey) + (ez + ew);
        float4 o = make_float4(ex * bv.x, ey * bv.y, ez * bv.z, ew * bv.w);
        *(float4*)(dt + i) = o;
    }
#pragma unroll
    for (int o = 16; o > 0; o >>= 1) sum += __shfl_xor_sync(0xffffffffu, sum, o);
    if (lane == 0) red[warp] = sum;
    __syncthreads();
    if (tid == 0) {
        float v = red[0] + red[1] + red[2] + red[3] + red[4] + red[5] + red[6] + red[7];
        g_psum[(b * SS + s_) * 4 + q] = v;
    }
}

// ============================================================================
// Kernel 4 (HMMA): h_unnorm partials = sum_n x[b,c,n] * AB_unnorm[b,s,n]
// BM=64(c), BN=64(s), BK=32. cp.async 3-stage fp32 smem pipeline.
// ============================================================================
#define NSTAGE 3
#define STG_F  (64 * 36)          // floats per stage buffer (pad 36)
// dyn smem layout (bytes):
//   xf : NSTAGE*STG_F*4
//   af : NSTAGE*STG_F*4
//   As_hi/As_lo : 64*A_STRIDE*2 each
//   Bs_hi/Bs_lo : 64*HB_STRIDE*2 each
#define HG_SMEM (2 * NSTAGE * STG_F * 4 + 4 * 64 * A_STRIDE * 2)

__global__ void __launch_bounds__(256) hgemm_mma_kernel(const float* __restrict__ x)
{
    extern __shared__ __align__(16) char dyn[];
    float* xf = (float*)dyn;
    float* af = xf + NSTAGE * STG_F;
    uint16_t* As_hi_p = (uint16_t*)(af + NSTAGE * STG_F);
    uint16_t* As_lo_p = As_hi_p + 64 * A_STRIDE;
    uint16_t* Bs_hi_p = As_lo_p + 64 * A_STRIDE;
    uint16_t* Bs_lo_p = Bs_hi_p + 64 * HB_STRIDE;

    const int c0 = blockIdx.x * 64;          // fastest -> L2 sharing of AB tile
    const int ks = blockIdx.y;               // 0..63
    const int b  = blockIdx.z;
    const int nbase = ks * (NN / KSPLIT_H);  // 1024 chunk
    const int tid  = threadIdx.x;
    const int wid  = tid >> 5;
    const int lane = tid & 31;
    const int wm = wid >> 2;
    const int wn = wid & 3;

    const float* xb = x + ((size_t)(b * CC + c0)) * NN;
    const float* ab = g_conv + ((size_t)(b * O3S + 128)) * NN;
    const uint32_t as_hi = smem_u32(As_hi_p), as_lo = smem_u32(As_lo_p);
    const uint32_t bs_hi = smem_u32(Bs_hi_p), bs_lo = smem_u32(Bs_lo_p);
    const uint32_t xf_u = smem_u32(xf), af_u = smem_u32(af);

    const int lr = tid >> 3;            // 0..31
    const int lk = (tid & 7) << 2;      // 0..28

    float acc[2][2][4];
#pragma unroll
    for (int i = 0; i < 2; i++)
#pragma unroll
        for (int j = 0; j < 2; j++)
#pragma unroll
            for (int q = 0; q < 4; q++) acc[i][j][q] = 0.f;

    // cp.async stage issue (one commit group per stage)
    auto issue = [&](int st, int kc) {
        uint32_t xs = xf_u + (uint32_t)(st * STG_F + lr * 36 + lk) * 4;
        const float* gx = xb + (size_t)lr * NN + nbase + kc + lk;
        cp16(xs, gx);
        cp16(xs + 32 * 36 * 4, gx + (size_t)32 * NN);
        uint32_t as = af_u + (uint32_t)(st * STG_F + lr * 36 + lk) * 4;
        const float* ga = ab + (size_t)lr * NN + nbase + kc + lk;
        cp16(as, ga);
        cp16(as + 32 * 36 * 4, ga + (size_t)32 * NN);
        CP_COMMIT();
    };

    issue(0, 0);
    issue(1, 32);

    const int ITERS = (NN / KSPLIT_H) / 32;   // 32
    for (int it = 0; it < ITERS; it++) {
        const int st = it % NSTAGE;
        if (it == ITERS - 1) { CP_WAIT(0); } else { CP_WAIT(1); }

        // convert own staged fp32 -> bf16 hi/lo smem (no cross-thread dep)
        {
            float4 v0 = *(float4*)(xf + st * STG_F + lr * 36 + lk);
            float4 v1 = *(float4*)(xf + st * STG_F + (lr + 32) * 36 + lk);
            uint32_t h01, l01, h23, l23;
            split2(v0.x, v0.y, h01, l01); split2(v0.z, v0.w, h23, l23);
            *(uint2*)(As_hi_p + lr * A_STRIDE + lk) = make_uint2(h01, h23);
            *(uint2*)(As_lo_p + lr * A_STRIDE + lk) = make_uint2(l01, l23);
            split2(v1.x, v1.y, h01, l01); split2(v1.z, v1.w, h23, l23);
            *(uint2*)(As_hi_p + (lr + 32) * A_STRIDE + lk) = make_uint2(h01, h23);
            *(uint2*)(As_lo_p + (lr + 32) * A_STRIDE + lk) = make_uint2(l01, l23);

            float4 a0 = *(float4*)(af + st * STG_F + lr * 36 + lk);
            float4 a1 = *(float4*)(af + st * STG_F + (lr + 32) * 36 + lk);
            split2(a0.x, a0.y, h01, l01); split2(a0.z, a0.w, h23, l23);
            *(uint2*)(Bs_hi_p + lr * HB_STRIDE + lk) = make_uint2(h01, h23);
            *(uint2*)(Bs_lo_p + lr * HB_STRIDE + lk) = make_uint2(l01, l23);
            split2(a1.x, a1.y, h01, l01); split2(a1.z, a1.w, h23, l23);
            *(uint2*)(Bs_hi_p + (lr + 32) * HB_STRIDE + lk) = make_uint2(h01, h23);
            *(uint2*)(Bs_lo_p + (lr + 32) * HB_STRIDE + lk) = make_uint2(l01, l23);
        }
        __syncthreads();

        if (it + NSTAGE - 1 < ITERS)
            issue((it + NSTAGE - 1) % NSTAGE, (it + NSTAGE - 1) * 32);

#pragma unroll
        for (int kq = 0; kq < 2; kq++) {
            uint32_t a_hi[2][4], a_lo[2][4];
            const int arow = lane & 15;
            const int acol = (lane >> 4) << 3;
#pragma unroll
            for (int mi = 0; mi < 2; mi++) {
                uint32_t off = (uint32_t)((wm * 32 + mi * 16 + arow) * A_STRIDE
                                          + kq * 16 + acol) * 2;
                ldsm_x4(a_hi[mi], as_hi + off);
                ldsm_x4(a_lo[mi], as_lo + off);
            }
            uint32_t b_hi[2][2], b_lo[2][2];
            const int l = lane & 15;
            const int srow = l & 7;
            const int koff = (l >> 3) << 3;
#pragma unroll
            for (int ni = 0; ni < 2; ni++) {
                uint32_t off = (uint32_t)((wn * 16 + ni * 8 + srow) * HB_STRIDE
                                          + kq * 16 + koff) * 2;
                ldsm_x2(b_hi[ni], bs_hi + off);
                ldsm_x2(b_lo[ni], bs_lo + off);
            }
#pragma unroll
            for (int mi = 0; mi < 2; mi++)
#pragma unroll
                for (int ni = 0; ni < 2; ni++) {
                    mma_bf16(acc[mi][ni], a_hi[mi], b_hi[ni]);
                    mma_bf16(acc[mi][ni], a_hi[mi], b_lo[ni]);
                    mma_bf16(acc[mi][ni], a_lo[mi], b_hi[ni]);
                }
        }
        __syncthreads();
    }

    float* dst = g_hpart + (size_t)ks * (BB * CC * SS);
    const int qrow = lane >> 2;
    const int qcol = (lane & 3) << 1;
#pragma unroll
    for (int mi = 0; mi < 2; mi++) {
        int cA = c0 + wm * 32 + mi * 16 + qrow;
#pragma unroll
        for (int ni = 0; ni < 2; ni++) {
            int sA = wn * 16 + ni * 8 + qcol;
            float* pA = dst + ((size_t)(b * CC + cA)) * SS + sA;
            float* pB = dst + ((size_t)(b * CC + cA + 8)) * SS + sA;
            *(float2*)pA = make_float2(acc[mi][ni][0], acc[mi][ni][1]);
            *(float2*)pB = make_float2(acc[mi][ni][2], acc[mi][ni][3]);
        }
    }
}

// reduction of split-K partials + deferred softmax normalization
__global__ void __launch_bounds__(256) hreduce_kernel()
{
    int i = blockIdx.x * 256 + threadIdx.x;   // ((b*CC+c)*SS+s) < 65536
    int b = i >> 14;
    int s = i & 63;
    const float* ps = &g_psum[(b * SS + s) * 4];
    float inv = 1.f / (ps[0] + ps[1] + ps[2] + ps[3]);
    float sum = 0.f;
#pragma unroll
    for (int ks = 0; ks < KSPLIT_H; ks++)
        sum += g_hpart[(size_t)ks * (BB * CC * SS) + i];
    g_h[i] = sum * inv;
}

// ============================================================================
// Kernel 5: hz = W_hz @ h + b_hz ; h3 = h2*silu(z) + h2*Dp
// ============================================================================
__global__ void __launch_bounds__(256) e1_kernel(
    const float* __restrict__ Whz, const float* __restrict__ bhz,
    const float* __restrict__ Dp)
{
    const int b = blockIdx.y;
    const int o = blockIdx.x * 4 + (threadIdx.x >> 6);
    const int s_ = threadIdx.x & 63;
    const float* hb = g_h + (size_t)b * CC * SS;
    const float* w1 = Whz + (size_t)o * 256;
    const float* w2 = Whz + (size_t)(o + 256) * 256;
    float a1 = bhz[o], a2 = bhz[o + 256];
    for (int c = 0; c < 256; c++) {
        float hv = hb[c * 64 + s_];
        a1 += w1[c] * hv;
        a2 += w2[c] * hv;
    }
    float sig = 1.f / (1.f + __expf(-a2));
    g_h3[((size_t)b * CC + o) * SS + s_] = a1 * (a2 * sig) + a1 * Dp[0];
}

// Kernel 6: h4 = W_out @ h3 + b_out ; write to scratch + output tail
__global__ void __launch_bounds__(256) e2_kernel(
    const float* __restrict__ Wout, const float* __restrict__ bout,
    float* __restrict__ out)
{
    const int b = blockIdx.y;
    const int o = blockIdx.x * 4 + (threadIdx.x >> 6);
    const int s_ = threadIdx.x & 63;
    const float* hb = g_h3 + (size_t)b * CC * SS;
    const float* w1 = Wout + (size_t)o * 256;
    float acc = bout[o];
    for (int c = 0; c < 256; c++)
        acc += w1[c] * hb[c * 64 + s_];
    size_t idx = ((size_t)b * CC + o) * SS + s_;
    g_h4[idx] = acc;
    out[YSIZE + idx] = acc;
}

// ============================================================================
// Kernel 7 (HMMA): y[b,c,n] = sum_s h4[b,c,s] * C_[b,s,n]
// ============================================================================
__global__ void __launch_bounds__(256) ygemm_mma_kernel(float* __restrict__ y)
{
    __shared__ __align__(16) uint16_t As_hi[64 * A_STRIDE];
    __shared__ __align__(16) uint16_t As_lo[64 * A_STRIDE];
    __shared__ __align__(16) uint16_t Bs_hi[32 * B_STRIDE];
    __shared__ __align__(16) uint16_t Bs_lo[32 * B_STRIDE];

    const int m0 = blockIdx.x * 64;     // fastest -> L2 sharing of C_ tile
    const int n0 = blockIdx.y * 128;
    const int b  = blockIdx.z;
    const int tid  = threadIdx.x;
    const int wid  = tid >> 5;
    const int lane = tid & 31;
    const int wm = wid >> 2;
    const int wn = wid & 3;

    const float* h4b = g_h4 + (size_t)b * CC * SS;
    const float* cp  = g_conv + ((size_t)(b * O3S + 64)) * NN;
    const uint32_t as_hi = smem_u32(As_hi), as_lo = smem_u32(As_lo);
    const uint32_t bs_hi = smem_u32(Bs_hi), bs_lo = smem_u32(Bs_lo);

    float acc[2][4][4];
#pragma unroll
    for (int i = 0; i < 2; i++)
#pragma unroll
        for (int j = 0; j < 4; j++)
#pragma unroll
            for (int q = 0; q < 4; q++) acc[i][j][q] = 0.f;

    for (int k0 = 0; k0 < 64; k0 += 32) {
#pragma unroll
        for (int r = 0; r < 2; r++) {
            int f = tid + r * 256;
            int m = f >> 3, k = (f & 7) << 2;
            float4 v = *(const float4*)(h4b + (size_t)(m0 + m) * SS + k0 + k);
            uint32_t h01, l01, h23, l23;
            split2(v.x, v.y, h01, l01);
            split2(v.z, v.w, h23, l23);
            int off = m * A_STRIDE + k;
            *(uint2*)(As_hi + off) = make_uint2(h01, h23);
            *(uint2*)(As_lo + off) = make_uint2(l01, l23);
        }
#pragma unroll
        for (int r = 0; r < 4; r++) {
            int f = tid + r * 256;
            int krow = f >> 5, n = (f & 31) << 2;
            float4 v = *(const float4*)(cp + (size_t)(k0 + krow) * NN + n0 + n);
            uint32_t h01, l01, h23, l23;
            split2(v.x, v.y, h01, l01);
            split2(v.z, v.w, h23, l23);
            int off = krow * B_STRIDE + n;
            *(uint2*)(Bs_hi + off) = make_uint2(h01, h23);
            *(uint2*)(Bs_lo + off) = make_uint2(l01, l23);
        }
        __syncthreads();

#pragma unroll
        for (int ks = 0; ks < 2; ks++) {
            uint32_t a_hi[2][4], a_lo[2][4];
            const int arow = lane & 15;
            const int acol = (lane >> 4) << 3;
#pragma unroll
            for (int mi = 0; mi < 2; mi++) {
                uint32_t off = (uint32_t)((wm * 32 + mi * 16 + arow) * A_STRIDE
                                          + ks * 16 + acol) * 2;
                ldsm_x4(a_hi[mi], as_hi + off);
                ldsm_x4(a_lo[mi], as_lo + off);
            }
            uint32_t b_hi[4][2], b_lo[4][2];
            const int brow = lane & 15;
#pragma unroll
            for (int ni = 0; ni < 4; ni++) {
                uint32_t off = (uint32_t)((ks * 16 + brow) * B_STRIDE
                                          + wn * 32 + ni * 8) * 2;
                ldsm_x2_t(b_hi[ni], bs_hi + off);
                ldsm_x2_t(b_lo[ni], bs_lo + off);
            }
#pragma unroll
            for (int mi = 0; mi < 2; mi++)
#pragma unroll
                for (int ni = 0; ni < 4; ni++) {
                    mma_bf16(acc[mi][ni], a_hi[mi], b_hi[ni]);
                    mma_bf16(acc[mi][ni], a_hi[mi], b_lo[ni]);
                    mma_bf16(acc[mi][ni], a_lo[mi], b_hi[ni]);
                }
        }
        __syncthreads();
    }

    const int qrow = lane >> 2;
    const int qcol = (lane & 3) << 1;
#pragma unroll
    for (int mi = 0; mi < 2; mi++) {
        int mA = m0 + wm * 32 + mi * 16 + qrow;
        float* rowA = y + ((size_t)(b * CC + mA)) * NN + n0;
        float* rowB = rowA + (size_t)8 * NN;
#pragma unroll
        for (int ni = 0; ni < 4; ni++) {
            int n = wn * 32 + ni * 8 + qcol;
            *(float2*)(rowA + n) = make_float2(acc[mi][ni][0], acc[mi][ni][1]);
            *(float2*)(rowB + n) = make_float2(acc[mi][ni][2], acc[mi][ni][3]);
        }
    }
}

// ============================================================================
extern "C" void kernel_launch(void* const* d_in, const int* in_sizes, int n_in,
                              void* d_out, int out_size)
{
    const float* x      = (const float*)d_in[0];
    const float* W_bcdt = (const float*)d_in[1];
    const float* b_bcdt = (const float*)d_in[2];
    const float* W_dw   = (const float*)d_in[3];
    const float* b_dw   = (const float*)d_in[4];
    const float* W_hz   = (const float*)d_in[5];
    const float* b_hz   = (const float*)d_in[6];
    const float* W_out  = (const float*)d_in[7];
    const float* b_out  = (const float*)d_in[8];
    // d_in[9] = A : unused (softmax shift invariance along the reduced axis)
    const float* Dp     = (const float*)d_in[10];
    float* out = (float*)d_out;

    static bool attr_set = false;
    if (!attr_set) {
        cudaFuncSetAttribute(hgemm_mma_kernel,
                             cudaFuncAttributeMaxDynamicSharedMemorySize, HG_SMEM);
        attr_set = true;
    }

    gemm1_mma_kernel<<<dim3(3, NN / 128, BB), 256>>>(x, W_bcdt, b_bcdt);
    conv_kernel<<<dim3(32, O3S, BB), 256>>>(W_dw, b_dw);
    softmax_ab_kernel<<<dim3(SS * 4, BB), 256>>>();
    hgemm_mma_kernel<<<dim3(4, KSPLIT_H, BB), 256, HG_SMEM>>>(x);
    hreduce_kernel<<<256, 256>>>();
    e1_kernel<<<dim3(64, BB), 256>>>(W_hz, b_hz, Dp);
    e2_kernel<<<dim3(64, BB), 256>>>(W_out, b_out, out);
    ygemm_mma_kernel<<<dim3(4, NN / 128, BB), 256>>>(out);
}

// round 8
// speedup vs baseline: 2.3276x; 1.0378x over previous
#include <cuda_runtime.h>
#include <cuda_bf16.h>
#include <cstdint>
#include <cstddef>

// Problem constants
#define BB   4
#define CC   256      // D_MODEL = D_INNER
#define SS   64
#define DD   16
#define HH   64
#define WW   64
#define NN   65536    // D*H*W
#define O3S  192      // 3*S
#define KSPLIT_H 64   // split-K factor for h-GEMM

static const size_t YSIZE = (size_t)BB * CC * NN;   // 67108864

// ---- static scratch (no runtime allocation allowed) ----
__device__ float g_bcdt[(size_t)BB * O3S * NN];   // GEMM1 output (pre-conv)
__device__ float g_ab[(size_t)BB * SS * NN];      // AB_unnorm = exp(conv dt)*conv B_
__device__ float g_c [(size_t)BB * SS * NN];      // conv C_ channels
__device__ float g_hpart[(size_t)KSPLIT_H * BB * CC * SS];
__device__ float g_psum[BB * SS * 2];             // per-h-half exp-sums
__device__ float g_h [BB * CC * SS];
__device__ float g_h3[BB * CC * SS];
__device__ float g_h4[BB * CC * SS];

// ============================================================================
// helpers
// ============================================================================
__device__ __forceinline__ uint32_t smem_u32(const void* p) {
    uint32_t a;
    asm("{ .reg .u64 t; cvta.to.shared.u64 t, %1; cvt.u32.u64 %0, t; }" : "=r"(a) : "l"(p));
    return a;
}
__device__ __forceinline__ void ldsm_x4(uint32_t* r, uint32_t addr) {
    asm volatile("ldmatrix.sync.aligned.m8n8.x4.shared.b16 {%0,%1,%2,%3}, [%4];"
        : "=r"(r[0]), "=r"(r[1]), "=r"(r[2]), "=r"(r[3]) : "r"(addr));
}
__device__ __forceinline__ void ldsm_x2(uint32_t* r, uint32_t addr) {
    asm volatile("ldmatrix.sync.aligned.m8n8.x2.shared.b16 {%0,%1}, [%2];"
        : "=r"(r[0]), "=r"(r[1]) : "r"(addr));
}
__device__ __forceinline__ void ldsm_x2_t(uint32_t* r, uint32_t addr) {
    asm volatile("ldmatrix.sync.aligned.m8n8.x2.trans.shared.b16 {%0,%1}, [%2];"
        : "=r"(r[0]), "=r"(r[1]) : "r"(addr));
}
__device__ __forceinline__ void mma_bf16(float* c, const uint32_t* a, const uint32_t* b) {
    asm volatile(
        "mma.sync.aligned.m16n8k16.row.col.f32.bf16.bf16.f32 "
        "{%0,%1,%2,%3}, {%4,%5,%6,%7}, {%8,%9}, {%0,%1,%2,%3};"
        : "+f"(c[0]), "+f"(c[1]), "+f"(c[2]), "+f"(c[3])
        : "r"(a[0]), "r"(a[1]), "r"(a[2]), "r"(a[3]), "r"(b[0]), "r"(b[1]));
}
__device__ __forceinline__ void split2(float v0, float v1, uint32_t& hi, uint32_t& lo) {
    __nv_bfloat16 h0 = __float2bfloat16(v0), h1 = __float2bfloat16(v1);
    float r0 = v0 - __bfloat162float(h0), r1 = v1 - __bfloat162float(h1);
    __nv_bfloat162 hh = __halves2bfloat162(h0, h1);
    __nv_bfloat162 ll = __floats2bfloat162_rn(r0, r1);
    hi = *(uint32_t*)&hh; lo = *(uint32_t*)&ll;
}
// FMA-pipe exp (poly 2^f on [-0.5,0.5], ~2e-9 rel err), clamped both sides
__device__ __forceinline__ float fexp(float x) {
    float t = fminf(fmaxf(x * 1.4426950408889634f, -125.0f), 125.0f);
    float n = rintf(t);
    float f = t - n;
    float p = 1.5403530393381609e-4f;
    p = fmaf(p, f, 1.3333558146428443e-3f);
    p = fmaf(p, f, 9.618129107628477e-3f);
    p = fmaf(p, f, 5.550410866482158e-2f);
    p = fmaf(p, f, 2.402265069591999e-1f);
    p = fmaf(p, f, 6.931471805599453e-1f);
    p = fmaf(p, f, 1.0f);
    return __int_as_float(((int)n + 127) << 23) * p;
}
__device__ __forceinline__ void cp16(uint32_t s, const void* g) {
    asm volatile("cp.async.cg.shared.global [%0], [%1], 16;" :: "r"(s), "l"(g));
}
#define CP_COMMIT() asm volatile("cp.async.commit_group;")
#define CP_WAIT(n)  asm volatile("cp.async.wait_group %0;" :: "n"(n))

#define A_STRIDE 40    // halves per 32-k row (32 + 8 pad)
#define B_STRIDE 136   // halves per 128-n row (128 + 8 pad)
#define HB_STRIDE 40

// ============================================================================
// Kernel 1 (HMMA): BCdt = W_bcdt(192x256) @ x(b,256,N) + b_bcdt
// BM=64, BN=128, BK=32. x tile register-prefetched.
// ============================================================================
__global__ void __launch_bounds__(256) gemm1_mma_kernel(
    const float* __restrict__ x, const float* __restrict__ W,
    const float* __restrict__ bias)
{
    __shared__ __align__(16) uint16_t As_hi[64 * A_STRIDE];
    __shared__ __align__(16) uint16_t As_lo[64 * A_STRIDE];
    __shared__ __align__(16) uint16_t Bs_hi[32 * B_STRIDE];
    __shared__ __align__(16) uint16_t Bs_lo[32 * B_STRIDE];

    const int m0 = blockIdx.x * 64;     // fastest -> L2 sharing of x tile
    const int n0 = blockIdx.y * 128;
    const int b  = blockIdx.z;
    const int tid  = threadIdx.x;
    const int wid  = tid >> 5;
    const int lane = tid & 31;
    const int wm = wid >> 2;
    const int wn = wid & 3;

    const float* xb = x + (size_t)b * CC * NN;
    const uint32_t as_hi = smem_u32(As_hi), as_lo = smem_u32(As_lo);
    const uint32_t bs_hi = smem_u32(Bs_hi), bs_lo = smem_u32(Bs_lo);

    const int krow0 = tid >> 5;
    const int nloc  = (tid & 31) << 2;

    float acc[2][4][4];
#pragma unroll
    for (int i = 0; i < 2; i++)
#pragma unroll
        for (int j = 0; j < 4; j++)
#pragma unroll
            for (int q = 0; q < 4; q++) acc[i][j][q] = 0.f;

    float4 rbx[4];
#pragma unroll
    for (int r = 0; r < 4; r++)
        rbx[r] = *(const float4*)(xb + (size_t)(krow0 + r * 8) * NN + n0 + nloc);

    for (int k0 = 0; k0 < 256; k0 += 32) {
#pragma unroll
        for (int r = 0; r < 2; r++) {
            int f = tid + r * 256;
            int m = f >> 3, k = (f & 7) << 2;
            float4 v = *(const float4*)(W + (size_t)(m0 + m) * 256 + k0 + k);
            uint32_t h01, l01, h23, l23;
            split2(v.x, v.y, h01, l01);
            split2(v.z, v.w, h23, l23);
            int off = m * A_STRIDE + k;
            *(uint2*)(As_hi + off) = make_uint2(h01, h23);
            *(uint2*)(As_lo + off) = make_uint2(l01, l23);
        }
#pragma unroll
        for (int r = 0; r < 4; r++) {
            float4 v = rbx[r];
            uint32_t h01, l01, h23, l23;
            split2(v.x, v.y, h01, l01);
            split2(v.z, v.w, h23, l23);
            int off = (krow0 + r * 8) * B_STRIDE + nloc;
            *(uint2*)(Bs_hi + off) = make_uint2(h01, h23);
            *(uint2*)(Bs_lo + off) = make_uint2(l01, l23);
        }
        __syncthreads();

        if (k0 + 32 < 256) {
#pragma unroll
            for (int r = 0; r < 4; r++)
                rbx[r] = *(const float4*)(xb + (size_t)(k0 + 32 + krow0 + r * 8) * NN + n0 + nloc);
        }

#pragma unroll
        for (int ks = 0; ks < 2; ks++) {
            uint32_t a_hi[2][4], a_lo[2][4];
            const int arow = lane & 15;
            const int acol = (lane >> 4) << 3;
#pragma unroll
            for (int mi = 0; mi < 2; mi++) {
                uint32_t off = (uint32_t)((wm * 32 + mi * 16 + arow) * A_STRIDE
                                          + ks * 16 + acol) * 2;
                ldsm_x4(a_hi[mi], as_hi + off);
                ldsm_x4(a_lo[mi], as_lo + off);
            }
            uint32_t b_hi[4][2], b_lo[4][2];
            const int brow = lane & 15;
#pragma unroll
            for (int ni = 0; ni < 4; ni++) {
                uint32_t off = (uint32_t)((ks * 16 + brow) * B_STRIDE
                                          + wn * 32 + ni * 8) * 2;
                ldsm_x2_t(b_hi[ni], bs_hi + off);
                ldsm_x2_t(b_lo[ni], bs_lo + off);
            }
#pragma unroll
            for (int mi = 0; mi < 2; mi++)
#pragma unroll
                for (int ni = 0; ni < 4; ni++) {
                    mma_bf16(acc[mi][ni], a_hi[mi], b_hi[ni]);
                    mma_bf16(acc[mi][ni], a_hi[mi], b_lo[ni]);
                    mma_bf16(acc[mi][ni], a_lo[mi], b_hi[ni]);
                }
        }
        __syncthreads();
    }

    const int qrow = lane >> 2;
    const int qcol = (lane & 3) << 1;
#pragma unroll
    for (int mi = 0; mi < 2; mi++) {
        int mA = m0 + wm * 32 + mi * 16 + qrow;
        float bA = bias[mA], bB = bias[mA + 8];
        float* rowA = g_bcdt + ((size_t)(b * O3S + mA)) * NN + n0;
        float* rowB = rowA + (size_t)8 * NN;
#pragma unroll
        for (int ni = 0; ni < 4; ni++) {
            int n = wn * 32 + ni * 8 + qcol;
            *(float2*)(rowA + n) = make_float2(acc[mi][ni][0] + bA, acc[mi][ni][1] + bA);
            *(float2*)(rowB + n) = make_float2(acc[mi][ni][2] + bB, acc[mi][ni][3] + bB);
        }
    }
}

// ============================================================================
// Kernel 2a: FUSED depthwise conv (B_ ch s and dt ch 128+s) + exp + multiply.
// Rolling 3-plane smem buffers over all dz => each z-plane loaded once.
// Writes AB_unnorm to g_ab; per-(b,s,hhalf) exp-sums to g_psum.
// Grid: (2 hhalf, SS, BB), 256 threads.
// ============================================================================
__global__ void __launch_bounds__(256) conv_ab_kernel(
    const float* __restrict__ wdw, const float* __restrict__ bdw)
{
    __shared__ float sB[3][34][66];
    __shared__ float sD[3][34][66];
    __shared__ float wB[27], wD[27];
    __shared__ float red[8];

    const int hhalf = blockIdx.x;
    const int s_ = blockIdx.y;
    const int b  = blockIdx.z;
    const int h0 = hhalf * 32;
    const int tid = threadIdx.x;
    const int chB = s_;
    const int chD = 128 + s_;

    const float* baseB = g_bcdt + ((size_t)(b * O3S + chB)) * NN;
    const float* baseD = g_bcdt + ((size_t)(b * O3S + chD)) * NN;

    if (tid < 27) wB[tid] = wdw[chB * 27 + tid];
    else if (tid >= 32 && tid < 59) wD[tid - 32] = wdw[chD * 27 + (tid - 32)];
    const float biasB = bdw[chB];
    const float biasD = bdw[chD];

    auto loadplane = [&](int z, int slot) {
        for (int idx = tid; idx < 34 * 66; idx += 256) {
            int ih = idx / 66, iw = idx % 66;
            int h = h0 - 1 + ih, w = iw - 1;
            bool ok = ((unsigned)z < (unsigned)DD) && ((unsigned)h < (unsigned)HH)
                      && ((unsigned)w < (unsigned)WW);
            size_t g = (size_t)z * (HH * WW) + (size_t)h * WW + w;
            sB[slot][ih][iw] = ok ? baseB[g] : 0.f;
            sD[slot][ih][iw] = ok ? baseD[g] : 0.f;
        }
    };
    loadplane(-1, 0);
    loadplane(0, 1);
    loadplane(1, 2);
    __syncthreads();

    const int w = tid & 63;
    const int hl0 = tid >> 6;
    float* abp = g_ab + ((size_t)(b * SS + s_)) * NN;
    float lsum = 0.f;

    for (int dz = 0; dz < DD; dz++) {
        const int p0 = dz % 3, p1 = (dz + 1) % 3, p2 = (dz + 2) % 3;
#pragma unroll
        for (int r = 0; r < 8; r++) {
            int hl = hl0 + r * 4;
            float aB = biasB, aD = biasD;
#pragma unroll
            for (int kh = 0; kh < 3; kh++)
#pragma unroll
                for (int kw = 0; kw < 3; kw++) {
                    aB += sB[p0][hl + kh][w + kw] * wB[0 * 9 + kh * 3 + kw];
                    aD += sD[p0][hl + kh][w + kw] * wD[0 * 9 + kh * 3 + kw];
                    aB += sB[p1][hl + kh][w + kw] * wB[1 * 9 + kh * 3 + kw];
                    aD += sD[p1][hl + kh][w + kw] * wD[1 * 9 + kh * 3 + kw];
                    aB += sB[p2][hl + kh][w + kw] * wB[2 * 9 + kh * 3 + kw];
                    aD += sD[p2][hl + kh][w + kw] * wD[2 * 9 + kh * 3 + kw];
                }
            float e = fexp(aD);
            lsum += e;
            abp[(size_t)dz * (HH * WW) + (h0 + hl) * WW + w] = e * aB;
        }
        __syncthreads();
        if (dz < DD - 1) loadplane(dz + 2, p0);
        __syncthreads();
    }

    // block reduce lsum
    const int lane = tid & 31, warp = tid >> 5;
#pragma unroll
    for (int o = 16; o > 0; o >>= 1) lsum += __shfl_xor_sync(0xffffffffu, lsum, o);
    if (lane == 0) red[warp] = lsum;
    __syncthreads();
    if (tid == 0) {
        float v = red[0] + red[1] + red[2] + red[3] + red[4] + red[5] + red[6] + red[7];
        g_psum[(b * SS + s_) * 2 + hhalf] = v;
    }
}

// ============================================================================
// Kernel 2b: depthwise conv for C_ channels (64..127), rolling dz.
// Writes g_c. Grid: (2, SS, BB).
// ============================================================================
__global__ void __launch_bounds__(256) conv_c_kernel(
    const float* __restrict__ wdw, const float* __restrict__ bdw)
{
    __shared__ float s[3][34][66];
    __shared__ float wt[27];

    const int hhalf = blockIdx.x;
    const int s_ = blockIdx.y;
    const int b  = blockIdx.z;
    const int h0 = hhalf * 32;
    const int tid = threadIdx.x;
    const int ch = 64 + s_;

    const float* base = g_bcdt + ((size_t)(b * O3S + ch)) * NN;
    if (tid < 27) wt[tid] = wdw[ch * 27 + tid];
    const float bb = bdw[ch];

    auto loadplane = [&](int z, int slot) {
        for (int idx = tid; idx < 34 * 66; idx += 256) {
            int ih = idx / 66, iw = idx % 66;
            int h = h0 - 1 + ih, w = iw - 1;
            bool ok = ((unsigned)z < (unsigned)DD) && ((unsigned)h < (unsigned)HH)
                      && ((unsigned)w < (unsigned)WW);
            size_t g = (size_t)z * (HH * WW) + (size_t)h * WW + w;
            s[slot][ih][iw] = ok ? base[g] : 0.f;
        }
    };
    loadplane(-1, 0);
    loadplane(0, 1);
    loadplane(1, 2);
    __syncthreads();

    const int w = tid & 63;
    const int hl0 = tid >> 6;
    float* outp = g_c + ((size_t)(b * SS + s_)) * NN;

    for (int dz = 0; dz < DD; dz++) {
        const int p0 = dz % 3, p1 = (dz + 1) % 3, p2 = (dz + 2) % 3;
#pragma unroll
        for (int r = 0; r < 8; r++) {
            int hl = hl0 + r * 4;
            float a = bb;
#pragma unroll
            for (int kh = 0; kh < 3; kh++)
#pragma unroll
                for (int kw = 0; kw < 3; kw++) {
                    a += s[p0][hl + kh][w + kw] * wt[0 * 9 + kh * 3 + kw];
                    a += s[p1][hl + kh][w + kw] * wt[1 * 9 + kh * 3 + kw];
                    a += s[p2][hl + kh][w + kw] * wt[2 * 9 + kh * 3 + kw];
                }
            outp[(size_t)dz * (HH * WW) + (h0 + hl) * WW + w] = a;
        }
        __syncthreads();
        if (dz < DD - 1) loadplane(dz + 2, p0);
        __syncthreads();
    }
}

// ============================================================================
// Kernel 4 (HMMA): h_unnorm partials = sum_n x[b,c,n] * AB_unnorm[b,s,n]
// BM=64(c), BN=64(s), BK=32. cp.async 3-stage fp32 smem pipeline.
// ============================================================================
#define NSTAGE 3
#define STG_F  (64 * 36)
#define HG_SMEM (2 * NSTAGE * STG_F * 4 + 4 * 64 * A_STRIDE * 2)

__global__ void __launch_bounds__(256) hgemm_mma_kernel(const float* __restrict__ x)
{
    extern __shared__ __align__(16) char dyn[];
    float* xf = (float*)dyn;
    float* af = xf + NSTAGE * STG_F;
    uint16_t* As_hi_p = (uint16_t*)(af + NSTAGE * STG_F);
    uint16_t* As_lo_p = As_hi_p + 64 * A_STRIDE;
    uint16_t* Bs_hi_p = As_lo_p + 64 * A_STRIDE;
    uint16_t* Bs_lo_p = Bs_hi_p + 64 * HB_STRIDE;

    const int c0 = blockIdx.x * 64;
    const int ks = blockIdx.y;
    const int b  = blockIdx.z;
    const int nbase = ks * (NN / KSPLIT_H);
    const int tid  = threadIdx.x;
    const int wid  = tid >> 5;
    const int lane = tid & 31;
    const int wm = wid >> 2;
    const int wn = wid & 3;

    const float* xb = x + ((size_t)(b * CC + c0)) * NN;
    const float* ab = g_ab + (size_t)b * SS * NN;
    const uint32_t as_hi = smem_u32(As_hi_p), as_lo = smem_u32(As_lo_p);
    const uint32_t bs_hi = smem_u32(Bs_hi_p), bs_lo = smem_u32(Bs_lo_p);
    const uint32_t xf_u = smem_u32(xf), af_u = smem_u32(af);

    const int lr = tid >> 3;
    const int lk = (tid & 7) << 2;

    float acc[2][2][4];
#pragma unroll
    for (int i = 0; i < 2; i++)
#pragma unroll
        for (int j = 0; j < 2; j++)
#pragma unroll
            for (int q = 0; q < 4; q++) acc[i][j][q] = 0.f;

    auto issue = [&](int st, int kc) {
        uint32_t xs = xf_u + (uint32_t)(st * STG_F + lr * 36 + lk) * 4;
        const float* gx = xb + (size_t)lr * NN + nbase + kc + lk;
        cp16(xs, gx);
        cp16(xs + 32 * 36 * 4, gx + (size_t)32 * NN);
        uint32_t as = af_u + (uint32_t)(st * STG_F + lr * 36 + lk) * 4;
        const float* ga = ab + (size_t)lr * NN + nbase + kc + lk;
        cp16(as, ga);
        cp16(as + 32 * 36 * 4, ga + (size_t)32 * NN);
        CP_COMMIT();
    };

    issue(0, 0);
    issue(1, 32);

    const int ITERS = (NN / KSPLIT_H) / 32;
    for (int it = 0; it < ITERS; it++) {
        const int st = it % NSTAGE;
        if (it == ITERS - 1) { CP_WAIT(0); } else { CP_WAIT(1); }

        {
            float4 v0 = *(float4*)(xf + st * STG_F + lr * 36 + lk);
            float4 v1 = *(float4*)(xf + st * STG_F + (lr + 32) * 36 + lk);
            uint32_t h01, l01, h23, l23;
            split2(v0.x, v0.y, h01, l01); split2(v0.z, v0.w, h23, l23);
            *(uint2*)(As_hi_p + lr * A_STRIDE + lk) = make_uint2(h01, h23);
            *(uint2*)(As_lo_p + lr * A_STRIDE + lk) = make_uint2(l01, l23);
            split2(v1.x, v1.y, h01, l01); split2(v1.z, v1.w, h23, l23);
            *(uint2*)(As_hi_p + (lr + 32) * A_STRIDE + lk) = make_uint2(h01, h23);
            *(uint2*)(As_lo_p + (lr + 32) * A_STRIDE + lk) = make_uint2(l01, l23);

            float4 a0 = *(float4*)(af + st * STG_F + lr * 36 + lk);
            float4 a1 = *(float4*)(af + st * STG_F + (lr + 32) * 36 + lk);
            split2(a0.x, a0.y, h01, l01); split2(a0.z, a0.w, h23, l23);
            *(uint2*)(Bs_hi_p + lr * HB_STRIDE + lk) = make_uint2(h01, h23);
            *(uint2*)(Bs_lo_p + lr * HB_STRIDE + lk) = make_uint2(l01, l23);
            split2(a1.x, a1.y, h01, l01); split2(a1.z, a1.w, h23, l23);
            *(uint2*)(Bs_hi_p + (lr + 32) * HB_STRIDE + lk) = make_uint2(h01, h23);
            *(uint2*)(Bs_lo_p + (lr + 32) * HB_STRIDE + lk) = make_uint2(l01, l23);
        }
        __syncthreads();

        if (it + NSTAGE - 1 < ITERS)
            issue((it + NSTAGE - 1) % NSTAGE, (it + NSTAGE - 1) * 32);

#pragma unroll
        for (int kq = 0; kq < 2; kq++) {
            uint32_t a_hi[2][4], a_lo[2][4];
            const int arow = lane & 15;
            const int acol = (lane >> 4) << 3;
#pragma unroll
            for (int mi = 0; mi < 2; mi++) {
                uint32_t off = (uint32_t)((wm * 32 + mi * 16 + arow) * A_STRIDE
                                          + kq * 16 + acol) * 2;
                ldsm_x4(a_hi[mi], as_hi + off);
                ldsm_x4(a_lo[mi], as_lo + off);
            }
            uint32_t b_hi[2][2], b_lo[2][2];
            const int l = lane & 15;
            const int srow = l & 7;
            const int koff = (l >> 3) << 3;
#pragma unroll
            for (int ni = 0; ni < 2; ni++) {
                uint32_t off = (uint32_t)((wn * 16 + ni * 8 + srow) * HB_STRIDE
                                          + kq * 16 + koff) * 2;
                ldsm_x2(b_hi[ni], bs_hi + off);
                ldsm_x2(b_lo[ni], bs_lo + off);
            }
#pragma unroll
            for (int mi = 0; mi < 2; mi++)
#pragma unroll
                for (int ni = 0; ni < 2; ni++) {
                    mma_bf16(acc[mi][ni], a_hi[mi], b_hi[ni]);
                    mma_bf16(acc[mi][ni], a_hi[mi], b_lo[ni]);
                    mma_bf16(acc[mi][ni], a_lo[mi], b_hi[ni]);
                }
        }
        __syncthreads();
    }

    float* dst = g_hpart + (size_t)ks * (BB * CC * SS);
    const int qrow = lane >> 2;
    const int qcol = (lane & 3) << 1;
#pragma unroll
    for (int mi = 0; mi < 2; mi++) {
        int cA = c0 + wm * 32 + mi * 16 + qrow;
#pragma unroll
        for (int ni = 0; ni < 2; ni++) {
            int sA = wn * 16 + ni * 8 + qcol;
            float* pA = dst + ((size_t)(b * CC + cA)) * SS + sA;
            float* pB = dst + ((size_t)(b * CC + cA + 8)) * SS + sA;
            *(float2*)pA = make_float2(acc[mi][ni][0], acc[mi][ni][1]);
            *(float2*)pB = make_float2(acc[mi][ni][2], acc[mi][ni][3]);
        }
    }
}

// reduction of split-K partials + deferred softmax normalization
__global__ void __launch_bounds__(256) hreduce_kernel()
{
    int i = blockIdx.x * 256 + threadIdx.x;   // ((b*CC+c)*SS+s) < 65536
    int b = i >> 14;
    int s = i & 63;
    const float* ps = &g_psum[(b * SS + s) * 2];
    float inv = 1.f / (ps[0] + ps[1]);
    float sum = 0.f;
#pragma unroll
    for (int ks = 0; ks < KSPLIT_H; ks++)
        sum += g_hpart[(size_t)ks * (BB * CC * SS) + i];
    g_h[i] = sum * inv;
}

// ============================================================================
// Kernel 5: hz = W_hz @ h + b_hz ; h3 = h2*silu(z) + h2*Dp
// ============================================================================
__global__ void __launch_bounds__(256) e1_kernel(
    const float* __restrict__ Whz, const float* __restrict__ bhz,
    const float* __restrict__ Dp)
{
    const int b = blockIdx.y;
    const int o = blockIdx.x * 4 + (threadIdx.x >> 6);
    const int s_ = threadIdx.x & 63;
    const float* hb = g_h + (size_t)b * CC * SS;
    const float* w1 = Whz + (size_t)o * 256;
    const float* w2 = Whz + (size_t)(o + 256) * 256;
    float a1 = bhz[o], a2 = bhz[o + 256];
    for (int c = 0; c < 256; c++) {
        float hv = hb[c * 64 + s_];
        a1 += w1[c] * hv;
        a2 += w2[c] * hv;
    }
    float sig = 1.f / (1.f + __expf(-a2));
    g_h3[((size_t)b * CC + o) * SS + s_] = a1 * (a2 * sig) + a1 * Dp[0];
}

// Kernel 6: h4 = W_out @ h3 + b_out ; write to scratch + output tail
__global__ void __launch_bounds__(256) e2_kernel(
    const float* __restrict__ Wout, const float* __restrict__ bout,
    float* __restrict__ out)
{
    const int b = blockIdx.y;
    const int o = blockIdx.x * 4 + (threadIdx.x >> 6);
    const int s_ = threadIdx.x & 63;
    const float* hb = g_h3 + (size_t)b * CC * SS;
    const float* w1 = Wout + (size_t)o * 256;
    float acc = bout[o];
    for (int c = 0; c < 256; c++)
        acc += w1[c] * hb[c * 64 + s_];
    size_t idx = ((size_t)b * CC + o) * SS + s_;
    g_h4[idx] = acc;
    out[YSIZE + idx] = acc;
}

// ============================================================================
// Kernel 7 (HMMA): y[b,c,n] = sum_s h4[b,c,s] * C_[b,s,n]
// ============================================================================
__global__ void __launch_bounds__(256) ygemm_mma_kernel(float* __restrict__ y)
{
    __shared__ __align__(16) uint16_t As_hi[64 * A_STRIDE];
    __shared__ __align__(16) uint16_t As_lo[64 * A_STRIDE];
    __shared__ __align__(16) uint16_t Bs_hi[32 * B_STRIDE];
    __shared__ __align__(16) uint16_t Bs_lo[32 * B_STRIDE];

    const int m0 = blockIdx.x * 64;     // fastest -> L2 sharing of C_ tile
    const int n0 = blockIdx.y * 128;
    const int b  = blockIdx.z;
    const int tid  = threadIdx.x;
    const int wid  = tid >> 5;
    const int lane = tid & 31;
    const int wm = wid >> 2;
    const int wn = wid & 3;

    const float* h4b = g_h4 + (size_t)b * CC * SS;
    const float* cp  = g_c + (size_t)b * SS * NN;
    const uint32_t as_hi = smem_u32(As_hi), as_lo = smem_u32(As_lo);
    const uint32_t bs_hi = smem_u32(Bs_hi), bs_lo = smem_u32(Bs_lo);

    float acc[2][4][4];
#pragma unroll
    for (int i = 0; i < 2; i++)
#pragma unroll
        for (int j = 0; j < 4; j++)
#pragma unroll
            for (int q = 0; q < 4; q++) acc[i][j][q] = 0.f;

    for (int k0 = 0; k0 < 64; k0 += 32) {
#pragma unroll
        for (int r = 0; r < 2; r++) {
            int f = tid + r * 256;
            int m = f >> 3, k = (f & 7) << 2;
            float4 v = *(const float4*)(h4b + (size_t)(m0 + m) * SS + k0 + k);
            uint32_t h01, l01, h23, l23;
            split2(v.x, v.y, h01, l01);
            split2(v.z, v.w, h23, l23);
            int off = m * A_STRIDE + k;
            *(uint2*)(As_hi + off) = make_uint2(h01, h23);
            *(uint2*)(As_lo + off) = make_uint2(l01, l23);
        }
#pragma unroll
        for (int r = 0; r < 4; r++) {
            int f = tid + r * 256;
            int krow = f >> 5, n = (f & 31) << 2;
            float4 v = *(const float4*)(cp + (size_t)(k0 + krow) * NN + n0 + n);
            uint32_t h01, l01, h23, l23;
            split2(v.x, v.y, h01, l01);
            split2(v.z, v.w, h23, l23);
            int off = krow * B_STRIDE + n;
            *(uint2*)(Bs_hi + off) = make_uint2(h01, h23);
            *(uint2*)(Bs_lo + off) = make_uint2(l01, l23);
        }
        __syncthreads();

#pragma unroll
        for (int ks = 0; ks < 2; ks++) {
            uint32_t a_hi[2][4], a_lo[2][4];
            const int arow = lane & 15;
            const int acol = (lane >> 4) << 3;
#pragma unroll
            for (int mi = 0; mi < 2; mi++) {
                uint32_t off = (uint32_t)((wm * 32 + mi * 16 + arow) * A_STRIDE
                                          + ks * 16 + acol) * 2;
                ldsm_x4(a_hi[mi], as_hi + off);
                ldsm_x4(a_lo[mi], as_lo + off);
            }
            uint32_t b_hi[4][2], b_lo[4][2];
            const int brow = lane & 15;
#pragma unroll
            for (int ni = 0; ni < 4; ni++) {
                uint32_t off = (uint32_t)((ks * 16 + brow) * B_STRIDE
                                          + wn * 32 + ni * 8) * 2;
                ldsm_x2_t(b_hi[ni], bs_hi + off);
                ldsm_x2_t(b_lo[ni], bs_lo + off);
            }
#pragma unroll
            for (int mi = 0; mi < 2; mi++)
#pragma unroll
                for (int ni = 0; ni < 4; ni++) {
                    mma_bf16(acc[mi][ni], a_hi[mi], b_hi[ni]);
                    mma_bf16(acc[mi][ni], a_hi[mi], b_lo[ni]);
                    mma_bf16(acc[mi][ni], a_lo[mi], b_hi[ni]);
                }
        }
        __syncthreads();
    }

    const int qrow = lane >> 2;
    const int qcol = (lane & 3) << 1;
#pragma unroll
    for (int mi = 0; mi < 2; mi++) {
        int mA = m0 + wm * 32 + mi * 16 + qrow;
        float* rowA = y + ((size_t)(b * CC + mA)) * NN + n0;
        float* rowB = rowA + (size_t)8 * NN;
#pragma unroll
        for (int ni = 0; ni < 4; ni++) {
            int n = wn * 32 + ni * 8 + qcol;
            *(float2*)(rowA + n) = make_float2(acc[mi][ni][0], acc[mi][ni][1]);
            *(float2*)(rowB + n) = make_float2(acc[mi][ni][2], acc[mi][ni][3]);
        }
    }
}

// ============================================================================
extern "C" void kernel_launch(void* const* d_in, const int* in_sizes, int n_in,
                              void* d_out, int out_size)
{
    const float* x      = (const float*)d_in[0];
    const float* W_bcdt = (const float*)d_in[1];
    const float* b_bcdt = (const float*)d_in[2];
    const float* W_dw   = (const float*)d_in[3];
    const float* b_dw   = (const float*)d_in[4];
    const float* W_hz   = (const float*)d_in[5];
    const float* b_hz   = (const float*)d_in[6];
    const float* W_out  = (const float*)d_in[7];
    const float* b_out  = (const float*)d_in[8];
    // d_in[9] = A : unused (softmax shift invariance along the reduced axis)
    const float* Dp     = (const float*)d_in[10];
    float* out = (float*)d_out;

    static bool attr_set = false;
    if (!attr_set) {
        cudaFuncSetAttribute(hgemm_mma_kernel,
                             cudaFuncAttributeMaxDynamicSharedMemorySize, HG_SMEM);
        attr_set = true;
    }

    gemm1_mma_kernel<<<dim3(3, NN / 128, BB), 256>>>(x, W_bcdt, b_bcdt);
    conv_ab_kernel<<<dim3(2, SS, BB), 256>>>(W_dw, b_dw);
    conv_c_kernel<<<dim3(2, SS, BB), 256>>>(W_dw, b_dw);
    hgemm_mma_kernel<<<dim3(4, KSPLIT_H, BB), 256, HG_SMEM>>>(x);
    hreduce_kernel<<<256, 256>>>();
    e1_kernel<<<dim3(64, BB), 256>>>(W_hz, b_hz, Dp);
    e2_kernel<<<dim3(64, BB), 256>>>(W_out, b_out, out);
    ygemm_mma_kernel<<<dim3(4, NN / 128, BB), 256>>>(out);
}

// round 9
// speedup vs baseline: 2.5212x; 1.0832x over previous
#include <cuda_runtime.h>
#include <cuda_bf16.h>
#include <cstdint>
#include <cstddef>

// Problem constants
#define BB   4
#define CC   256      // D_MODEL = D_INNER
#define SS   64
#define DD   16
#define HH   64
#define WW   64
#define NN   65536    // D*H*W
#define O3S  192      // 3*S
#define KSPLIT_H 64   // split-K factor for h-GEMM

static const size_t YSIZE = (size_t)BB * CC * NN;   // 67108864

// ---- static scratch (no runtime allocation allowed) ----
__device__ float g_bcdt[(size_t)BB * O3S * NN];   // GEMM1 output (pre-conv)
__device__ float g_ab[(size_t)BB * SS * NN];      // AB_unnorm = exp(conv dt)*conv B_
__device__ float g_c [(size_t)BB * SS * NN];      // conv C_ channels
__device__ float g_hpart[(size_t)KSPLIT_H * BB * CC * SS];
__device__ float g_psum[BB * SS * 2];             // per-h-half exp-sums
__device__ float g_h [BB * CC * SS];
__device__ float g_h3[BB * CC * SS];
__device__ float g_h4[BB * CC * SS];

// ============================================================================
// helpers
// ============================================================================
__device__ __forceinline__ uint32_t smem_u32(const void* p) {
    uint32_t a;
    asm("{ .reg .u64 t; cvta.to.shared.u64 t, %1; cvt.u32.u64 %0, t; }" : "=r"(a) : "l"(p));
    return a;
}
__device__ __forceinline__ void ldsm_x4(uint32_t* r, uint32_t addr) {
    asm volatile("ldmatrix.sync.aligned.m8n8.x4.shared.b16 {%0,%1,%2,%3}, [%4];"
        : "=r"(r[0]), "=r"(r[1]), "=r"(r[2]), "=r"(r[3]) : "r"(addr));
}
__device__ __forceinline__ void ldsm_x2(uint32_t* r, uint32_t addr) {
    asm volatile("ldmatrix.sync.aligned.m8n8.x2.shared.b16 {%0,%1}, [%2];"
        : "=r"(r[0]), "=r"(r[1]) : "r"(addr));
}
__device__ __forceinline__ void ldsm_x2_t(uint32_t* r, uint32_t addr) {
    asm volatile("ldmatrix.sync.aligned.m8n8.x2.trans.shared.b16 {%0,%1}, [%2];"
        : "=r"(r[0]), "=r"(r[1]) : "r"(addr));
}
__device__ __forceinline__ void mma_bf16(float* c, const uint32_t* a, const uint32_t* b) {
    asm volatile(
        "mma.sync.aligned.m16n8k16.row.col.f32.bf16.bf16.f32 "
        "{%0,%1,%2,%3}, {%4,%5,%6,%7}, {%8,%9}, {%0,%1,%2,%3};"
        : "+f"(c[0]), "+f"(c[1]), "+f"(c[2]), "+f"(c[3])
        : "r"(a[0]), "r"(a[1]), "r"(a[2]), "r"(a[3]), "r"(b[0]), "r"(b[1]));
}
__device__ __forceinline__ void split2(float v0, float v1, uint32_t& hi, uint32_t& lo) {
    __nv_bfloat16 h0 = __float2bfloat16(v0), h1 = __float2bfloat16(v1);
    float r0 = v0 - __bfloat162float(h0), r1 = v1 - __bfloat162float(h1);
    __nv_bfloat162 hh = __halves2bfloat162(h0, h1);
    __nv_bfloat162 ll = __floats2bfloat162_rn(r0, r1);
    hi = *(uint32_t*)&hh; lo = *(uint32_t*)&ll;
}
// FMA-pipe exp (poly 2^f on [-0.5,0.5], ~2e-9 rel err), clamped both sides
__device__ __forceinline__ float fexp(float x) {
    float t = fminf(fmaxf(x * 1.4426950408889634f, -125.0f), 125.0f);
    float n = rintf(t);
    float f = t - n;
    float p = 1.5403530393381609e-4f;
    p = fmaf(p, f, 1.3333558146428443e-3f);
    p = fmaf(p, f, 9.618129107628477e-3f);
    p = fmaf(p, f, 5.550410866482158e-2f);
    p = fmaf(p, f, 2.402265069591999e-1f);
    p = fmaf(p, f, 6.931471805599453e-1f);
    p = fmaf(p, f, 1.0f);
    return __int_as_float(((int)n + 127) << 23) * p;
}

#define A_STRIDE 40    // halves per 32-k row (32 + 8 pad)
#define B_STRIDE 136   // halves per 128-n row (128 + 8 pad)
#define HB_STRIDE 40

// ============================================================================
// Kernel 1 (HMMA): BCdt = W_bcdt(192x256) @ x(b,256,N) + b_bcdt
// BM=64, BN=128, BK=32. x tile register-prefetched.
// ============================================================================
__global__ void __launch_bounds__(256) gemm1_mma_kernel(
    const float* __restrict__ x, const float* __restrict__ W,
    const float* __restrict__ bias)
{
    __shared__ __align__(16) uint16_t As_hi[64 * A_STRIDE];
    __shared__ __align__(16) uint16_t As_lo[64 * A_STRIDE];
    __shared__ __align__(16) uint16_t Bs_hi[32 * B_STRIDE];
    __shared__ __align__(16) uint16_t Bs_lo[32 * B_STRIDE];

    const int m0 = blockIdx.x * 64;     // fastest -> L2 sharing of x tile
    const int n0 = blockIdx.y * 128;
    const int b  = blockIdx.z;
    const int tid  = threadIdx.x;
    const int wid  = tid >> 5;
    const int lane = tid & 31;
    const int wm = wid >> 2;
    const int wn = wid & 3;

    const float* xb = x + (size_t)b * CC * NN;
    const uint32_t as_hi = smem_u32(As_hi), as_lo = smem_u32(As_lo);
    const uint32_t bs_hi = smem_u32(Bs_hi), bs_lo = smem_u32(Bs_lo);

    const int krow0 = tid >> 5;
    const int nloc  = (tid & 31) << 2;

    float acc[2][4][4];
#pragma unroll
    for (int i = 0; i < 2; i++)
#pragma unroll
        for (int j = 0; j < 4; j++)
#pragma unroll
            for (int q = 0; q < 4; q++) acc[i][j][q] = 0.f;

    float4 rbx[4];
#pragma unroll
    for (int r = 0; r < 4; r++)
        rbx[r] = *(const float4*)(xb + (size_t)(krow0 + r * 8) * NN + n0 + nloc);

    for (int k0 = 0; k0 < 256; k0 += 32) {
#pragma unroll
        for (int r = 0; r < 2; r++) {
            int f = tid + r * 256;
            int m = f >> 3, k = (f & 7) << 2;
            float4 v = *(const float4*)(W + (size_t)(m0 + m) * 256 + k0 + k);
            uint32_t h01, l01, h23, l23;
            split2(v.x, v.y, h01, l01);
            split2(v.z, v.w, h23, l23);
            int off = m * A_STRIDE + k;
            *(uint2*)(As_hi + off) = make_uint2(h01, h23);
            *(uint2*)(As_lo + off) = make_uint2(l01, l23);
        }
#pragma unroll
        for (int r = 0; r < 4; r++) {
            float4 v = rbx[r];
            uint32_t h01, l01, h23, l23;
            split2(v.x, v.y, h01, l01);
            split2(v.z, v.w, h23, l23);
            int off = (krow0 + r * 8) * B_STRIDE + nloc;
            *(uint2*)(Bs_hi + off) = make_uint2(h01, h23);
            *(uint2*)(Bs_lo + off) = make_uint2(l01, l23);
        }
        __syncthreads();

        if (k0 + 32 < 256) {
#pragma unroll
            for (int r = 0; r < 4; r++)
                rbx[r] = *(const float4*)(xb + (size_t)(k0 + 32 + krow0 + r * 8) * NN + n0 + nloc);
        }

#pragma unroll
        for (int ks = 0; ks < 2; ks++) {
            uint32_t a_hi[2][4], a_lo[2][4];
            const int arow = lane & 15;
            const int acol = (lane >> 4) << 3;
#pragma unroll
            for (int mi = 0; mi < 2; mi++) {
                uint32_t off = (uint32_t)((wm * 32 + mi * 16 + arow) * A_STRIDE
                                          + ks * 16 + acol) * 2;
                ldsm_x4(a_hi[mi], as_hi + off);
                ldsm_x4(a_lo[mi], as_lo + off);
            }
            uint32_t b_hi[4][2], b_lo[4][2];
            const int brow = lane & 15;
#pragma unroll
            for (int ni = 0; ni < 4; ni++) {
                uint32_t off = (uint32_t)((ks * 16 + brow) * B_STRIDE
                                          + wn * 32 + ni * 8) * 2;
                ldsm_x2_t(b_hi[ni], bs_hi + off);
                ldsm_x2_t(b_lo[ni], bs_lo + off);
            }
#pragma unroll
            for (int mi = 0; mi < 2; mi++)
#pragma unroll
                for (int ni = 0; ni < 4; ni++) {
                    mma_bf16(acc[mi][ni], a_hi[mi], b_hi[ni]);
                    mma_bf16(acc[mi][ni], a_hi[mi], b_lo[ni]);
                    mma_bf16(acc[mi][ni], a_lo[mi], b_hi[ni]);
                }
        }
        __syncthreads();
    }

    const int qrow = lane >> 2;
    const int qcol = (lane & 3) << 1;
#pragma unroll
    for (int mi = 0; mi < 2; mi++) {
        int mA = m0 + wm * 32 + mi * 16 + qrow;
        float bA = bias[mA], bB = bias[mA + 8];
        float* rowA = g_bcdt + ((size_t)(b * O3S + mA)) * NN + n0;
        float* rowB = rowA + (size_t)8 * NN;
#pragma unroll
        for (int ni = 0; ni < 4; ni++) {
            int n = wn * 32 + ni * 8 + qcol;
            *(float2*)(rowA + n) = make_float2(acc[mi][ni][0] + bA, acc[mi][ni][1] + bA);
            *(float2*)(rowB + n) = make_float2(acc[mi][ni][2] + bB, acc[mi][ni][3] + bB);
        }
    }
}

// ============================================================================
// Kernel 2a: FUSED depthwise conv (B_ ch s and dt ch 128+s) + exp + multiply.
// Rolling 3-plane smem buffers over all dz => each z-plane loaded once.
// ============================================================================
__global__ void __launch_bounds__(256) conv_ab_kernel(
    const float* __restrict__ wdw, const float* __restrict__ bdw)
{
    __shared__ float sB[3][34][66];
    __shared__ float sD[3][34][66];
    __shared__ float wB[27], wD[27];
    __shared__ float red[8];

    const int hhalf = blockIdx.x;
    const int s_ = blockIdx.y;
    const int b  = blockIdx.z;
    const int h0 = hhalf * 32;
    const int tid = threadIdx.x;
    const int chB = s_;
    const int chD = 128 + s_;

    const float* baseB = g_bcdt + ((size_t)(b * O3S + chB)) * NN;
    const float* baseD = g_bcdt + ((size_t)(b * O3S + chD)) * NN;

    if (tid < 27) wB[tid] = wdw[chB * 27 + tid];
    else if (tid >= 32 && tid < 59) wD[tid - 32] = wdw[chD * 27 + (tid - 32)];
    const float biasB = bdw[chB];
    const float biasD = bdw[chD];

    auto loadplane = [&](int z, int slot) {
        for (int idx = tid; idx < 34 * 66; idx += 256) {
            int ih = idx / 66, iw = idx % 66;
            int h = h0 - 1 + ih, w = iw - 1;
            bool ok = ((unsigned)z < (unsigned)DD) && ((unsigned)h < (unsigned)HH)
                      && ((unsigned)w < (unsigned)WW);
            size_t g = (size_t)z * (HH * WW) + (size_t)h * WW + w;
            sB[slot][ih][iw] = ok ? baseB[g] : 0.f;
            sD[slot][ih][iw] = ok ? baseD[g] : 0.f;
        }
    };
    loadplane(-1, 0);
    loadplane(0, 1);
    loadplane(1, 2);
    __syncthreads();

    const int w = tid & 63;
    const int hl0 = tid >> 6;
    float* abp = g_ab + ((size_t)(b * SS + s_)) * NN;
    float lsum = 0.f;

    for (int dz = 0; dz < DD; dz++) {
        const int p0 = dz % 3, p1 = (dz + 1) % 3, p2 = (dz + 2) % 3;
#pragma unroll
        for (int r = 0; r < 8; r++) {
            int hl = hl0 + r * 4;
            float aB = biasB, aD = biasD;
#pragma unroll
            for (int kh = 0; kh < 3; kh++)
#pragma unroll
                for (int kw = 0; kw < 3; kw++) {
                    aB += sB[p0][hl + kh][w + kw] * wB[0 * 9 + kh * 3 + kw];
                    aD += sD[p0][hl + kh][w + kw] * wD[0 * 9 + kh * 3 + kw];
                    aB += sB[p1][hl + kh][w + kw] * wB[1 * 9 + kh * 3 + kw];
                    aD += sD[p1][hl + kh][w + kw] * wD[1 * 9 + kh * 3 + kw];
                    aB += sB[p2][hl + kh][w + kw] * wB[2 * 9 + kh * 3 + kw];
                    aD += sD[p2][hl + kh][w + kw] * wD[2 * 9 + kh * 3 + kw];
                }
            float e = fexp(aD);
            lsum += e;
            abp[(size_t)dz * (HH * WW) + (h0 + hl) * WW + w] = e * aB;
        }
        __syncthreads();
        if (dz < DD - 1) loadplane(dz + 2, p0);
        __syncthreads();
    }

    const int lane = tid & 31, warp = tid >> 5;
#pragma unroll
    for (int o = 16; o > 0; o >>= 1) lsum += __shfl_xor_sync(0xffffffffu, lsum, o);
    if (lane == 0) red[warp] = lsum;
    __syncthreads();
    if (tid == 0) {
        float v = red[0] + red[1] + red[2] + red[3] + red[4] + red[5] + red[6] + red[7];
        g_psum[(b * SS + s_) * 2 + hhalf] = v;
    }
}

// ============================================================================
// Kernel 2b: depthwise conv for C_ channels (64..127), rolling dz.
// ============================================================================
__global__ void __launch_bounds__(256) conv_c_kernel(
    const float* __restrict__ wdw, const float* __restrict__ bdw)
{
    __shared__ float s[3][34][66];
    __shared__ float wt[27];

    const int hhalf = blockIdx.x;
    const int s_ = blockIdx.y;
    const int b  = blockIdx.z;
    const int h0 = hhalf * 32;
    const int tid = threadIdx.x;
    const int ch = 64 + s_;

    const float* base = g_bcdt + ((size_t)(b * O3S + ch)) * NN;
    if (tid < 27) wt[tid] = wdw[ch * 27 + tid];
    const float bb = bdw[ch];

    auto loadplane = [&](int z, int slot) {
        for (int idx = tid; idx < 34 * 66; idx += 256) {
            int ih = idx / 66, iw = idx % 66;
            int h = h0 - 1 + ih, w = iw - 1;
            bool ok = ((unsigned)z < (unsigned)DD) && ((unsigned)h < (unsigned)HH)
                      && ((unsigned)w < (unsigned)WW);
            size_t g = (size_t)z * (HH * WW) + (size_t)h * WW + w;
            s[slot][ih][iw] = ok ? base[g] : 0.f;
        }
    };
    loadplane(-1, 0);
    loadplane(0, 1);
    loadplane(1, 2);
    __syncthreads();

    const int w = tid & 63;
    const int hl0 = tid >> 6;
    float* outp = g_c + ((size_t)(b * SS + s_)) * NN;

    for (int dz = 0; dz < DD; dz++) {
        const int p0 = dz % 3, p1 = (dz + 1) % 3, p2 = (dz + 2) % 3;
#pragma unroll
        for (int r = 0; r < 8; r++) {
            int hl = hl0 + r * 4;
            float a = bb;
#pragma unroll
            for (int kh = 0; kh < 3; kh++)
#pragma unroll
                for (int kw = 0; kw < 3; kw++) {
                    a += s[p0][hl + kh][w + kw] * wt[0 * 9 + kh * 3 + kw];
                    a += s[p1][hl + kh][w + kw] * wt[1 * 9 + kh * 3 + kw];
                    a += s[p2][hl + kh][w + kw] * wt[2 * 9 + kh * 3 + kw];
                }
            outp[(size_t)dz * (HH * WW) + (h0 + hl) * WW + w] = a;
        }
        __syncthreads();
        if (dz < DD - 1) loadplane(dz + 2, p0);
        __syncthreads();
    }
}

// ============================================================================
// Kernel 4 (HMMA): h_unnorm partials = sum_n x * AB_unnorm
// BM=64(c), BN=64(s), BK=32. Register-prefetch double buffer (R6 form).
// ============================================================================
__global__ void __launch_bounds__(256) hgemm_mma_kernel(const float* __restrict__ x)
{
    __shared__ __align__(16) uint16_t As_hi[64 * A_STRIDE];
    __shared__ __align__(16) uint16_t As_lo[64 * A_STRIDE];
    __shared__ __align__(16) uint16_t Bs_hi[64 * HB_STRIDE];
    __shared__ __align__(16) uint16_t Bs_lo[64 * HB_STRIDE];

    const int c0 = blockIdx.x * 64;          // fastest -> L2 sharing of AB tile
    const int ks = blockIdx.y;               // 0..63
    const int b  = blockIdx.z;
    const int nbase = ks * (NN / KSPLIT_H);  // 1024 chunk
    const int tid  = threadIdx.x;
    const int wid  = tid >> 5;
    const int lane = tid & 31;
    const int wm = wid >> 2;
    const int wn = wid & 3;

    const float* xb = x + ((size_t)(b * CC + c0)) * NN;
    const float* ab = g_ab + (size_t)b * SS * NN;
    const uint32_t as_hi = smem_u32(As_hi), as_lo = smem_u32(As_lo);
    const uint32_t bs_hi = smem_u32(Bs_hi), bs_lo = smem_u32(Bs_lo);

    const int lr = tid >> 3;            // 0..31
    const int lk = (tid & 7) << 2;      // 0..28

    float acc[2][2][4];
#pragma unroll
    for (int i = 0; i < 2; i++)
#pragma unroll
        for (int j = 0; j < 2; j++)
#pragma unroll
            for (int q = 0; q < 4; q++) acc[i][j][q] = 0.f;

    float4 rx[2], rab[2];
    rx[0]  = *(const float4*)(xb + (size_t)lr * NN + nbase + lk);
    rx[1]  = *(const float4*)(xb + (size_t)(lr + 32) * NN + nbase + lk);
    rab[0] = *(const float4*)(ab + (size_t)lr * NN + nbase + lk);
    rab[1] = *(const float4*)(ab + (size_t)(lr + 32) * NN + nbase + lk);

    for (int kc = 0; kc < NN / KSPLIT_H; kc += 32) {
#pragma unroll
        for (int r = 0; r < 2; r++) {
            float4 v = rx[r];
            uint32_t h01, l01, h23, l23;
            split2(v.x, v.y, h01, l01);
            split2(v.z, v.w, h23, l23);
            int off = (lr + r * 32) * A_STRIDE + lk;
            *(uint2*)(As_hi + off) = make_uint2(h01, h23);
            *(uint2*)(As_lo + off) = make_uint2(l01, l23);
        }
#pragma unroll
        for (int r = 0; r < 2; r++) {
            float4 v = rab[r];
            uint32_t h01, l01, h23, l23;
            split2(v.x, v.y, h01, l01);
            split2(v.z, v.w, h23, l23);
            int off = (lr + r * 32) * HB_STRIDE + lk;
            *(uint2*)(Bs_hi + off) = make_uint2(h01, h23);
            *(uint2*)(Bs_lo + off) = make_uint2(l01, l23);
        }
        __syncthreads();

        if (kc + 32 < NN / KSPLIT_H) {
            const int nb2 = nbase + kc + 32;
            rx[0]  = *(const float4*)(xb + (size_t)lr * NN + nb2 + lk);
            rx[1]  = *(const float4*)(xb + (size_t)(lr + 32) * NN + nb2 + lk);
            rab[0] = *(const float4*)(ab + (size_t)lr * NN + nb2 + lk);
            rab[1] = *(const float4*)(ab + (size_t)(lr + 32) * NN + nb2 + lk);
        }

#pragma unroll
        for (int kq = 0; kq < 2; kq++) {
            uint32_t a_hi[2][4], a_lo[2][4];
            const int arow = lane & 15;
            const int acol = (lane >> 4) << 3;
#pragma unroll
            for (int mi = 0; mi < 2; mi++) {
                uint32_t off = (uint32_t)((wm * 32 + mi * 16 + arow) * A_STRIDE
                                          + kq * 16 + acol) * 2;
                ldsm_x4(a_hi[mi], as_hi + off);
                ldsm_x4(a_lo[mi], as_lo + off);
            }
            uint32_t b_hi[2][2], b_lo[2][2];
            const int l = lane & 15;
            const int srow = l & 7;
            const int koff = (l >> 3) << 3;
#pragma unroll
            for (int ni = 0; ni < 2; ni++) {
                uint32_t off = (uint32_t)((wn * 16 + ni * 8 + srow) * HB_STRIDE
                                          + kq * 16 + koff) * 2;
                ldsm_x2(b_hi[ni], bs_hi + off);
                ldsm_x2(b_lo[ni], bs_lo + off);
            }
#pragma unroll
            for (int mi = 0; mi < 2; mi++)
#pragma unroll
                for (int ni = 0; ni < 2; ni++) {
                    mma_bf16(acc[mi][ni], a_hi[mi], b_hi[ni]);
                    mma_bf16(acc[mi][ni], a_hi[mi], b_lo[ni]);
                    mma_bf16(acc[mi][ni], a_lo[mi], b_hi[ni]);
                }
        }
        __syncthreads();
    }

    float* dst = g_hpart + (size_t)ks * (BB * CC * SS);
    const int qrow = lane >> 2;
    const int qcol = (lane & 3) << 1;
#pragma unroll
    for (int mi = 0; mi < 2; mi++) {
        int cA = c0 + wm * 32 + mi * 16 + qrow;
#pragma unroll
        for (int ni = 0; ni < 2; ni++) {
            int sA = wn * 16 + ni * 8 + qcol;
            float* pA = dst + ((size_t)(b * CC + cA)) * SS + sA;
            float* pB = dst + ((size_t)(b * CC + cA + 8)) * SS + sA;
            *(float2*)pA = make_float2(acc[mi][ni][0], acc[mi][ni][1]);
            *(float2*)pB = make_float2(acc[mi][ni][2], acc[mi][ni][3]);
        }
    }
}

// reduction of split-K partials + deferred softmax normalization
__global__ void __launch_bounds__(256) hreduce_kernel()
{
    int i = blockIdx.x * 256 + threadIdx.x;   // ((b*CC+c)*SS+s) < 65536
    int b = i >> 14;
    int s = i & 63;
    const float* ps = &g_psum[(b * SS + s) * 2];
    float inv = 1.f / (ps[0] + ps[1]);
    float sum = 0.f;
#pragma unroll
    for (int ks = 0; ks < KSPLIT_H; ks++)
        sum += g_hpart[(size_t)ks * (BB * CC * SS) + i];
    g_h[i] = sum * inv;
}

// ============================================================================
// Kernel 5: hz = W_hz @ h + b_hz ; h3 = h2*silu(z) + h2*Dp
// ============================================================================
__global__ void __launch_bounds__(256) e1_kernel(
    const float* __restrict__ Whz, const float* __restrict__ bhz,
    const float* __restrict__ Dp)
{
    const int b = blockIdx.y;
    const int o = blockIdx.x * 4 + (threadIdx.x >> 6);
    const int s_ = threadIdx.x & 63;
    const float* hb = g_h + (size_t)b * CC * SS;
    const float* w1 = Whz + (size_t)o * 256;
    const float* w2 = Whz + (size_t)(o + 256) * 256;
    float a1 = bhz[o], a2 = bhz[o + 256];
    for (int c = 0; c < 256; c++) {
        float hv = hb[c * 64 + s_];
        a1 += w1[c] * hv;
        a2 += w2[c] * hv;
    }
    float sig = 1.f / (1.f + __expf(-a2));
    g_h3[((size_t)b * CC + o) * SS + s_] = a1 * (a2 * sig) + a1 * Dp[0];
}

// Kernel 6: h4 = W_out @ h3 + b_out ; write to scratch + output tail
__global__ void __launch_bounds__(256) e2_kernel(
    const float* __restrict__ Wout, const float* __restrict__ bout,
    float* __restrict__ out)
{
    const int b = blockIdx.y;
    const int o = blockIdx.x * 4 + (threadIdx.x >> 6);
    const int s_ = threadIdx.x & 63;
    const float* hb = g_h3 + (size_t)b * CC * SS;
    const float* w1 = Wout + (size_t)o * 256;
    float acc = bout[o];
    for (int c = 0; c < 256; c++)
        acc += w1[c] * hb[c * 64 + s_];
    size_t idx = ((size_t)b * CC + o) * SS + s_;
    g_h4[idx] = acc;
    out[YSIZE + idx] = acc;
}

// ============================================================================
// Kernel 7 (HMMA): y[b,c,n] = sum_s h4[b,c,s] * C_[b,s,n]
// ============================================================================
__global__ void __launch_bounds__(256) ygemm_mma_kernel(float* __restrict__ y)
{
    __shared__ __align__(16) uint16_t As_hi[64 * A_STRIDE];
    __shared__ __align__(16) uint16_t As_lo[64 * A_STRIDE];
    __shared__ __align__(16) uint16_t Bs_hi[32 * B_STRIDE];
    __shared__ __align__(16) uint16_t Bs_lo[32 * B_STRIDE];

    const int m0 = blockIdx.x * 64;     // fastest -> L2 sharing of C_ tile
    const int n0 = blockIdx.y * 128;
    const int b  = blockIdx.z;
    const int tid  = threadIdx.x;
    const int wid  = tid >> 5;
    const int lane = tid & 31;
    const int wm = wid >> 2;
    const int wn = wid & 3;

    const float* h4b = g_h4 + (size_t)b * CC * SS;
    const float* cp  = g_c + (size_t)b * SS * NN;
    const uint32_t as_hi = smem_u32(As_hi), as_lo = smem_u32(As_lo);
    const uint32_t bs_hi = smem_u32(Bs_hi), bs_lo = smem_u32(Bs_lo);

    float acc[2][4][4];
#pragma unroll
    for (int i = 0; i < 2; i++)
#pragma unroll
        for (int j = 0; j < 4; j++)
#pragma unroll
            for (int q = 0; q < 4; q++) acc[i][j][q] = 0.f;

    for (int k0 = 0; k0 < 64; k0 += 32) {
#pragma unroll
        for (int r = 0; r < 2; r++) {
            int f = tid + r * 256;
            int m = f >> 3, k = (f & 7) << 2;
            float4 v = *(const float4*)(h4b + (size_t)(m0 + m) * SS + k0 + k);
            uint32_t h01, l01, h23, l23;
            split2(v.x, v.y, h01, l01);
            split2(v.z, v.w, h23, l23);
            int off = m * A_STRIDE + k;
            *(uint2*)(As_hi + off) = make_uint2(h01, h23);
            *(uint2*)(As_lo + off) = make_uint2(l01, l23);
        }
#pragma unroll
        for (int r = 0; r < 4; r++) {
            int f = tid + r * 256;
            int krow = f >> 5, n = (f & 31) << 2;
            float4 v = *(const float4*)(cp + (size_t)(k0 + krow) * NN + n0 + n);
            uint32_t h01, l01, h23, l23;
            split2(v.x, v.y, h01, l01);
            split2(v.z, v.w, h23, l23);
            int off = krow * B_STRIDE + n;
            *(uint2*)(Bs_hi + off) = make_uint2(h01, h23);
            *(uint2*)(Bs_lo + off) = make_uint2(l01, l23);
        }
        __syncthreads();

#pragma unroll
        for (int ks = 0; ks < 2; ks++) {
            uint32_t a_hi[2][4], a_lo[2][4];
            const int arow = lane & 15;
            const int acol = (lane >> 4) << 3;
#pragma unroll
            for (int mi = 0; mi < 2; mi++) {
                uint32_t off = (uint32_t)((wm * 32 + mi * 16 + arow) * A_STRIDE
                                          + ks * 16 + acol) * 2;
                ldsm_x4(a_hi[mi], as_hi + off);
                ldsm_x4(a_lo[mi], as_lo + off);
            }
            uint32_t b_hi[4][2], b_lo[4][2];
            const int brow = lane & 15;
#pragma unroll
            for (int ni = 0; ni < 4; ni++) {
                uint32_t off = (uint32_t)((ks * 16 + brow) * B_STRIDE
                                          + wn * 32 + ni * 8) * 2;
                ldsm_x2_t(b_hi[ni], bs_hi + off);
                ldsm_x2_t(b_lo[ni], bs_lo + off);
            }
#pragma unroll
            for (int mi = 0; mi < 2; mi++)
#pragma unroll
                for (int ni = 0; ni < 4; ni++) {
                    mma_bf16(acc[mi][ni], a_hi[mi], b_hi[ni]);
                    mma_bf16(acc[mi][ni], a_hi[mi], b_lo[ni]);
                    mma_bf16(acc[mi][ni], a_lo[mi], b_hi[ni]);
                }
        }
        __syncthreads();
    }

    const int qrow = lane >> 2;
    const int qcol = (lane & 3) << 1;
#pragma unroll
    for (int mi = 0; mi < 2; mi++) {
        int mA = m0 + wm * 32 + mi * 16 + qrow;
        float* rowA = y + ((size_t)(b * CC + mA)) * NN + n0;
        float* rowB = rowA + (size_t)8 * NN;
#pragma unroll
        for (int ni = 0; ni < 4; ni++) {
            int n = wn * 32 + ni * 8 + qcol;
            *(float2*)(rowA + n) = make_float2(acc[mi][ni][0], acc[mi][ni][1]);
            *(float2*)(rowB + n) = make_float2(acc[mi][ni][2], acc[mi][ni][3]);
        }
    }
}

// ============================================================================
extern "C" void kernel_launch(void* const* d_in, const int* in_sizes, int n_in,
                              void* d_out, int out_size)
{
    const float* x      = (const float*)d_in[0];
    const float* W_bcdt = (const float*)d_in[1];
    const float* b_bcdt = (const float*)d_in[2];
    const float* W_dw   = (const float*)d_in[3];
    const float* b_dw   = (const float*)d_in[4];
    const float* W_hz   = (const float*)d_in[5];
    const float* b_hz   = (const float*)d_in[6];
    const float* W_out  = (const float*)d_in[7];
    const float* b_out  = (const float*)d_in[8];
    // d_in[9] = A : unused (softmax shift invariance along the reduced axis)
    const float* Dp     = (const float*)d_in[10];
    float* out = (float*)d_out;

    // side stream + fork/join events for conv_c overlap (created once; not
    // device-memory allocations). Graph capture records the fork/join as
    // graph dependencies.
    static cudaStream_t s1 = nullptr;
    static cudaEvent_t ev_g1 = nullptr, ev_c = nullptr;
    if (!s1) {
        cudaStreamCreateWithFlags(&s1, cudaStreamNonBlocking);
        cudaEventCreateWithFlags(&ev_g1, cudaEventDisableTiming);
        cudaEventCreateWithFlags(&ev_c, cudaEventDisableTiming);
    }

    gemm1_mma_kernel<<<dim3(3, NN / 128, BB), 256>>>(x, W_bcdt, b_bcdt);
    cudaEventRecord(ev_g1, 0);

    // side stream: conv_c overlaps with conv_ab/hgemm/hreduce/e1/e2
    cudaStreamWaitEvent(s1, ev_g1, 0);
    conv_c_kernel<<<dim3(2, SS, BB), 256, 0, s1>>>(W_dw, b_dw);
    cudaEventRecord(ev_c, s1);

    conv_ab_kernel<<<dim3(2, SS, BB), 256>>>(W_dw, b_dw);
    hgemm_mma_kernel<<<dim3(4, KSPLIT_H, BB), 256>>>(x);
    hreduce_kernel<<<256, 256>>>();
    e1_kernel<<<dim3(64, BB), 256>>>(W_hz, b_hz, Dp);
    e2_kernel<<<dim3(64, BB), 256>>>(W_out, b_out, out);

    cudaStreamWaitEvent(0, ev_c, 0);
    ygemm_mma_kernel<<<dim3(4, NN / 128, BB), 256>>>(out);
}